// round 3
// baseline (speedup 1.0000x reference)
#include <cuda_runtime.h>
#include <math.h>

// ---------------- problem constants ----------------
#define B_    2
#define S_    2048
#define D_    1024
#define H_    16
#define DH_   64
#define R_    256
#define NK_   4096
#define KR_   256
#define TOPK_ 8
#define NBLK_ (S_/8)   // route blocks per batch (8 rows per block)

// ---------------- device scratch (allocation-free) ----------------
__device__ float g_nx [B_*S_*D_];        // LN output (reused for LN2)
__device__ float g_part[B_*NBLK_*64];    // routing partial sums
__device__ float g_rw [5*B_*16];         // normalized router weights: slots c,q,k,v,m
__device__ float g_sc [B_*D_*R_];        // compress matrix (reused for mc)
__device__ float g_h  [B_*S_*R_];        // h (reused for Qm)
__device__ float g_e  [3*(B_*R_*D_)];    // expand matrices q,k,v
__device__ float g_q  [B_*S_*D_];
__device__ float g_k  [B_*S_*D_];
__device__ float g_v  [B_*S_*D_];
__device__ float g_ao [B_*S_*D_];

// ---------------- LayerNorm: one block per row ----------------
__global__ void ln_kernel(const float* __restrict__ x,
                          const float* __restrict__ g,
                          const float* __restrict__ b,
                          float* __restrict__ out)
{
    int row = blockIdx.x;                 // 0 .. B*S-1
    int t = threadIdx.x;                  // 256
    const float4* xr = (const float4*)(x + (size_t)row * D_);
    float4 v = xr[t];
    float s1 = v.x + v.y + v.z + v.w;
    float s2 = v.x*v.x + v.y*v.y + v.z*v.z + v.w*v.w;
    #pragma unroll
    for (int off = 16; off > 0; off >>= 1) {
        s1 += __shfl_xor_sync(0xffffffffu, s1, off);
        s2 += __shfl_xor_sync(0xffffffffu, s2, off);
    }
    __shared__ float sa[8], sb[8];
    __shared__ float s_mu, s_rs;
    int warp = t >> 5, lane = t & 31;
    if (lane == 0) { sa[warp] = s1; sb[warp] = s2; }
    __syncthreads();
    if (t == 0) {
        float ta = 0.f, tb = 0.f;
        #pragma unroll
        for (int w = 0; w < 8; ++w) { ta += sa[w]; tb += sb[w]; }
        float mu = ta * (1.0f / D_);
        float var = tb * (1.0f / D_) - mu * mu;
        s_mu = mu;
        s_rs = rsqrtf(var + 1e-5f);
    }
    __syncthreads();
    float mu = s_mu, rs = s_rs;
    float4 gg = ((const float4*)g)[t];
    float4 bb = ((const float4*)b)[t];
    float4 o;
    o.x = (v.x - mu) * rs * gg.x + bb.x;
    o.y = (v.y - mu) * rs * gg.y + bb.y;
    o.z = (v.z - mu) * rs * gg.z + bb.z;
    o.w = (v.w - mu) * rs * gg.w + bb.w;
    ((float4*)(out + (size_t)row * D_))[t] = o;
}

// ---------------- routing: logits + softmax + importance pool (deterministic) ----------------
// grid (NBLK_, B), block 256. Handles up to 4 routers (64 expert pairs). 8 rows per block.
__global__ void route_kernel(const float* __restrict__ nx, const float* __restrict__ imp,
                             const float* __restrict__ W0, const float* __restrict__ W1,
                             const float* __restrict__ W2, const float* __restrict__ W3,
                             int nPairs)
{
    __shared__ float xs[8][128];
    __shared__ float ws[64][129];
    __shared__ float lg[8][64];
    int t = threadIdx.x;
    int b = blockIdx.y;
    int r0 = blockIdx.x * 8;
    float acc[8] = {0.f,0.f,0.f,0.f,0.f,0.f,0.f,0.f};
    for (int c = 0; c < 8; ++c) {
        int d0 = c * 128;
        for (int idx = t; idx < 8*128; idx += 256) {
            int r = idx >> 7, dd = idx & 127;
            xs[r][dd] = nx[((size_t)(b*S_ + r0 + r))*D_ + d0 + dd];
        }
        for (int idx = t; idx < nPairs*128; idx += 256) {
            int p = idx >> 7, dd = idx & 127;
            const float* Wp = (p < 16) ? W0 : (p < 32) ? W1 : (p < 48) ? W2 : W3;
            ws[p][dd] = Wp[(size_t)(p & 15)*D_ + d0 + dd];
        }
        __syncthreads();
        if (t < nPairs) {
            for (int dd = 0; dd < 128; ++dd) {
                float wv = ws[t][dd];
                #pragma unroll
                for (int r = 0; r < 8; ++r) acc[r] += wv * xs[r][dd];
            }
        }
        __syncthreads();
    }
    if (t < nPairs) {
        #pragma unroll
        for (int r = 0; r < 8; ++r) lg[r][t] = acc[r];
    }
    __syncthreads();
    if (t < nPairs) {
        int router = t >> 4;
        float contrib = 0.f;
        for (int r = 0; r < 8; ++r) {
            float mx = -1e30f;
            for (int e = 0; e < 16; ++e) mx = fmaxf(mx, lg[r][(router<<4) + e]);
            float ssum = 0.f;
            for (int e = 0; e < 16; ++e) ssum += __expf(lg[r][(router<<4) + e] - mx);
            float p = __expf(lg[r][t] - mx) / ssum;
            contrib += imp[b*S_ + r0 + r] * p;
        }
        g_part[((size_t)(b*NBLK_) + blockIdx.x)*64 + t] = contrib;
    }
}

// grid nRouters, block 32. Deterministic reduction of partials + normalization.
__global__ void reduce_norm_kernel(int slotBase)
{
    int r = blockIdx.x;
    int lane = threadIdx.x;
    int b = lane >> 4, e = lane & 15;
    float acc = 0.f;
    for (int blk = 0; blk < NBLK_; ++blk)
        acc += g_part[((size_t)(b*NBLK_) + blk)*64 + (r<<4) + e];
    float gs = acc;
    gs += __shfl_xor_sync(0xffffffffu, gs, 1);
    gs += __shfl_xor_sync(0xffffffffu, gs, 2);
    gs += __shfl_xor_sync(0xffffffffu, gs, 4);
    gs += __shfl_xor_sync(0xffffffffu, gs, 8);
    g_rw[(slotBase + r)*B_*16 + b*16 + e] = acc / (gs + 1e-8f);
}

// ---------------- weighted pool mixes ----------------
__global__ void mix_sc_kernel(const float* __restrict__ cn, int slot, float* __restrict__ out)
{
    int idx = blockIdx.x*256 + threadIdx.x;
    if (idx >= B_*D_*R_) return;
    int b = idx / (D_*R_);
    int dr = idx - b*(D_*R_);
    float acc = 0.f;
    #pragma unroll
    for (int n = 0; n < 16; ++n)
        acc += g_rw[slot*B_*16 + b*16 + n] * cn[(size_t)n*(D_*R_) + dr];
    out[idx] = acc;
}

__global__ void mix_e_kernel(const float* __restrict__ pool)
{
    int idx = blockIdx.x*256 + threadIdx.x;
    if (idx >= B_*R_*D_) return;
    int which = blockIdx.y;               // 0=q 1=k 2=v -> rw slots 1..3
    int b = idx / (R_*D_);
    int rd = idx - b*(R_*D_);
    float acc = 0.f;
    #pragma unroll
    for (int n = 0; n < 16; ++n)
        acc += g_rw[(which+1)*B_*16 + b*16 + n] * pool[(size_t)n*(R_*D_) + rd];
    g_e[(size_t)which*(B_*R_*D_) + idx] = acc;
}

// ---------------- generic tiled SGEMM ----------------
// C[M,N] = A[M,K] @ B (NN: B[K,N] ; NT: B[N,K]) (+ addsrc[M,N] if non-null)
// grid (N/64, M/64, batch), block 256, 64x64x16 tiles, 4x4 per-thread micro-tile.
template<bool TB>
__global__ void sgemm_kernel(const float* __restrict__ A, const float* __restrict__ Bm,
                             float* __restrict__ C, int M, int N, int K,
                             long long sA, long long sB, long long sC,
                             const float* __restrict__ addsrc)
{
    A  += (long long)blockIdx.z * sA;
    Bm += (long long)blockIdx.z * sB;
    C  += (long long)blockIdx.z * sC;
    __shared__ __align__(16) float as[16][68];
    __shared__ __align__(16) float bs[16][68];
    int m0 = blockIdx.y * 64, n0 = blockIdx.x * 64;
    int t = threadIdx.x;
    int tx = t & 15, ty = t >> 4;
    int lm  = t >> 2;
    int lk4 = (t & 3) * 4;
    float acc[4][4] = {};
    for (int k0 = 0; k0 < K; k0 += 16) {
        float4 av = *(const float4*)(A + (long long)(m0+lm)*K + k0 + lk4);
        as[lk4+0][lm]=av.x; as[lk4+1][lm]=av.y; as[lk4+2][lm]=av.z; as[lk4+3][lm]=av.w;
        if (TB) {
            float4 bv = *(const float4*)(Bm + (long long)(n0+lm)*K + k0 + lk4);
            bs[lk4+0][lm]=bv.x; bs[lk4+1][lm]=bv.y; bs[lk4+2][lm]=bv.z; bs[lk4+3][lm]=bv.w;
        } else {
            int bk = t >> 4;          // 0..15
            int bn = (t & 15) * 4;    // 0..60
            float4 bv = *(const float4*)(Bm + (long long)(k0+bk)*N + n0 + bn);
            *(float4*)&bs[bk][bn] = bv;
        }
        __syncthreads();
        #pragma unroll
        for (int kk = 0; kk < 16; ++kk) {
            float4 a = *(const float4*)(&as[kk][ty<<2]);
            float4 b = *(const float4*)(&bs[kk][tx<<2]);
            acc[0][0] += a.x*b.x; acc[0][1] += a.x*b.y; acc[0][2] += a.x*b.z; acc[0][3] += a.x*b.w;
            acc[1][0] += a.y*b.x; acc[1][1] += a.y*b.y; acc[1][2] += a.y*b.z; acc[1][3] += a.y*b.w;
            acc[2][0] += a.z*b.x; acc[2][1] += a.z*b.y; acc[2][2] += a.z*b.z; acc[2][3] += a.z*b.w;
            acc[3][0] += a.w*b.x; acc[3][1] += a.w*b.y; acc[3][2] += a.w*b.z; acc[3][3] += a.w*b.w;
        }
        __syncthreads();
    }
    #pragma unroll
    for (int i = 0; i < 4; ++i) {
        long long row = m0 + (ty<<2) + i;
        #pragma unroll
        for (int j = 0; j < 4; ++j) {
            long long col = n0 + (tx<<2) + j;
            float v = acc[i][j];
            if (addsrc) v += addsrc[row*N + col];
            C[row*N + col] = v;
        }
    }
}

// ---------------- causal attention (flash-style, warp per query row) ----------------
// grid (S/8, H, B), block 256 (8 warps = 8 query rows). dh = 64.
__global__ void attn_kernel(const float* __restrict__ Q, const float* __restrict__ Kg,
                            const float* __restrict__ Vg, float* __restrict__ O)
{
    int b = blockIdx.z, h = blockIdx.y;
    int qbase = blockIdx.x * 8;
    int w = threadIdx.x >> 5, lane = threadIdx.x & 31;
    int q = qbase + w;
    __shared__ float Ks[64][64];
    __shared__ float Vs[64][64];
    long long ho = (long long)h * DH_;
    long long qoff = ((long long)(b*S_ + q))*D_ + ho;
    float q0 = Q[qoff + lane];
    float q1 = Q[qoff + lane + 32];
    float m = -1e30f, l = 0.f, o0 = 0.f, o1 = 0.f;
    int qmax = qbase + 7;
    for (int j0 = 0; j0 <= qmax; j0 += 64) {
        for (int idx = threadIdx.x; idx < 64*64; idx += 256) {
            int r = idx >> 6, d = idx & 63;
            long long g = ((long long)(b*S_ + j0 + r))*D_ + ho + d;
            Ks[r][d] = Kg[g];
            Vs[r][d] = Vg[g];
        }
        __syncthreads();
        int jend = min(63, q - j0);
        for (int j = 0; j <= jend; ++j) {
            float s = q0*Ks[j][lane] + q1*Ks[j][lane+32];
            s += __shfl_xor_sync(0xffffffffu, s, 16);
            s += __shfl_xor_sync(0xffffffffu, s, 8);
            s += __shfl_xor_sync(0xffffffffu, s, 4);
            s += __shfl_xor_sync(0xffffffffu, s, 2);
            s += __shfl_xor_sync(0xffffffffu, s, 1);
            s *= 0.125f;                       // 1/sqrt(64)
            float mn = fmaxf(m, s);
            float c = __expf(m - mn);
            float p = __expf(s - mn);
            l = l*c + p;
            o0 = o0*c + p*Vs[j][lane];
            o1 = o1*c + p*Vs[j][lane+32];
            m = mn;
        }
        __syncthreads();
    }
    float inv = 1.f / l;
    O[qoff + lane]      = o0 * inv;
    O[qoff + lane + 32] = o1 * inv;
}

// ---------------- fused knowledge memory: scores + top-8 + softmax + gather ----------------
// grid B*S/16, block 256 (8 warps x 2 rows each). Eliminates the [B,S,NK] scratch.
// kK staged d-major in smem (bank = lane, conflict-free); per-lane register top-8;
// exact warp merge with (value, index) tiebreak matching jax.lax.top_k.
__global__ void knowledge_kernel(const float* __restrict__ Qm,
                                 const float* __restrict__ kK,
                                 const float* __restrict__ kV,
                                 float* __restrict__ out)
{
    __shared__ float kKs[KR_ * 32];      // d-major: kKs[d*32 + key]
    __shared__ float qs[16 * KR_];       // qs[r*256 + d]
    int t = threadIdx.x, w = t >> 5, lane = t & 31;
    int rowBase = blockIdx.x * 16;
    int r0 = w * 2, r1 = w * 2 + 1;

    // stage 16 Qm rows
    for (int i = t; i < 16 * KR_ / 4; i += 256)
        ((float4*)qs)[i] = ((const float4*)(Qm + (size_t)rowBase * KR_))[i];

    float v0[TOPK_], v1[TOPK_]; int i0[TOPK_], i1[TOPK_];
    #pragma unroll
    for (int j = 0; j < TOPK_; ++j) {
        v0[j] = -3.0e38f; v1[j] = -3.0e38f; i0[j] = 0x7fffffff; i1[j] = 0x7fffffff;
    }

    for (int t0 = 0; t0 < NK_; t0 += 32) {
        __syncthreads();
        // stage kK tile transposed: thread t handles key kk = t/8, d-range (t%8)*32..+31
        {
            int kk = t >> 3;
            int d0 = (t & 7) * 32;
            const float* src = kK + (size_t)(t0 + kk) * KR_ + d0;
            #pragma unroll
            for (int j = 0; j < 32; j += 4) {
                float4 vv = *(const float4*)(src + j);
                kKs[(d0 + j + 0) * 32 + kk] = vv.x;
                kKs[(d0 + j + 1) * 32 + kk] = vv.y;
                kKs[(d0 + j + 2) * 32 + kk] = vv.z;
                kKs[(d0 + j + 3) * 32 + kk] = vv.w;
            }
        }
        __syncthreads();
        float a0 = 0.f, a1 = 0.f;
        #pragma unroll 8
        for (int d = 0; d < KR_; d += 4) {
            float4 qa = *(const float4*)(qs + r0 * KR_ + d);
            float4 qb = *(const float4*)(qs + r1 * KR_ + d);
            float k0v = kKs[(d + 0) * 32 + lane];
            float k1v = kKs[(d + 1) * 32 + lane];
            float k2v = kKs[(d + 2) * 32 + lane];
            float k3v = kKs[(d + 3) * 32 + lane];
            a0 += qa.x * k0v; a0 += qa.y * k1v; a0 += qa.z * k2v; a0 += qa.w * k3v;
            a1 += qb.x * k0v; a1 += qb.y * k1v; a1 += qb.z * k2v; a1 += qb.w * k3v;
        }
        int keyIdx = t0 + lane;
        // insert (strict > keeps lower index on ties; keys processed in increasing order)
        if (a0 > v0[TOPK_-1]) {
            v0[TOPK_-1] = a0; i0[TOPK_-1] = keyIdx;
            #pragma unroll
            for (int j = TOPK_-1; j > 0; --j)
                if (v0[j] > v0[j-1]) {
                    float tv = v0[j]; v0[j] = v0[j-1]; v0[j-1] = tv;
                    int ti = i0[j]; i0[j] = i0[j-1]; i0[j-1] = ti;
                }
        }
        if (a1 > v1[TOPK_-1]) {
            v1[TOPK_-1] = a1; i1[TOPK_-1] = keyIdx;
            #pragma unroll
            for (int j = TOPK_-1; j > 0; --j)
                if (v1[j] > v1[j-1]) {
                    float tv = v1[j]; v1[j] = v1[j-1]; v1[j-1] = tv;
                    int ti = i1[j]; i1[j] = i1[j-1]; i1[j-1] = ti;
                }
        }
    }

    // merge + softmax + gather for each of this warp's two rows
    #pragma unroll
    for (int rr = 0; rr < 2; ++rr) {
        float* lv = rr ? v1 : v0;
        int*   li = rr ? i1 : i0;
        int gr = rowBase + (rr ? r1 : r0);
        float tv[TOPK_]; int ti[TOPK_];
        int p = 0;
        #pragma unroll
        for (int it = 0; it < TOPK_; ++it) {
            float bv = lv[p];          // p < 8 always (only 8 total pops)
            int   bi = li[p];
            float mv = bv; int mi = bi;
            #pragma unroll
            for (int off = 16; off > 0; off >>= 1) {
                float ov = __shfl_xor_sync(0xffffffffu, mv, off);
                int   oi = __shfl_xor_sync(0xffffffffu, mi, off);
                if (ov > mv || (ov == mv && oi < mi)) { mv = ov; mi = oi; }
            }
            tv[it] = mv; ti[it] = mi;
            if (bi == mi) ++p;          // winner lane pops its candidate
        }
        // softmax over scaled top values (tv[0] is the max)
        float mx = tv[0] * 0.0625f;     // 1/sqrt(KR)
        float w8[TOPK_]; float ssum = 0.f;
        #pragma unroll
        for (int k2 = 0; k2 < TOPK_; ++k2) { w8[k2] = __expf(tv[k2] * 0.0625f - mx); ssum += w8[k2]; }
        float inv = 1.f / ssum;
        // gather-accumulate: warp covers D, coalesced
        for (int j = 0; j < D_ / 32; ++j) {
            int d = j * 32 + lane;
            float acc = 0.f;
            #pragma unroll
            for (int k2 = 0; k2 < TOPK_; ++k2)
                acc += w8[k2] * kV[(size_t)ti[k2] * D_ + d];
            out[(size_t)gr * D_ + d] += acc * inv;
        }
    }
}

// ---------------- host orchestration ----------------
extern "C" void kernel_launch(void* const* d_in, const int* in_sizes, int n_in,
                              void* d_out, int out_size)
{
    (void)in_sizes; (void)n_in; (void)out_size;
    const float* x   = (const float*)d_in[0];
    const float* imp = (const float*)d_in[1];
    const float* Wc  = (const float*)d_in[2];
    const float* WQ  = (const float*)d_in[3];
    const float* WK  = (const float*)d_in[4];
    const float* WV  = (const float*)d_in[5];
    const float* Wm  = (const float*)d_in[6];
    const float* cn  = (const float*)d_in[7];
    const float* pool= (const float*)d_in[8];
    const float* kK  = (const float*)d_in[9];
    const float* kV  = (const float*)d_in[10];
    const float* WO  = (const float*)d_in[11];
    const float* g1  = (const float*)d_in[12];
    const float* b1  = (const float*)d_in[13];
    const float* g2  = (const float*)d_in[14];
    const float* b2  = (const float*)d_in[15];
    float* out = (float*)d_out;

    float *nx, *sc, *h, *e, *q, *k, *v, *ao;
    cudaGetSymbolAddress((void**)&nx, g_nx);
    cudaGetSymbolAddress((void**)&sc, g_sc);
    cudaGetSymbolAddress((void**)&h,  g_h);
    cudaGetSymbolAddress((void**)&e,  g_e);
    cudaGetSymbolAddress((void**)&q,  g_q);
    cudaGetSymbolAddress((void**)&k,  g_k);
    cudaGetSymbolAddress((void**)&v,  g_v);
    cudaGetSymbolAddress((void**)&ao, g_ao);

    const long long BRD = (long long)B_*R_*D_;

    // ---- attention sub-block ----
    ln_kernel<<<B_*S_, 256>>>(x, g1, b1, nx);
    route_kernel<<<dim3(NBLK_, B_), 256>>>(nx, imp, Wc, WQ, WK, WV, 64);
    reduce_norm_kernel<<<4, 32>>>(0);
    mix_sc_kernel<<<(B_*D_*R_ + 255)/256, 256>>>(cn, 0, sc);
    // h[b] = nx[b] @ sc[b]   (S x D) @ (D x R)
    sgemm_kernel<false><<<dim3(R_/64, S_/64, B_), 256>>>(
        nx, sc, h, S_, R_, D_, (long long)S_*D_, (long long)D_*R_, (long long)S_*R_, nullptr);
    mix_e_kernel<<<dim3((B_*R_*D_ + 255)/256, 3), 256>>>(pool);
    // Q/K/V[b] = h[b] @ e_x[b]   (S x R) @ (R x D)
    sgemm_kernel<false><<<dim3(D_/64, S_/64, B_), 256>>>(
        h, e + 0*BRD, q, S_, D_, R_, (long long)S_*R_, (long long)R_*D_, (long long)S_*D_, nullptr);
    sgemm_kernel<false><<<dim3(D_/64, S_/64, B_), 256>>>(
        h, e + 1*BRD, k, S_, D_, R_, (long long)S_*R_, (long long)R_*D_, (long long)S_*D_, nullptr);
    sgemm_kernel<false><<<dim3(D_/64, S_/64, B_), 256>>>(
        h, e + 2*BRD, v, S_, D_, R_, (long long)S_*R_, (long long)R_*D_, (long long)S_*D_, nullptr);
    attn_kernel<<<dim3(S_/8, H_, B_), 256>>>(q, k, v, ao);
    // out = x + ao @ WO^T    ([B*S, D] @ [D, D]^T), NT
    sgemm_kernel<true><<<dim3(D_/64, (B_*S_)/64, 1), 256>>>(
        ao, WO, out, B_*S_, D_, D_, 0, 0, 0, x);

    // ---- memory sub-block ----
    ln_kernel<<<B_*S_, 256>>>(out, g2, b2, nx);
    route_kernel<<<dim3(NBLK_, B_), 256>>>(nx, imp, Wm, Wm, Wm, Wm, 16);
    reduce_norm_kernel<<<1, 32>>>(4);
    mix_sc_kernel<<<(B_*D_*R_ + 255)/256, 256>>>(cn, 4, sc);
    // Qm[b] = nx2[b] @ mc[b]
    sgemm_kernel<false><<<dim3(R_/64, S_/64, B_), 256>>>(
        nx, sc, h, S_, R_, D_, (long long)S_*D_, (long long)D_*R_, (long long)S_*R_, nullptr);
    // fused: ms = Qm @ kK^T -> top-8 -> softmax -> gather(kV) -> out +=
    knowledge_kernel<<<(B_*S_)/16, 256>>>(h, kK, kV, out);
}

// round 4
// speedup vs baseline: 1.8910x; 1.8910x over previous
#include <cuda_runtime.h>
#include <math.h>

// ---------------- problem constants ----------------
#define B_    2
#define S_    2048
#define D_    1024
#define H_    16
#define DH_   64
#define R_    256
#define NK_   4096
#define KR_   256
#define TOPK_ 8
#define NBLK_ (S_/8)   // route blocks per batch (8 rows per block)

// ---------------- device scratch (allocation-free) ----------------
__device__ float g_nx [B_*S_*D_];        // LN output (reused for LN2)
__device__ float g_part[B_*NBLK_*64];    // routing partial sums
__device__ float g_rw [5*B_*16];         // normalized router weights: slots c,q,k,v,m
__device__ float g_sc [B_*D_*R_];        // compress matrix (reused for mc)
__device__ float g_h  [B_*S_*R_];        // h (reused for Qm)
__device__ float g_e  [3*(B_*R_*D_)];    // expand matrices q,k,v
__device__ float g_q  [B_*S_*D_];
__device__ float g_k  [B_*S_*D_];
__device__ float g_v  [B_*S_*D_];
__device__ float g_ao [B_*S_*D_];

// ---------------- LayerNorm: one block per row ----------------
__global__ void ln_kernel(const float* __restrict__ x,
                          const float* __restrict__ g,
                          const float* __restrict__ b,
                          float* __restrict__ out)
{
    int row = blockIdx.x;                 // 0 .. B*S-1
    int t = threadIdx.x;                  // 256
    const float4* xr = (const float4*)(x + (size_t)row * D_);
    float4 v = xr[t];
    float s1 = v.x + v.y + v.z + v.w;
    float s2 = v.x*v.x + v.y*v.y + v.z*v.z + v.w*v.w;
    #pragma unroll
    for (int off = 16; off > 0; off >>= 1) {
        s1 += __shfl_xor_sync(0xffffffffu, s1, off);
        s2 += __shfl_xor_sync(0xffffffffu, s2, off);
    }
    __shared__ float sa[8], sb[8];
    __shared__ float s_mu, s_rs;
    int warp = t >> 5, lane = t & 31;
    if (lane == 0) { sa[warp] = s1; sb[warp] = s2; }
    __syncthreads();
    if (t == 0) {
        float ta = 0.f, tb = 0.f;
        #pragma unroll
        for (int w = 0; w < 8; ++w) { ta += sa[w]; tb += sb[w]; }
        float mu = ta * (1.0f / D_);
        float var = tb * (1.0f / D_) - mu * mu;
        s_mu = mu;
        s_rs = rsqrtf(var + 1e-5f);
    }
    __syncthreads();
    float mu = s_mu, rs = s_rs;
    float4 gg = ((const float4*)g)[t];
    float4 bb = ((const float4*)b)[t];
    float4 o;
    o.x = (v.x - mu) * rs * gg.x + bb.x;
    o.y = (v.y - mu) * rs * gg.y + bb.y;
    o.z = (v.z - mu) * rs * gg.z + bb.z;
    o.w = (v.w - mu) * rs * gg.w + bb.w;
    ((float4*)(out + (size_t)row * D_))[t] = o;
}

// ---------------- routing: logits + softmax + importance pool (deterministic) ----------------
__global__ void route_kernel(const float* __restrict__ nx, const float* __restrict__ imp,
                             const float* __restrict__ W0, const float* __restrict__ W1,
                             const float* __restrict__ W2, const float* __restrict__ W3,
                             int nPairs)
{
    __shared__ float xs[8][128];
    __shared__ float ws[64][129];
    __shared__ float lg[8][64];
    int t = threadIdx.x;
    int b = blockIdx.y;
    int r0 = blockIdx.x * 8;
    float acc[8] = {0.f,0.f,0.f,0.f,0.f,0.f,0.f,0.f};
    for (int c = 0; c < 8; ++c) {
        int d0 = c * 128;
        for (int idx = t; idx < 8*128; idx += 256) {
            int r = idx >> 7, dd = idx & 127;
            xs[r][dd] = nx[((size_t)(b*S_ + r0 + r))*D_ + d0 + dd];
        }
        for (int idx = t; idx < nPairs*128; idx += 256) {
            int p = idx >> 7, dd = idx & 127;
            const float* Wp = (p < 16) ? W0 : (p < 32) ? W1 : (p < 48) ? W2 : W3;
            ws[p][dd] = Wp[(size_t)(p & 15)*D_ + d0 + dd];
        }
        __syncthreads();
        if (t < nPairs) {
            for (int dd = 0; dd < 128; ++dd) {
                float wv = ws[t][dd];
                #pragma unroll
                for (int r = 0; r < 8; ++r) acc[r] += wv * xs[r][dd];
            }
        }
        __syncthreads();
    }
    if (t < nPairs) {
        #pragma unroll
        for (int r = 0; r < 8; ++r) lg[r][t] = acc[r];
    }
    __syncthreads();
    if (t < nPairs) {
        int router = t >> 4;
        float contrib = 0.f;
        for (int r = 0; r < 8; ++r) {
            float mx = -1e30f;
            for (int e = 0; e < 16; ++e) mx = fmaxf(mx, lg[r][(router<<4) + e]);
            float ssum = 0.f;
            for (int e = 0; e < 16; ++e) ssum += __expf(lg[r][(router<<4) + e] - mx);
            float p = __expf(lg[r][t] - mx) / ssum;
            contrib += imp[b*S_ + r0 + r] * p;
        }
        g_part[((size_t)(b*NBLK_) + blockIdx.x)*64 + t] = contrib;
    }
}

// grid nRouters, block 32. Deterministic reduction of partials + normalization.
__global__ void reduce_norm_kernel(int slotBase)
{
    int r = blockIdx.x;
    int lane = threadIdx.x;
    int b = lane >> 4, e = lane & 15;
    float acc = 0.f;
    for (int blk = 0; blk < NBLK_; ++blk)
        acc += g_part[((size_t)(b*NBLK_) + blk)*64 + (r<<4) + e];
    float gs = acc;
    gs += __shfl_xor_sync(0xffffffffu, gs, 1);
    gs += __shfl_xor_sync(0xffffffffu, gs, 2);
    gs += __shfl_xor_sync(0xffffffffu, gs, 4);
    gs += __shfl_xor_sync(0xffffffffu, gs, 8);
    g_rw[(slotBase + r)*B_*16 + b*16 + e] = acc / (gs + 1e-8f);
}

// ---------------- weighted pool mixes ----------------
__global__ void mix_sc_kernel(const float* __restrict__ cn, int slot, float* __restrict__ out)
{
    int idx = blockIdx.x*256 + threadIdx.x;
    if (idx >= B_*D_*R_) return;
    int b = idx / (D_*R_);
    int dr = idx - b*(D_*R_);
    float acc = 0.f;
    #pragma unroll
    for (int n = 0; n < 16; ++n)
        acc += g_rw[slot*B_*16 + b*16 + n] * cn[(size_t)n*(D_*R_) + dr];
    out[idx] = acc;
}

__global__ void mix_e_kernel(const float* __restrict__ pool)
{
    int idx = blockIdx.x*256 + threadIdx.x;
    if (idx >= B_*R_*D_) return;
    int which = blockIdx.y;               // 0=q 1=k 2=v -> rw slots 1..3
    int b = idx / (R_*D_);
    int rd = idx - b*(R_*D_);
    float acc = 0.f;
    #pragma unroll
    for (int n = 0; n < 16; ++n)
        acc += g_rw[(which+1)*B_*16 + b*16 + n] * pool[(size_t)n*(R_*D_) + rd];
    g_e[(size_t)which*(B_*R_*D_) + idx] = acc;
}

// ---------------- 128x64 double-buffered SGEMM ----------------
// C[M,N] = A[M,K] @ B (NN: B[K,N] ; NT: B[N,K]) (+ addsrc[M,N] if non-null)
// grid (N/64, M/128, batch), block 256, 8x4 micro-tile, double-buffered smem.
template<bool TB>
__global__ void sgemm_kernel(const float* __restrict__ A, const float* __restrict__ Bm,
                             float* __restrict__ C, int M, int N, int K,
                             long long sA, long long sB, long long sC,
                             const float* __restrict__ addsrc)
{
    A  += (long long)blockIdx.z * sA;
    Bm += (long long)blockIdx.z * sB;
    C  += (long long)blockIdx.z * sC;
    __shared__ __align__(16) float as[2][16][132];
    __shared__ __align__(16) float bs[2][16][68];
    int m0 = blockIdx.y * 128, n0 = blockIdx.x * 64;
    int t = threadIdx.x;
    int tx = t & 15, ty = t >> 4;
    // load mappings
    int ar  = t >> 2;                 // 0..63 (and +64)
    int ac4 = (t & 3) << 2;           // 0,4,8,12
    int bnr = t >> 4;                 // NN: k-row 0..15
    int bnc = (t & 15) << 2;          // NN: col4
    float acc[8][4] = {};
    float4 aR0, aR1, bR;

    // prologue: load k-tile 0
    aR0 = *(const float4*)(A + (long long)(m0 + ar)*K + ac4);
    aR1 = *(const float4*)(A + (long long)(m0 + ar + 64)*K + ac4);
    if (TB) bR = *(const float4*)(Bm + (long long)(n0 + ar)*K + ac4);
    else    bR = *(const float4*)(Bm + (long long)(bnr)*N + n0 + bnc);
    {
        as[0][ac4+0][ar] = aR0.x; as[0][ac4+1][ar] = aR0.y;
        as[0][ac4+2][ar] = aR0.z; as[0][ac4+3][ar] = aR0.w;
        as[0][ac4+0][ar+64] = aR1.x; as[0][ac4+1][ar+64] = aR1.y;
        as[0][ac4+2][ar+64] = aR1.z; as[0][ac4+3][ar+64] = aR1.w;
        if (TB) {
            bs[0][ac4+0][ar] = bR.x; bs[0][ac4+1][ar] = bR.y;
            bs[0][ac4+2][ar] = bR.z; bs[0][ac4+3][ar] = bR.w;
        } else {
            *(float4*)&bs[0][bnr][bnc] = bR;
        }
    }
    __syncthreads();

    int nk = K >> 4;
    for (int kt = 0; kt < nk; ++kt) {
        int cur = kt & 1;
        if (kt + 1 < nk) {
            int k0 = (kt + 1) << 4;
            aR0 = *(const float4*)(A + (long long)(m0 + ar)*K + k0 + ac4);
            aR1 = *(const float4*)(A + (long long)(m0 + ar + 64)*K + k0 + ac4);
            if (TB) bR = *(const float4*)(Bm + (long long)(n0 + ar)*K + k0 + ac4);
            else    bR = *(const float4*)(Bm + (long long)(k0 + bnr)*N + n0 + bnc);
        }
        #pragma unroll
        for (int kk = 0; kk < 16; ++kk) {
            float4 a0 = *(const float4*)(&as[cur][kk][ty*8]);
            float4 a1 = *(const float4*)(&as[cur][kk][ty*8+4]);
            float4 b  = *(const float4*)(&bs[cur][kk][tx*4]);
            acc[0][0]+=a0.x*b.x; acc[0][1]+=a0.x*b.y; acc[0][2]+=a0.x*b.z; acc[0][3]+=a0.x*b.w;
            acc[1][0]+=a0.y*b.x; acc[1][1]+=a0.y*b.y; acc[1][2]+=a0.y*b.z; acc[1][3]+=a0.y*b.w;
            acc[2][0]+=a0.z*b.x; acc[2][1]+=a0.z*b.y; acc[2][2]+=a0.z*b.z; acc[2][3]+=a0.z*b.w;
            acc[3][0]+=a0.w*b.x; acc[3][1]+=a0.w*b.y; acc[3][2]+=a0.w*b.z; acc[3][3]+=a0.w*b.w;
            acc[4][0]+=a1.x*b.x; acc[4][1]+=a1.x*b.y; acc[4][2]+=a1.x*b.z; acc[4][3]+=a1.x*b.w;
            acc[5][0]+=a1.y*b.x; acc[5][1]+=a1.y*b.y; acc[5][2]+=a1.y*b.z; acc[5][3]+=a1.y*b.w;
            acc[6][0]+=a1.z*b.x; acc[6][1]+=a1.z*b.y; acc[6][2]+=a1.z*b.z; acc[6][3]+=a1.z*b.w;
            acc[7][0]+=a1.w*b.x; acc[7][1]+=a1.w*b.y; acc[7][2]+=a1.w*b.z; acc[7][3]+=a1.w*b.w;
        }
        if (kt + 1 < nk) {
            int nb = cur ^ 1;
            as[nb][ac4+0][ar] = aR0.x; as[nb][ac4+1][ar] = aR0.y;
            as[nb][ac4+2][ar] = aR0.z; as[nb][ac4+3][ar] = aR0.w;
            as[nb][ac4+0][ar+64] = aR1.x; as[nb][ac4+1][ar+64] = aR1.y;
            as[nb][ac4+2][ar+64] = aR1.z; as[nb][ac4+3][ar+64] = aR1.w;
            if (TB) {
                bs[nb][ac4+0][ar] = bR.x; bs[nb][ac4+1][ar] = bR.y;
                bs[nb][ac4+2][ar] = bR.z; bs[nb][ac4+3][ar] = bR.w;
            } else {
                *(float4*)&bs[nb][bnr][bnc] = bR;
            }
            __syncthreads();
        }
    }
    #pragma unroll
    for (int i = 0; i < 8; ++i) {
        long long row = m0 + ty*8 + i;
        long long off = row * N + n0 + (tx<<2);
        float4 r = make_float4(acc[i][0], acc[i][1], acc[i][2], acc[i][3]);
        if (addsrc) {
            float4 a = *(const float4*)(addsrc + off);
            r.x += a.x; r.y += a.y; r.z += a.z; r.w += a.w;
        }
        *(float4*)(C + off) = r;
    }
}

// ---------------- block-tiled flash attention (fp32) ----------------
// grid (S/32, H, B), block 128. Tile: 32 queries x 64 keys, dh=64.
// Score and PV both computed as 4x4-microtile GEMMs from smem.
__global__ void attn_kernel(const float* __restrict__ Q, const float* __restrict__ Kg,
                            const float* __restrict__ Vg, float* __restrict__ O)
{
    __shared__ __align__(16) float Qs[64][36];   // [d][q]
    __shared__ __align__(16) float Ks[64][68];   // [d][k]; reused as Ps[64][36] ([k][q])
    __shared__ __align__(16) float Vs[64][68];   // [k][d]
    float* Ps = &Ks[0][0];
    int b = blockIdx.z, h = blockIdx.y;
    int q0 = blockIdx.x * 32;
    int t = threadIdx.x;            // 128
    int tx = t & 15, ty = t >> 4;   // ty 0..7 (q groups of 4), tx 0..15 (k/d groups of 4)
    long long base = ((long long)(b*S_))*D_ + (long long)h*DH_;

    // load Q tile transposed: 32 rows x 16 float4
    for (int i = t; i < 32*16; i += 128) {
        int qi = i >> 4, d4 = (i & 15) << 2;
        float4 v = *(const float4*)(Q + base + (long long)(q0+qi)*D_ + d4);
        Qs[d4+0][qi]=v.x; Qs[d4+1][qi]=v.y; Qs[d4+2][qi]=v.z; Qs[d4+3][qi]=v.w;
    }
    float m[4], l[4], o[4][4];
    #pragma unroll
    for (int i = 0; i < 4; ++i) {
        m[i] = -1e30f; l[i] = 0.f;
        #pragma unroll
        for (int j = 0; j < 4; ++j) o[i][j] = 0.f;
    }
    int lastKT = (q0 + 31) >> 6;
    for (int kt = 0; kt <= lastKT; ++kt) {
        int k0 = kt << 6;
        __syncthreads();    // prior PV reads of Ps/Vs complete before overwrite
        for (int i = t; i < 64*16; i += 128) {
            int kk = i >> 4, d4 = (i & 15) << 2;
            float4 kv = *(const float4*)(Kg + base + (long long)(k0+kk)*D_ + d4);
            Ks[d4+0][kk]=kv.x; Ks[d4+1][kk]=kv.y; Ks[d4+2][kk]=kv.z; Ks[d4+3][kk]=kv.w;
            float4 vv = *(const float4*)(Vg + base + (long long)(k0+kk)*D_ + d4);
            *(float4*)&Vs[kk][d4] = vv;
        }
        __syncthreads();
        // score GEMM: s[4q][4k]
        float s[4][4] = {};
        #pragma unroll 8
        for (int d = 0; d < 64; ++d) {
            float4 a = *(const float4*)&Qs[d][ty*4];
            float4 kb = *(const float4*)&Ks[d][tx*4];
            s[0][0]+=a.x*kb.x; s[0][1]+=a.x*kb.y; s[0][2]+=a.x*kb.z; s[0][3]+=a.x*kb.w;
            s[1][0]+=a.y*kb.x; s[1][1]+=a.y*kb.y; s[1][2]+=a.y*kb.z; s[1][3]+=a.y*kb.w;
            s[2][0]+=a.z*kb.x; s[2][1]+=a.z*kb.y; s[2][2]+=a.z*kb.z; s[2][3]+=a.z*kb.w;
            s[3][0]+=a.w*kb.x; s[3][1]+=a.w*kb.y; s[3][2]+=a.w*kb.z; s[3][3]+=a.w*kb.w;
        }
        // scale + causal mask
        bool diag = (k0 + 63 > q0 + 31) || (k0 + 63 >= q0);  // apply mask on tile that can cross
        #pragma unroll
        for (int i = 0; i < 4; ++i) {
            int qg = q0 + ty*4 + i;
            #pragma unroll
            for (int j = 0; j < 4; ++j) {
                int kg = k0 + tx*4 + j;
                float v = s[i][j] * 0.125f;
                s[i][j] = (kg > qg) ? -1e30f : v;
            }
        }
        (void)diag;
        // online softmax (rows = same-ty 16-lane groups)
        float c[4];
        #pragma unroll
        for (int i = 0; i < 4; ++i) {
            float rm = fmaxf(fmaxf(s[i][0], s[i][1]), fmaxf(s[i][2], s[i][3]));
            #pragma unroll
            for (int off = 8; off > 0; off >>= 1)
                rm = fmaxf(rm, __shfl_xor_sync(0xffffffffu, rm, off));
            float mn = fmaxf(m[i], rm);
            c[i] = __expf(m[i] - mn);
            float rs = 0.f;
            #pragma unroll
            for (int j = 0; j < 4; ++j) { s[i][j] = __expf(s[i][j] - mn); rs += s[i][j]; }
            #pragma unroll
            for (int off = 8; off > 0; off >>= 1)
                rs += __shfl_xor_sync(0xffffffffu, rs, off);
            l[i] = l[i]*c[i] + rs;
            m[i] = mn;
            #pragma unroll
            for (int j = 0; j < 4; ++j) o[i][j] *= c[i];
        }
        __syncthreads();    // all score reads of Ks done before Ps overwrite
        #pragma unroll
        for (int i = 0; i < 4; ++i)
            #pragma unroll
            for (int j = 0; j < 4; ++j)
                Ps[(tx*4+j)*36 + ty*4+i] = s[i][j];
        __syncthreads();
        // PV GEMM: o[4q][4d] += P[4q][k] * V[k][4d]
        #pragma unroll 8
        for (int kk = 0; kk < 64; ++kk) {
            float4 p = *(const float4*)&Ps[kk*36 + ty*4];
            float4 v = *(const float4*)&Vs[kk][tx*4];
            o[0][0]+=p.x*v.x; o[0][1]+=p.x*v.y; o[0][2]+=p.x*v.z; o[0][3]+=p.x*v.w;
            o[1][0]+=p.y*v.x; o[1][1]+=p.y*v.y; o[1][2]+=p.y*v.z; o[1][3]+=p.y*v.w;
            o[2][0]+=p.z*v.x; o[2][1]+=p.z*v.y; o[2][2]+=p.z*v.z; o[2][3]+=p.z*v.w;
            o[3][0]+=p.w*v.x; o[3][1]+=p.w*v.y; o[3][2]+=p.w*v.z; o[3][3]+=p.w*v.w;
        }
    }
    #pragma unroll
    for (int i = 0; i < 4; ++i) {
        float inv = 1.f / l[i];
        long long q = q0 + ty*4 + i;
        float4 r = make_float4(o[i][0]*inv, o[i][1]*inv, o[i][2]*inv, o[i][3]*inv);
        *(float4*)(O + base + q*D_ + (tx<<2)) = r;
    }
}

// ---------------- fused knowledge memory: scores + top-8 + softmax + gather ----------------
__global__ void knowledge_kernel(const float* __restrict__ Qm,
                                 const float* __restrict__ kK,
                                 const float* __restrict__ kV,
                                 float* __restrict__ out)
{
    __shared__ float kKs[KR_ * 32];      // d-major: kKs[d*32 + key]
    __shared__ float qs[16 * KR_];       // qs[r*256 + d]
    int t = threadIdx.x, w = t >> 5, lane = t & 31;
    int rowBase = blockIdx.x * 16;
    int r0 = w * 2, r1 = w * 2 + 1;

    for (int i = t; i < 16 * KR_ / 4; i += 256)
        ((float4*)qs)[i] = ((const float4*)(Qm + (size_t)rowBase * KR_))[i];

    float v0[TOPK_], v1[TOPK_]; int i0[TOPK_], i1[TOPK_];
    #pragma unroll
    for (int j = 0; j < TOPK_; ++j) {
        v0[j] = -3.0e38f; v1[j] = -3.0e38f; i0[j] = 0x7fffffff; i1[j] = 0x7fffffff;
    }

    for (int t0 = 0; t0 < NK_; t0 += 32) {
        __syncthreads();
        {
            int kk = t >> 3;
            int d0 = (t & 7) * 32;
            const float* src = kK + (size_t)(t0 + kk) * KR_ + d0;
            #pragma unroll
            for (int j = 0; j < 32; j += 4) {
                float4 vv = *(const float4*)(src + j);
                kKs[(d0 + j + 0) * 32 + kk] = vv.x;
                kKs[(d0 + j + 1) * 32 + kk] = vv.y;
                kKs[(d0 + j + 2) * 32 + kk] = vv.z;
                kKs[(d0 + j + 3) * 32 + kk] = vv.w;
            }
        }
        __syncthreads();
        float a0 = 0.f, a1 = 0.f;
        #pragma unroll 8
        for (int d = 0; d < KR_; d += 4) {
            float4 qa = *(const float4*)(qs + r0 * KR_ + d);
            float4 qb = *(const float4*)(qs + r1 * KR_ + d);
            float k0v = kKs[(d + 0) * 32 + lane];
            float k1v = kKs[(d + 1) * 32 + lane];
            float k2v = kKs[(d + 2) * 32 + lane];
            float k3v = kKs[(d + 3) * 32 + lane];
            a0 += qa.x * k0v; a0 += qa.y * k1v; a0 += qa.z * k2v; a0 += qa.w * k3v;
            a1 += qb.x * k0v; a1 += qb.y * k1v; a1 += qb.z * k2v; a1 += qb.w * k3v;
        }
        int keyIdx = t0 + lane;
        if (a0 > v0[TOPK_-1]) {
            v0[TOPK_-1] = a0; i0[TOPK_-1] = keyIdx;
            #pragma unroll
            for (int j = TOPK_-1; j > 0; --j)
                if (v0[j] > v0[j-1]) {
                    float tv = v0[j]; v0[j] = v0[j-1]; v0[j-1] = tv;
                    int ti = i0[j]; i0[j] = i0[j-1]; i0[j-1] = ti;
                }
        }
        if (a1 > v1[TOPK_-1]) {
            v1[TOPK_-1] = a1; i1[TOPK_-1] = keyIdx;
            #pragma unroll
            for (int j = TOPK_-1; j > 0; --j)
                if (v1[j] > v1[j-1]) {
                    float tv = v1[j]; v1[j] = v1[j-1]; v1[j-1] = tv;
                    int ti = i1[j]; i1[j] = i1[j-1]; i1[j-1] = ti;
                }
        }
    }

    #pragma unroll
    for (int rr = 0; rr < 2; ++rr) {
        float* lv = rr ? v1 : v0;
        int*   li = rr ? i1 : i0;
        int gr = rowBase + (rr ? r1 : r0);
        float tv[TOPK_]; int ti[TOPK_];
        int p = 0;
        #pragma unroll
        for (int it = 0; it < TOPK_; ++it) {
            float bv = lv[p];
            int   bi = li[p];
            float mv = bv; int mi = bi;
            #pragma unroll
            for (int off = 16; off > 0; off >>= 1) {
                float ov = __shfl_xor_sync(0xffffffffu, mv, off);
                int   oi = __shfl_xor_sync(0xffffffffu, mi, off);
                if (ov > mv || (ov == mv && oi < mi)) { mv = ov; mi = oi; }
            }
            tv[it] = mv; ti[it] = mi;
            if (bi == mi) ++p;
        }
        float mx = tv[0] * 0.0625f;
        float w8[TOPK_]; float ssum = 0.f;
        #pragma unroll
        for (int k2 = 0; k2 < TOPK_; ++k2) { w8[k2] = __expf(tv[k2] * 0.0625f - mx); ssum += w8[k2]; }
        float inv = 1.f / ssum;
        for (int j = 0; j < D_ / 32; ++j) {
            int d = j * 32 + lane;
            float acc = 0.f;
            #pragma unroll
            for (int k2 = 0; k2 < TOPK_; ++k2)
                acc += w8[k2] * kV[(size_t)ti[k2] * D_ + d];
            out[(size_t)gr * D_ + d] += acc * inv;
        }
    }
}

// ---------------- host orchestration ----------------
extern "C" void kernel_launch(void* const* d_in, const int* in_sizes, int n_in,
                              void* d_out, int out_size)
{
    (void)in_sizes; (void)n_in; (void)out_size;
    const float* x   = (const float*)d_in[0];
    const float* imp = (const float*)d_in[1];
    const float* Wc  = (const float*)d_in[2];
    const float* WQ  = (const float*)d_in[3];
    const float* WK  = (const float*)d_in[4];
    const float* WV  = (const float*)d_in[5];
    const float* Wm  = (const float*)d_in[6];
    const float* cn  = (const float*)d_in[7];
    const float* pool= (const float*)d_in[8];
    const float* kK  = (const float*)d_in[9];
    const float* kV  = (const float*)d_in[10];
    const float* WO  = (const float*)d_in[11];
    const float* g1  = (const float*)d_in[12];
    const float* b1  = (const float*)d_in[13];
    const float* g2  = (const float*)d_in[14];
    const float* b2  = (const float*)d_in[15];
    float* out = (float*)d_out;

    float *nx, *sc, *h, *e, *q, *k, *v, *ao;
    cudaGetSymbolAddress((void**)&nx, g_nx);
    cudaGetSymbolAddress((void**)&sc, g_sc);
    cudaGetSymbolAddress((void**)&h,  g_h);
    cudaGetSymbolAddress((void**)&e,  g_e);
    cudaGetSymbolAddress((void**)&q,  g_q);
    cudaGetSymbolAddress((void**)&k,  g_k);
    cudaGetSymbolAddress((void**)&v,  g_v);
    cudaGetSymbolAddress((void**)&ao, g_ao);

    const long long BRD = (long long)B_*R_*D_;

    // ---- attention sub-block ----
    ln_kernel<<<B_*S_, 256>>>(x, g1, b1, nx);
    route_kernel<<<dim3(NBLK_, B_), 256>>>(nx, imp, Wc, WQ, WK, WV, 64);
    reduce_norm_kernel<<<4, 32>>>(0);
    mix_sc_kernel<<<(B_*D_*R_ + 255)/256, 256>>>(cn, 0, sc);
    // h[b] = nx[b] @ sc[b]   (S x D) @ (D x R)
    sgemm_kernel<false><<<dim3(R_/64, S_/128, B_), 256>>>(
        nx, sc, h, S_, R_, D_, (long long)S_*D_, (long long)D_*R_, (long long)S_*R_, nullptr);
    mix_e_kernel<<<dim3((B_*R_*D_ + 255)/256, 3), 256>>>(pool);
    // Q/K/V[b] = h[b] @ e_x[b]   (S x R) @ (R x D)
    sgemm_kernel<false><<<dim3(D_/64, S_/128, B_), 256>>>(
        h, e + 0*BRD, q, S_, D_, R_, (long long)S_*R_, (long long)R_*D_, (long long)S_*D_, nullptr);
    sgemm_kernel<false><<<dim3(D_/64, S_/128, B_), 256>>>(
        h, e + 1*BRD, k, S_, D_, R_, (long long)S_*R_, (long long)R_*D_, (long long)S_*D_, nullptr);
    sgemm_kernel<false><<<dim3(D_/64, S_/128, B_), 256>>>(
        h, e + 2*BRD, v, S_, D_, R_, (long long)S_*R_, (long long)R_*D_, (long long)S_*D_, nullptr);
    attn_kernel<<<dim3(S_/32, H_, B_), 128>>>(q, k, v, ao);
    // out = x + ao @ WO^T    ([B*S, D] @ [D, D]^T), NT
    sgemm_kernel<true><<<dim3(D_/64, (B_*S_)/128, 1), 256>>>(
        ao, WO, out, B_*S_, D_, D_, 0, 0, 0, x);

    // ---- memory sub-block ----
    ln_kernel<<<B_*S_, 256>>>(out, g2, b2, nx);
    route_kernel<<<dim3(NBLK_, B_), 256>>>(nx, imp, Wm, Wm, Wm, Wm, 16);
    reduce_norm_kernel<<<1, 32>>>(4);
    mix_sc_kernel<<<(B_*D_*R_ + 255)/256, 256>>>(cn, 4, sc);
    // Qm[b] = nx2[b] @ mc[b]
    sgemm_kernel<false><<<dim3(R_/64, S_/128, B_), 256>>>(
        nx, sc, h, S_, R_, D_, (long long)S_*D_, (long long)D_*R_, (long long)S_*R_, nullptr);
    // fused: ms = Qm @ kK^T -> top-8 -> softmax -> gather(kV) -> out +=
    knowledge_kernel<<<(B_*S_)/16, 256>>>(h, kK, kV, out);
}

// round 5
// speedup vs baseline: 2.0762x; 1.0979x over previous
#include <cuda_runtime.h>
#include <math.h>
#include <stdint.h>

// ---------------- problem constants ----------------
#define B_    2
#define S_    2048
#define D_    1024
#define H_    16
#define DH_   64
#define R_    256
#define NK_   4096
#define KR_   256
#define TOPK_ 8
#define NBLK_ (S_/8)   // route blocks per batch (8 rows per block)

// ---------------- device scratch (allocation-free) ----------------
__device__ float g_nx [B_*S_*D_];        // LN output (reused for LN2)
__device__ float g_part[B_*NBLK_*64];    // routing partial sums
__device__ float g_rw [5*B_*16];         // normalized router weights: slots c,q,k,v,m
__device__ float g_sc [B_*D_*R_];        // compress matrix (reused for mc)
__device__ float g_h  [B_*S_*R_];        // h (reused for Qm)
__device__ float g_e  [3*(B_*R_*D_)];    // expand matrices q,k,v
__device__ float g_q  [B_*S_*D_];
__device__ float g_k  [B_*S_*D_];
__device__ float g_v  [B_*S_*D_];
__device__ float g_ao [B_*S_*D_];

// ---------------- tf32 helpers ----------------
__device__ __forceinline__ float to_tf32(float x) {
    uint32_t u;
    asm("cvt.rna.tf32.f32 %0, %1;" : "=r"(u) : "f"(x));
    return __uint_as_float(u);
}

__device__ __forceinline__ void mma_tf32(float* d, const uint32_t* a, const uint32_t* b) {
    asm volatile(
        "mma.sync.aligned.m16n8k8.row.col.f32.tf32.tf32.f32 "
        "{%0,%1,%2,%3},{%4,%5,%6,%7},{%8,%9},{%0,%1,%2,%3};"
        : "+f"(d[0]), "+f"(d[1]), "+f"(d[2]), "+f"(d[3])
        : "r"(a[0]), "r"(a[1]), "r"(a[2]), "r"(a[3]), "r"(b[0]), "r"(b[1]));
}

// ---------------- LayerNorm: one block per row ----------------
__global__ void ln_kernel(const float* __restrict__ x,
                          const float* __restrict__ g,
                          const float* __restrict__ b,
                          float* __restrict__ out)
{
    int row = blockIdx.x;                 // 0 .. B*S-1
    int t = threadIdx.x;                  // 256
    const float4* xr = (const float4*)(x + (size_t)row * D_);
    float4 v = xr[t];
    float s1 = v.x + v.y + v.z + v.w;
    float s2 = v.x*v.x + v.y*v.y + v.z*v.z + v.w*v.w;
    #pragma unroll
    for (int off = 16; off > 0; off >>= 1) {
        s1 += __shfl_xor_sync(0xffffffffu, s1, off);
        s2 += __shfl_xor_sync(0xffffffffu, s2, off);
    }
    __shared__ float sa[8], sb[8];
    __shared__ float s_mu, s_rs;
    int warp = t >> 5, lane = t & 31;
    if (lane == 0) { sa[warp] = s1; sb[warp] = s2; }
    __syncthreads();
    if (t == 0) {
        float ta = 0.f, tb = 0.f;
        #pragma unroll
        for (int w = 0; w < 8; ++w) { ta += sa[w]; tb += sb[w]; }
        float mu = ta * (1.0f / D_);
        float var = tb * (1.0f / D_) - mu * mu;
        s_mu = mu;
        s_rs = rsqrtf(var + 1e-5f);
    }
    __syncthreads();
    float mu = s_mu, rs = s_rs;
    float4 gg = ((const float4*)g)[t];
    float4 bb = ((const float4*)b)[t];
    float4 o;
    o.x = (v.x - mu) * rs * gg.x + bb.x;
    o.y = (v.y - mu) * rs * gg.y + bb.y;
    o.z = (v.z - mu) * rs * gg.z + bb.z;
    o.w = (v.w - mu) * rs * gg.w + bb.w;
    ((float4*)(out + (size_t)row * D_))[t] = o;
}

// ---------------- routing: logits + softmax + importance pool (deterministic) ----------------
__global__ void route_kernel(const float* __restrict__ nx, const float* __restrict__ imp,
                             const float* __restrict__ W0, const float* __restrict__ W1,
                             const float* __restrict__ W2, const float* __restrict__ W3,
                             int nPairs)
{
    __shared__ float xs[8][128];
    __shared__ float ws[64][129];
    __shared__ float lg[8][64];
    int t = threadIdx.x;
    int b = blockIdx.y;
    int r0 = blockIdx.x * 8;
    float acc[8] = {0.f,0.f,0.f,0.f,0.f,0.f,0.f,0.f};
    for (int c = 0; c < 8; ++c) {
        int d0 = c * 128;
        for (int idx = t; idx < 8*128; idx += 256) {
            int r = idx >> 7, dd = idx & 127;
            xs[r][dd] = nx[((size_t)(b*S_ + r0 + r))*D_ + d0 + dd];
        }
        for (int idx = t; idx < nPairs*128; idx += 256) {
            int p = idx >> 7, dd = idx & 127;
            const float* Wp = (p < 16) ? W0 : (p < 32) ? W1 : (p < 48) ? W2 : W3;
            ws[p][dd] = Wp[(size_t)(p & 15)*D_ + d0 + dd];
        }
        __syncthreads();
        if (t < nPairs) {
            for (int dd = 0; dd < 128; ++dd) {
                float wv = ws[t][dd];
                #pragma unroll
                for (int r = 0; r < 8; ++r) acc[r] += wv * xs[r][dd];
            }
        }
        __syncthreads();
    }
    if (t < nPairs) {
        #pragma unroll
        for (int r = 0; r < 8; ++r) lg[r][t] = acc[r];
    }
    __syncthreads();
    if (t < nPairs) {
        int router = t >> 4;
        float contrib = 0.f;
        for (int r = 0; r < 8; ++r) {
            float mx = -1e30f;
            for (int e = 0; e < 16; ++e) mx = fmaxf(mx, lg[r][(router<<4) + e]);
            float ssum = 0.f;
            for (int e = 0; e < 16; ++e) ssum += __expf(lg[r][(router<<4) + e] - mx);
            float p = __expf(lg[r][t] - mx) / ssum;
            contrib += imp[b*S_ + r0 + r] * p;
        }
        g_part[((size_t)(b*NBLK_) + blockIdx.x)*64 + t] = contrib;
    }
}

// grid nRouters, block 32. Deterministic reduction of partials + normalization.
__global__ void reduce_norm_kernel(int slotBase)
{
    int r = blockIdx.x;
    int lane = threadIdx.x;
    int b = lane >> 4, e = lane & 15;
    float acc = 0.f;
    for (int blk = 0; blk < NBLK_; ++blk)
        acc += g_part[((size_t)(b*NBLK_) + blk)*64 + (r<<4) + e];
    float gs = acc;
    gs += __shfl_xor_sync(0xffffffffu, gs, 1);
    gs += __shfl_xor_sync(0xffffffffu, gs, 2);
    gs += __shfl_xor_sync(0xffffffffu, gs, 4);
    gs += __shfl_xor_sync(0xffffffffu, gs, 8);
    g_rw[(slotBase + r)*B_*16 + b*16 + e] = acc / (gs + 1e-8f);
}

// ---------------- weighted pool mixes ----------------
__global__ void mix_sc_kernel(const float* __restrict__ cn, int slot, float* __restrict__ out)
{
    int idx = blockIdx.x*256 + threadIdx.x;
    if (idx >= B_*D_*R_) return;
    int b = idx / (D_*R_);
    int dr = idx - b*(D_*R_);
    float acc = 0.f;
    #pragma unroll
    for (int n = 0; n < 16; ++n)
        acc += g_rw[slot*B_*16 + b*16 + n] * cn[(size_t)n*(D_*R_) + dr];
    out[idx] = acc;
}

__global__ void mix_e_kernel(const float* __restrict__ pool)
{
    int idx = blockIdx.x*256 + threadIdx.x;
    if (idx >= B_*R_*D_) return;
    int which = blockIdx.y;               // 0=q 1=k 2=v -> rw slots 1..3
    int b = idx / (R_*D_);
    int rd = idx - b*(R_*D_);
    float acc = 0.f;
    #pragma unroll
    for (int n = 0; n < 16; ++n)
        acc += g_rw[(which+1)*B_*16 + b*16 + n] * pool[(size_t)n*(R_*D_) + rd];
    g_e[(size_t)which*(B_*R_*D_) + idx] = acc;
}

// ---------------- 128x64 double-buffered TF32 tensor-core SGEMM ----------------
// C[M,N] = A[M,K] @ B (NN: B[K,N] ; NT: B[N,K]) (+ addsrc[M,N] if non-null)
// grid (N/64, M/128, batch), block 256 = 8 warps (4 along M x 2 along N).
// Warp tile 32x32 via mma.sync.m16n8k8 tf32 (2 m-tiles x 4 n-tiles x 2 k-steps).
template<bool TB>
__global__ void sgemm_kernel(const float* __restrict__ A, const float* __restrict__ Bm,
                             float* __restrict__ C, int M, int N, int K,
                             long long sA, long long sB, long long sC,
                             const float* __restrict__ addsrc)
{
    A  += (long long)blockIdx.z * sA;
    Bm += (long long)blockIdx.z * sB;
    C  += (long long)blockIdx.z * sC;
    __shared__ __align__(16) float as[2][128][20];   // [m][k], pad 20 -> conflict-free frag loads
    __shared__ __align__(16) float bs[2][16][76];    // [k][n], pad 76
    int m0 = blockIdx.y * 128, n0 = blockIdx.x * 64;
    int t = threadIdx.x;
    int warp = t >> 5, lane = t & 31;
    int wm = warp >> 1, wn = warp & 1;   // 4 x 2 warp grid
    int qr = lane >> 2, qc = lane & 3;   // mma fragment coords
    // load mappings
    int ar  = t >> 2;                 // 0..63 (and +64)
    int ac4 = (t & 3) << 2;           // 0,4,8,12
    int bnr = t >> 4;                 // NN: k-row 0..15
    int bnc = (t & 15) << 2;          // NN: col4
    float acc[2][4][4];
    #pragma unroll
    for (int i = 0; i < 2; ++i)
        #pragma unroll
        for (int j = 0; j < 4; ++j)
            #pragma unroll
            for (int c = 0; c < 4; ++c) acc[i][j][c] = 0.f;
    float4 aR0, aR1, bR;

    // prologue: load k-tile 0
    aR0 = *(const float4*)(A + (long long)(m0 + ar)*K + ac4);
    aR1 = *(const float4*)(A + (long long)(m0 + ar + 64)*K + ac4);
    if (TB) bR = *(const float4*)(Bm + (long long)(n0 + ar)*K + ac4);
    else    bR = *(const float4*)(Bm + (long long)(bnr)*N + n0 + bnc);
    {
        float4 c0 = make_float4(to_tf32(aR0.x), to_tf32(aR0.y), to_tf32(aR0.z), to_tf32(aR0.w));
        float4 c1 = make_float4(to_tf32(aR1.x), to_tf32(aR1.y), to_tf32(aR1.z), to_tf32(aR1.w));
        *(float4*)&as[0][ar][ac4]      = c0;
        *(float4*)&as[0][ar + 64][ac4] = c1;
        if (TB) {
            bs[0][ac4+0][ar] = to_tf32(bR.x); bs[0][ac4+1][ar] = to_tf32(bR.y);
            bs[0][ac4+2][ar] = to_tf32(bR.z); bs[0][ac4+3][ar] = to_tf32(bR.w);
        } else {
            float4 cb = make_float4(to_tf32(bR.x), to_tf32(bR.y), to_tf32(bR.z), to_tf32(bR.w));
            *(float4*)&bs[0][bnr][bnc] = cb;
        }
    }
    __syncthreads();

    int nk = K >> 4;
    for (int kt = 0; kt < nk; ++kt) {
        int cur = kt & 1;
        if (kt + 1 < nk) {
            int k0 = (kt + 1) << 4;
            aR0 = *(const float4*)(A + (long long)(m0 + ar)*K + k0 + ac4);
            aR1 = *(const float4*)(A + (long long)(m0 + ar + 64)*K + k0 + ac4);
            if (TB) bR = *(const float4*)(Bm + (long long)(n0 + ar)*K + k0 + ac4);
            else    bR = *(const float4*)(Bm + (long long)(k0 + bnr)*N + n0 + bnc);
        }
        #pragma unroll
        for (int ks = 0; ks < 16; ks += 8) {
            uint32_t af[2][4], bf[4][2];
            #pragma unroll
            for (int mt = 0; mt < 2; ++mt) {
                int mb = wm*32 + mt*16;
                af[mt][0] = __float_as_uint(as[cur][mb + qr    ][ks + qc    ]);
                af[mt][1] = __float_as_uint(as[cur][mb + qr + 8][ks + qc    ]);
                af[mt][2] = __float_as_uint(as[cur][mb + qr    ][ks + qc + 4]);
                af[mt][3] = __float_as_uint(as[cur][mb + qr + 8][ks + qc + 4]);
            }
            #pragma unroll
            for (int nt = 0; nt < 4; ++nt) {
                int nb = wn*32 + nt*8;
                bf[nt][0] = __float_as_uint(bs[cur][ks + qc    ][nb + qr]);
                bf[nt][1] = __float_as_uint(bs[cur][ks + qc + 4][nb + qr]);
            }
            #pragma unroll
            for (int mt = 0; mt < 2; ++mt)
                #pragma unroll
                for (int nt = 0; nt < 4; ++nt)
                    mma_tf32(acc[mt][nt], af[mt], bf[nt]);
        }
        if (kt + 1 < nk) {
            int nb = cur ^ 1;
            float4 c0 = make_float4(to_tf32(aR0.x), to_tf32(aR0.y), to_tf32(aR0.z), to_tf32(aR0.w));
            float4 c1 = make_float4(to_tf32(aR1.x), to_tf32(aR1.y), to_tf32(aR1.z), to_tf32(aR1.w));
            __syncthreads();   // compute done on both buffers' readers before overwrite of nb
            *(float4*)&as[nb][ar][ac4]      = c0;
            *(float4*)&as[nb][ar + 64][ac4] = c1;
            if (TB) {
                bs[nb][ac4+0][ar] = to_tf32(bR.x); bs[nb][ac4+1][ar] = to_tf32(bR.y);
                bs[nb][ac4+2][ar] = to_tf32(bR.z); bs[nb][ac4+3][ar] = to_tf32(bR.w);
            } else {
                float4 cb = make_float4(to_tf32(bR.x), to_tf32(bR.y), to_tf32(bR.z), to_tf32(bR.w));
                *(float4*)&bs[nb][bnr][bnc] = cb;
            }
            __syncthreads();
        }
    }
    // epilogue: each (mt, nt) fragment: d0,d1 at (row, 2qc), d2,d3 at (row+8, 2qc)
    #pragma unroll
    for (int mt = 0; mt < 2; ++mt) {
        long long row = m0 + wm*32 + mt*16 + qr;
        #pragma unroll
        for (int nt = 0; nt < 4; ++nt) {
            long long col = n0 + wn*32 + nt*8 + qc*2;
            long long off0 = row * N + col;
            long long off1 = (row + 8) * N + col;
            float2 r0 = make_float2(acc[mt][nt][0], acc[mt][nt][1]);
            float2 r1 = make_float2(acc[mt][nt][2], acc[mt][nt][3]);
            if (addsrc) {
                float2 a0 = *(const float2*)(addsrc + off0);
                float2 a1 = *(const float2*)(addsrc + off1);
                r0.x += a0.x; r0.y += a0.y; r1.x += a1.x; r1.y += a1.y;
            }
            *(float2*)(C + off0) = r0;
            *(float2*)(C + off1) = r1;
        }
    }
}

// ---------------- block-tiled flash attention (fp32) ----------------
// grid (S/32, H, B), block 128. Tile: 32 queries x 64 keys, dh=64.
__global__ void attn_kernel(const float* __restrict__ Q, const float* __restrict__ Kg,
                            const float* __restrict__ Vg, float* __restrict__ O)
{
    __shared__ __align__(16) float Qs[64][36];   // [d][q]
    __shared__ __align__(16) float Ks[64][68];   // [d][k]; reused as Ps[64][36] ([k][q])
    __shared__ __align__(16) float Vs[64][68];   // [k][d]
    float* Ps = &Ks[0][0];
    int b = blockIdx.z, h = blockIdx.y;
    int q0 = blockIdx.x * 32;
    int t = threadIdx.x;            // 128
    int tx = t & 15, ty = t >> 4;   // ty 0..7 (q groups of 4), tx 0..15 (k/d groups of 4)
    long long base = ((long long)(b*S_))*D_ + (long long)h*DH_;

    for (int i = t; i < 32*16; i += 128) {
        int qi = i >> 4, d4 = (i & 15) << 2;
        float4 v = *(const float4*)(Q + base + (long long)(q0+qi)*D_ + d4);
        Qs[d4+0][qi]=v.x; Qs[d4+1][qi]=v.y; Qs[d4+2][qi]=v.z; Qs[d4+3][qi]=v.w;
    }
    float m[4], l[4], o[4][4];
    #pragma unroll
    for (int i = 0; i < 4; ++i) {
        m[i] = -1e30f; l[i] = 0.f;
        #pragma unroll
        for (int j = 0; j < 4; ++j) o[i][j] = 0.f;
    }
    int lastKT = (q0 + 31) >> 6;
    for (int kt = 0; kt <= lastKT; ++kt) {
        int k0 = kt << 6;
        __syncthreads();
        for (int i = t; i < 64*16; i += 128) {
            int kk = i >> 4, d4 = (i & 15) << 2;
            float4 kv = *(const float4*)(Kg + base + (long long)(k0+kk)*D_ + d4);
            Ks[d4+0][kk]=kv.x; Ks[d4+1][kk]=kv.y; Ks[d4+2][kk]=kv.z; Ks[d4+3][kk]=kv.w;
            float4 vv = *(const float4*)(Vg + base + (long long)(k0+kk)*D_ + d4);
            *(float4*)&Vs[kk][d4] = vv;
        }
        __syncthreads();
        float s[4][4] = {};
        #pragma unroll 8
        for (int d = 0; d < 64; ++d) {
            float4 a = *(const float4*)&Qs[d][ty*4];
            float4 kb = *(const float4*)&Ks[d][tx*4];
            s[0][0]+=a.x*kb.x; s[0][1]+=a.x*kb.y; s[0][2]+=a.x*kb.z; s[0][3]+=a.x*kb.w;
            s[1][0]+=a.y*kb.x; s[1][1]+=a.y*kb.y; s[1][2]+=a.y*kb.z; s[1][3]+=a.y*kb.w;
            s[2][0]+=a.z*kb.x; s[2][1]+=a.z*kb.y; s[2][2]+=a.z*kb.z; s[2][3]+=a.z*kb.w;
            s[3][0]+=a.w*kb.x; s[3][1]+=a.w*kb.y; s[3][2]+=a.w*kb.z; s[3][3]+=a.w*kb.w;
        }
        #pragma unroll
        for (int i = 0; i < 4; ++i) {
            int qg = q0 + ty*4 + i;
            #pragma unroll
            for (int j = 0; j < 4; ++j) {
                int kg = k0 + tx*4 + j;
                float v = s[i][j] * 0.125f;
                s[i][j] = (kg > qg) ? -1e30f : v;
            }
        }
        float c[4];
        #pragma unroll
        for (int i = 0; i < 4; ++i) {
            float rm = fmaxf(fmaxf(s[i][0], s[i][1]), fmaxf(s[i][2], s[i][3]));
            #pragma unroll
            for (int off = 8; off > 0; off >>= 1)
                rm = fmaxf(rm, __shfl_xor_sync(0xffffffffu, rm, off));
            float mn = fmaxf(m[i], rm);
            c[i] = __expf(m[i] - mn);
            float rs = 0.f;
            #pragma unroll
            for (int j = 0; j < 4; ++j) { s[i][j] = __expf(s[i][j] - mn); rs += s[i][j]; }
            #pragma unroll
            for (int off = 8; off > 0; off >>= 1)
                rs += __shfl_xor_sync(0xffffffffu, rs, off);
            l[i] = l[i]*c[i] + rs;
            m[i] = mn;
            #pragma unroll
            for (int j = 0; j < 4; ++j) o[i][j] *= c[i];
        }
        __syncthreads();
        #pragma unroll
        for (int i = 0; i < 4; ++i)
            #pragma unroll
            for (int j = 0; j < 4; ++j)
                Ps[(tx*4+j)*36 + ty*4+i] = s[i][j];
        __syncthreads();
        #pragma unroll 8
        for (int kk = 0; kk < 64; ++kk) {
            float4 p = *(const float4*)&Ps[kk*36 + ty*4];
            float4 v = *(const float4*)&Vs[kk][tx*4];
            o[0][0]+=p.x*v.x; o[0][1]+=p.x*v.y; o[0][2]+=p.x*v.z; o[0][3]+=p.x*v.w;
            o[1][0]+=p.y*v.x; o[1][1]+=p.y*v.y; o[1][2]+=p.y*v.z; o[1][3]+=p.y*v.w;
            o[2][0]+=p.z*v.x; o[2][1]+=p.z*v.y; o[2][2]+=p.z*v.z; o[2][3]+=p.z*v.w;
            o[3][0]+=p.w*v.x; o[3][1]+=p.w*v.y; o[3][2]+=p.w*v.z; o[3][3]+=p.w*v.w;
        }
    }
    #pragma unroll
    for (int i = 0; i < 4; ++i) {
        float inv = 1.f / l[i];
        long long q = q0 + ty*4 + i;
        float4 r = make_float4(o[i][0]*inv, o[i][1]*inv, o[i][2]*inv, o[i][3]*inv);
        *(float4*)(O + base + q*D_ + (tx<<2)) = r;
    }
}

// ---------------- fused knowledge memory: scores + top-8 + softmax + gather ----------------
__global__ void knowledge_kernel(const float* __restrict__ Qm,
                                 const float* __restrict__ kK,
                                 const float* __restrict__ kV,
                                 float* __restrict__ out)
{
    __shared__ float kKs[KR_ * 32];      // d-major: kKs[d*32 + key]
    __shared__ float qs[16 * KR_];       // qs[r*256 + d]
    int t = threadIdx.x, w = t >> 5, lane = t & 31;
    int rowBase = blockIdx.x * 16;
    int r0 = w * 2, r1 = w * 2 + 1;

    for (int i = t; i < 16 * KR_ / 4; i += 256)
        ((float4*)qs)[i] = ((const float4*)(Qm + (size_t)rowBase * KR_))[i];

    float v0[TOPK_], v1[TOPK_]; int i0[TOPK_], i1[TOPK_];
    #pragma unroll
    for (int j = 0; j < TOPK_; ++j) {
        v0[j] = -3.0e38f; v1[j] = -3.0e38f; i0[j] = 0x7fffffff; i1[j] = 0x7fffffff;
    }

    for (int t0 = 0; t0 < NK_; t0 += 32) {
        __syncthreads();
        {
            int kk = t >> 3;
            int d0 = (t & 7) * 32;
            const float* src = kK + (size_t)(t0 + kk) * KR_ + d0;
            #pragma unroll
            for (int j = 0; j < 32; j += 4) {
                float4 vv = *(const float4*)(src + j);
                kKs[(d0 + j + 0) * 32 + kk] = vv.x;
                kKs[(d0 + j + 1) * 32 + kk] = vv.y;
                kKs[(d0 + j + 2) * 32 + kk] = vv.z;
                kKs[(d0 + j + 3) * 32 + kk] = vv.w;
            }
        }
        __syncthreads();
        float a0 = 0.f, a1 = 0.f;
        #pragma unroll 8
        for (int d = 0; d < KR_; d += 4) {
            float4 qa = *(const float4*)(qs + r0 * KR_ + d);
            float4 qb = *(const float4*)(qs + r1 * KR_ + d);
            float k0v = kKs[(d + 0) * 32 + lane];
            float k1v = kKs[(d + 1) * 32 + lane];
            float k2v = kKs[(d + 2) * 32 + lane];
            float k3v = kKs[(d + 3) * 32 + lane];
            a0 += qa.x * k0v; a0 += qa.y * k1v; a0 += qa.z * k2v; a0 += qa.w * k3v;
            a1 += qb.x * k0v; a1 += qb.y * k1v; a1 += qb.z * k2v; a1 += qb.w * k3v;
        }
        int keyIdx = t0 + lane;
        if (a0 > v0[TOPK_-1]) {
            v0[TOPK_-1] = a0; i0[TOPK_-1] = keyIdx;
            #pragma unroll
            for (int j = TOPK_-1; j > 0; --j)
                if (v0[j] > v0[j-1]) {
                    float tv = v0[j]; v0[j] = v0[j-1]; v0[j-1] = tv;
                    int ti = i0[j]; i0[j] = i0[j-1]; i0[j-1] = ti;
                }
        }
        if (a1 > v1[TOPK_-1]) {
            v1[TOPK_-1] = a1; i1[TOPK_-1] = keyIdx;
            #pragma unroll
            for (int j = TOPK_-1; j > 0; --j)
                if (v1[j] > v1[j-1]) {
                    float tv = v1[j]; v1[j] = v1[j-1]; v1[j-1] = tv;
                    int ti = i1[j]; i1[j] = i1[j-1]; i1[j-1] = ti;
                }
        }
    }

    #pragma unroll
    for (int rr = 0; rr < 2; ++rr) {
        float* lv = rr ? v1 : v0;
        int*   li = rr ? i1 : i0;
        int gr = rowBase + (rr ? r1 : r0);
        float tv[TOPK_]; int ti[TOPK_];
        int p = 0;
        #pragma unroll
        for (int it = 0; it < TOPK_; ++it) {
            float bv = lv[p];
            int   bi = li[p];
            float mv = bv; int mi = bi;
            #pragma unroll
            for (int off = 16; off > 0; off >>= 1) {
                float ov = __shfl_xor_sync(0xffffffffu, mv, off);
                int   oi = __shfl_xor_sync(0xffffffffu, mi, off);
                if (ov > mv || (ov == mv && oi < mi)) { mv = ov; mi = oi; }
            }
            tv[it] = mv; ti[it] = mi;
            if (bi == mi) ++p;
        }
        float mx = tv[0] * 0.0625f;
        float w8[TOPK_]; float ssum = 0.f;
        #pragma unroll
        for (int k2 = 0; k2 < TOPK_; ++k2) { w8[k2] = __expf(tv[k2] * 0.0625f - mx); ssum += w8[k2]; }
        float inv = 1.f / ssum;
        for (int j = 0; j < D_ / 32; ++j) {
            int d = j * 32 + lane;
            float acc = 0.f;
            #pragma unroll
            for (int k2 = 0; k2 < TOPK_; ++k2)
                acc += w8[k2] * kV[(size_t)ti[k2] * D_ + d];
            out[(size_t)gr * D_ + d] += acc * inv;
        }
    }
}

// ---------------- host orchestration ----------------
extern "C" void kernel_launch(void* const* d_in, const int* in_sizes, int n_in,
                              void* d_out, int out_size)
{
    (void)in_sizes; (void)n_in; (void)out_size;
    const float* x   = (const float*)d_in[0];
    const float* imp = (const float*)d_in[1];
    const float* Wc  = (const float*)d_in[2];
    const float* WQ  = (const float*)d_in[3];
    const float* WK  = (const float*)d_in[4];
    const float* WV  = (const float*)d_in[5];
    const float* Wm  = (const float*)d_in[6];
    const float* cn  = (const float*)d_in[7];
    const float* pool= (const float*)d_in[8];
    const float* kK  = (const float*)d_in[9];
    const float* kV  = (const float*)d_in[10];
    const float* WO  = (const float*)d_in[11];
    const float* g1  = (const float*)d_in[12];
    const float* b1  = (const float*)d_in[13];
    const float* g2  = (const float*)d_in[14];
    const float* b2  = (const float*)d_in[15];
    float* out = (float*)d_out;

    float *nx, *sc, *h, *e, *q, *k, *v, *ao;
    cudaGetSymbolAddress((void**)&nx, g_nx);
    cudaGetSymbolAddress((void**)&sc, g_sc);
    cudaGetSymbolAddress((void**)&h,  g_h);
    cudaGetSymbolAddress((void**)&e,  g_e);
    cudaGetSymbolAddress((void**)&q,  g_q);
    cudaGetSymbolAddress((void**)&k,  g_k);
    cudaGetSymbolAddress((void**)&v,  g_v);
    cudaGetSymbolAddress((void**)&ao, g_ao);

    const long long BRD = (long long)B_*R_*D_;

    // ---- attention sub-block ----
    ln_kernel<<<B_*S_, 256>>>(x, g1, b1, nx);
    route_kernel<<<dim3(NBLK_, B_), 256>>>(nx, imp, Wc, WQ, WK, WV, 64);
    reduce_norm_kernel<<<4, 32>>>(0);
    mix_sc_kernel<<<(B_*D_*R_ + 255)/256, 256>>>(cn, 0, sc);
    // h[b] = nx[b] @ sc[b]   (S x D) @ (D x R)
    sgemm_kernel<false><<<dim3(R_/64, S_/128, B_), 256>>>(
        nx, sc, h, S_, R_, D_, (long long)S_*D_, (long long)D_*R_, (long long)S_*R_, nullptr);
    mix_e_kernel<<<dim3((B_*R_*D_ + 255)/256, 3), 256>>>(pool);
    // Q/K/V[b] = h[b] @ e_x[b]   (S x R) @ (R x D)
    sgemm_kernel<false><<<dim3(D_/64, S_/128, B_), 256>>>(
        h, e + 0*BRD, q, S_, D_, R_, (long long)S_*R_, (long long)R_*D_, (long long)S_*D_, nullptr);
    sgemm_kernel<false><<<dim3(D_/64, S_/128, B_), 256>>>(
        h, e + 1*BRD, k, S_, D_, R_, (long long)S_*R_, (long long)R_*D_, (long long)S_*D_, nullptr);
    sgemm_kernel<false><<<dim3(D_/64, S_/128, B_), 256>>>(
        h, e + 2*BRD, v, S_, D_, R_, (long long)S_*R_, (long long)R_*D_, (long long)S_*D_, nullptr);
    attn_kernel<<<dim3(S_/32, H_, B_), 128>>>(q, k, v, ao);
    // out = x + ao @ WO^T    ([B*S, D] @ [D, D]^T), NT
    sgemm_kernel<true><<<dim3(D_/64, (B_*S_)/128, 1), 256>>>(
        ao, WO, out, B_*S_, D_, D_, 0, 0, 0, x);

    // ---- memory sub-block ----
    ln_kernel<<<B_*S_, 256>>>(out, g2, b2, nx);
    route_kernel<<<dim3(NBLK_, B_), 256>>>(nx, imp, Wm, Wm, Wm, Wm, 16);
    reduce_norm_kernel<<<1, 32>>>(4);
    mix_sc_kernel<<<(B_*D_*R_ + 255)/256, 256>>>(cn, 4, sc);
    // Qm[b] = nx2[b] @ mc[b]
    sgemm_kernel<false><<<dim3(R_/64, S_/128, B_), 256>>>(
        nx, sc, h, S_, R_, D_, (long long)S_*D_, (long long)D_*R_, (long long)S_*R_, nullptr);
    // fused: ms = Qm @ kK^T -> top-8 -> softmax -> gather(kV) -> out +=
    knowledge_kernel<<<(B_*S_)/16, 256>>>(h, kK, kV, out);
}

// round 6
// speedup vs baseline: 2.1620x; 1.0414x over previous
#include <cuda_runtime.h>
#include <math.h>
#include <stdint.h>

// ---------------- problem constants ----------------
#define B_    2
#define S_    2048
#define D_    1024
#define H_    16
#define DH_   64
#define R_    256
#define NK_   4096
#define KR_   256
#define TOPK_ 8
#define NBLK_ (S_/8)   // route blocks per batch (8 rows per block)

// ---------------- device scratch (allocation-free) ----------------
__device__ float g_nx [B_*S_*D_];        // LN output (reused for LN2)
__device__ float g_part[B_*NBLK_*64];    // routing partial sums
__device__ float g_rw [5*B_*16];         // normalized router weights: slots c,q,k,v,m
__device__ float g_sc [B_*D_*R_];        // compress matrix (reused for mc)
__device__ float g_h  [B_*S_*R_];        // h (reused for Qm)
__device__ float g_e  [3*(B_*R_*D_)];    // expand matrices q,k,v
__device__ float g_q  [B_*S_*D_];
__device__ float g_k  [B_*S_*D_];
__device__ float g_v  [B_*S_*D_];
__device__ float g_ao [B_*S_*D_];

// ---------------- mma / cp.async helpers ----------------
__device__ __forceinline__ void mma_tf32(float* d, const uint32_t* a, const uint32_t* b) {
    asm volatile(
        "mma.sync.aligned.m16n8k8.row.col.f32.tf32.tf32.f32 "
        "{%0,%1,%2,%3},{%4,%5,%6,%7},{%8,%9},{%0,%1,%2,%3};"
        : "+f"(d[0]), "+f"(d[1]), "+f"(d[2]), "+f"(d[3])
        : "r"(a[0]), "r"(a[1]), "r"(a[2]), "r"(a[3]), "r"(b[0]), "r"(b[1]));
}

__device__ __forceinline__ void cpa16(float* smem, const float* g) {
    uint32_t s = (uint32_t)__cvta_generic_to_shared(smem);
    asm volatile("cp.async.cg.shared.global [%0], [%1], 16;\n" :: "r"(s), "l"(g));
}
#define CPA_COMMIT() asm volatile("cp.async.commit_group;\n" ::: "memory")
#define CPA_WAIT2()  asm volatile("cp.async.wait_group 2;\n" ::: "memory")

// ---------------- LayerNorm: one block per row ----------------
__global__ void ln_kernel(const float* __restrict__ x,
                          const float* __restrict__ g,
                          const float* __restrict__ b,
                          float* __restrict__ out)
{
    int row = blockIdx.x;                 // 0 .. B*S-1
    int t = threadIdx.x;                  // 256
    const float4* xr = (const float4*)(x + (size_t)row * D_);
    float4 v = xr[t];
    float s1 = v.x + v.y + v.z + v.w;
    float s2 = v.x*v.x + v.y*v.y + v.z*v.z + v.w*v.w;
    #pragma unroll
    for (int off = 16; off > 0; off >>= 1) {
        s1 += __shfl_xor_sync(0xffffffffu, s1, off);
        s2 += __shfl_xor_sync(0xffffffffu, s2, off);
    }
    __shared__ float sa[8], sb[8];
    __shared__ float s_mu, s_rs;
    int warp = t >> 5, lane = t & 31;
    if (lane == 0) { sa[warp] = s1; sb[warp] = s2; }
    __syncthreads();
    if (t == 0) {
        float ta = 0.f, tb = 0.f;
        #pragma unroll
        for (int w = 0; w < 8; ++w) { ta += sa[w]; tb += sb[w]; }
        float mu = ta * (1.0f / D_);
        float var = tb * (1.0f / D_) - mu * mu;
        s_mu = mu;
        s_rs = rsqrtf(var + 1e-5f);
    }
    __syncthreads();
    float mu = s_mu, rs = s_rs;
    float4 gg = ((const float4*)g)[t];
    float4 bb = ((const float4*)b)[t];
    float4 o;
    o.x = (v.x - mu) * rs * gg.x + bb.x;
    o.y = (v.y - mu) * rs * gg.y + bb.y;
    o.z = (v.z - mu) * rs * gg.z + bb.z;
    o.w = (v.w - mu) * rs * gg.w + bb.w;
    ((float4*)(out + (size_t)row * D_))[t] = o;
}

// ---------------- routing: logits + softmax + importance pool (deterministic) ----------------
__global__ void route_kernel(const float* __restrict__ nx, const float* __restrict__ imp,
                             const float* __restrict__ W0, const float* __restrict__ W1,
                             const float* __restrict__ W2, const float* __restrict__ W3,
                             int nPairs)
{
    __shared__ float xs[8][128];
    __shared__ float ws[64][129];
    __shared__ float lg[8][64];
    int t = threadIdx.x;
    int b = blockIdx.y;
    int r0 = blockIdx.x * 8;
    float acc[8] = {0.f,0.f,0.f,0.f,0.f,0.f,0.f,0.f};
    for (int c = 0; c < 8; ++c) {
        int d0 = c * 128;
        for (int idx = t; idx < 8*128; idx += 256) {
            int r = idx >> 7, dd = idx & 127;
            xs[r][dd] = nx[((size_t)(b*S_ + r0 + r))*D_ + d0 + dd];
        }
        for (int idx = t; idx < nPairs*128; idx += 256) {
            int p = idx >> 7, dd = idx & 127;
            const float* Wp = (p < 16) ? W0 : (p < 32) ? W1 : (p < 48) ? W2 : W3;
            ws[p][dd] = Wp[(size_t)(p & 15)*D_ + d0 + dd];
        }
        __syncthreads();
        if (t < nPairs) {
            for (int dd = 0; dd < 128; ++dd) {
                float wv = ws[t][dd];
                #pragma unroll
                for (int r = 0; r < 8; ++r) acc[r] += wv * xs[r][dd];
            }
        }
        __syncthreads();
    }
    if (t < nPairs) {
        #pragma unroll
        for (int r = 0; r < 8; ++r) lg[r][t] = acc[r];
    }
    __syncthreads();
    if (t < nPairs) {
        int router = t >> 4;
        float contrib = 0.f;
        for (int r = 0; r < 8; ++r) {
            float mx = -1e30f;
            for (int e = 0; e < 16; ++e) mx = fmaxf(mx, lg[r][(router<<4) + e]);
            float ssum = 0.f;
            for (int e = 0; e < 16; ++e) ssum += __expf(lg[r][(router<<4) + e] - mx);
            float p = __expf(lg[r][t] - mx) / ssum;
            contrib += imp[b*S_ + r0 + r] * p;
        }
        g_part[((size_t)(b*NBLK_) + blockIdx.x)*64 + t] = contrib;
    }
}

// grid nRouters, block 32. Deterministic reduction of partials + normalization.
__global__ void reduce_norm_kernel(int slotBase)
{
    int r = blockIdx.x;
    int lane = threadIdx.x;
    int b = lane >> 4, e = lane & 15;
    float acc = 0.f;
    for (int blk = 0; blk < NBLK_; ++blk)
        acc += g_part[((size_t)(b*NBLK_) + blk)*64 + (r<<4) + e];
    float gs = acc;
    gs += __shfl_xor_sync(0xffffffffu, gs, 1);
    gs += __shfl_xor_sync(0xffffffffu, gs, 2);
    gs += __shfl_xor_sync(0xffffffffu, gs, 4);
    gs += __shfl_xor_sync(0xffffffffu, gs, 8);
    g_rw[(slotBase + r)*B_*16 + b*16 + e] = acc / (gs + 1e-8f);
}

// ---------------- weighted pool mixes ----------------
__global__ void mix_sc_kernel(const float* __restrict__ cn, int slot, float* __restrict__ out)
{
    int idx = blockIdx.x*256 + threadIdx.x;
    if (idx >= B_*D_*R_) return;
    int b = idx / (D_*R_);
    int dr = idx - b*(D_*R_);
    float acc = 0.f;
    #pragma unroll
    for (int n = 0; n < 16; ++n)
        acc += g_rw[slot*B_*16 + b*16 + n] * cn[(size_t)n*(D_*R_) + dr];
    out[idx] = acc;
}

__global__ void mix_e_kernel(const float* __restrict__ pool)
{
    int idx = blockIdx.x*256 + threadIdx.x;
    if (idx >= B_*R_*D_) return;
    int which = blockIdx.y;               // 0=q 1=k 2=v -> rw slots 1..3
    int b = idx / (R_*D_);
    int rd = idx - b*(R_*D_);
    float acc = 0.f;
    #pragma unroll
    for (int n = 0; n < 16; ++n)
        acc += g_rw[(which+1)*B_*16 + b*16 + n] * pool[(size_t)n*(R_*D_) + rd];
    g_e[(size_t)which*(B_*R_*D_) + idx] = acc;
}

// ---------------- 128x64 3-stage cp.async TF32 tensor-core SGEMM ----------------
// C[M,N] = A[M,K] @ B (NN: B[K,N] ; NT: B[N,K]) (+ addsrc[M,N] if non-null)
// grid (N/64, M/128, batch), block 256 = 8 warps (4 along M x 2 along N).
// K-tile 32, 3-stage cp.async pipeline. tf32 via HW truncation inside HMMA.
// smem layout (dynamic, 82944B):
//   A stages: 3 x [128][36] floats  (pad 36 -> frag loads conflict-free)
//   B stages: 3 x 2304 floats ( NN: [32][72] ; NT: [64][36] )
#define AS_STRIDE (128*36)
#define BS_STRIDE 2304
#define SMEM_GEMM_BYTES ((3*AS_STRIDE + 3*BS_STRIDE)*4)

template<bool TB>
__global__ void sgemm_kernel(const float* __restrict__ A, const float* __restrict__ Bm,
                             float* __restrict__ C, int M, int N, int K,
                             long long sA, long long sB, long long sC,
                             const float* __restrict__ addsrc)
{
    extern __shared__ float smem[];
    float* asBase = smem;
    float* bsBase = smem + 3*AS_STRIDE;
    A  += (long long)blockIdx.z * sA;
    Bm += (long long)blockIdx.z * sB;
    C  += (long long)blockIdx.z * sC;
    int m0 = blockIdx.y * 128, n0 = blockIdx.x * 64;
    int t = threadIdx.x;
    int warp = t >> 5, lane = t & 31;
    int wm = warp >> 1, wn = warp & 1;   // 4 x 2 warp grid
    int qr = lane >> 2, qc = lane & 3;   // mma fragment coords

    float acc[2][4][4];
    #pragma unroll
    for (int i = 0; i < 2; ++i)
        #pragma unroll
        for (int j = 0; j < 4; ++j)
            #pragma unroll
            for (int c = 0; c < 4; ++c) acc[i][j][c] = 0.f;

    // stage loader: A tile 128x32 (1024 16B chunks), B tile 2304 floats (512 chunks)
    auto stage_load = [&](int stage, int kt) {
        float* asS = asBase + stage * AS_STRIDE;
        float* bsS = bsBase + stage * BS_STRIDE;
        int k0 = kt * 32;
        #pragma unroll
        for (int i = 0; i < 4; ++i) {
            int c = t + i*256;
            int m = c >> 3, k4 = (c & 7) << 2;
            cpa16(asS + m*36 + k4, A + (long long)(m0 + m)*K + k0 + k4);
        }
        #pragma unroll
        for (int i = 0; i < 2; ++i) {
            int c = t + i*256;
            if (TB) {
                int n = c >> 3, k4 = (c & 7) << 2;
                cpa16(bsS + n*36 + k4, Bm + (long long)(n0 + n)*K + k0 + k4);
            } else {
                int kr = c >> 4, n4 = (c & 15) << 2;
                cpa16(bsS + kr*72 + n4, Bm + (long long)(k0 + kr)*N + n0 + n4);
            }
        }
    };

    int nk = K >> 5;                 // K multiple of 32 for all call sites
    stage_load(0, 0); CPA_COMMIT();
    stage_load(1, 1); CPA_COMMIT();

    for (int kt = 0; kt < nk; ++kt) {
        if (kt + 2 < nk) stage_load((kt + 2) % 3, kt + 2);
        CPA_COMMIT();                 // (possibly empty) keeps group count uniform
        CPA_WAIT2();
        __syncthreads();
        float* asS = asBase + (kt % 3) * AS_STRIDE;
        float* bsS = bsBase + (kt % 3) * BS_STRIDE;
        #pragma unroll
        for (int ks = 0; ks < 32; ks += 8) {
            uint32_t af[2][4], bf[4][2];
            #pragma unroll
            for (int mt = 0; mt < 2; ++mt) {
                int mb = wm*32 + mt*16;
                const float* ap = asS + (mb + qr)*36 + ks + qc;
                af[mt][0] = __float_as_uint(ap[0]);
                af[mt][1] = __float_as_uint(ap[8*36]);
                af[mt][2] = __float_as_uint(ap[4]);
                af[mt][3] = __float_as_uint(ap[8*36 + 4]);
            }
            #pragma unroll
            for (int nt = 0; nt < 4; ++nt) {
                int nb = wn*32 + nt*8;
                if (TB) {
                    const float* bp = bsS + (nb + qr)*36 + ks + qc;
                    bf[nt][0] = __float_as_uint(bp[0]);
                    bf[nt][1] = __float_as_uint(bp[4]);
                } else {
                    const float* bp = bsS + (ks + qc)*72 + nb + qr;
                    bf[nt][0] = __float_as_uint(bp[0]);
                    bf[nt][1] = __float_as_uint(bp[4*72]);
                }
            }
            #pragma unroll
            for (int mt = 0; mt < 2; ++mt)
                #pragma unroll
                for (int nt = 0; nt < 4; ++nt)
                    mma_tf32(acc[mt][nt], af[mt], bf[nt]);
        }
        __syncthreads();
    }

    // epilogue: fragment (mt,nt): d0,d1 at (row, 2qc), d2,d3 at (row+8, 2qc)
    #pragma unroll
    for (int mt = 0; mt < 2; ++mt) {
        long long row = m0 + wm*32 + mt*16 + qr;
        #pragma unroll
        for (int nt = 0; nt < 4; ++nt) {
            long long col = n0 + wn*32 + nt*8 + qc*2;
            long long off0 = row * N + col;
            long long off1 = (row + 8) * N + col;
            float2 r0 = make_float2(acc[mt][nt][0], acc[mt][nt][1]);
            float2 r1 = make_float2(acc[mt][nt][2], acc[mt][nt][3]);
            if (addsrc) {
                float2 a0 = *(const float2*)(addsrc + off0);
                float2 a1 = *(const float2*)(addsrc + off1);
                r0.x += a0.x; r0.y += a0.y; r1.x += a1.x; r1.y += a1.y;
            }
            *(float2*)(C + off0) = r0;
            *(float2*)(C + off1) = r1;
        }
    }
}

// ---------------- block-tiled flash attention (fp32) ----------------
// grid (S/32, H, B), block 128. Tile: 32 queries x 64 keys, dh=64.
__global__ void attn_kernel(const float* __restrict__ Q, const float* __restrict__ Kg,
                            const float* __restrict__ Vg, float* __restrict__ O)
{
    __shared__ __align__(16) float Qs[64][36];   // [d][q]
    __shared__ __align__(16) float Ks[64][68];   // [d][k]; reused as Ps[64][36] ([k][q])
    __shared__ __align__(16) float Vs[64][68];   // [k][d]
    float* Ps = &Ks[0][0];
    int b = blockIdx.z, h = blockIdx.y;
    int q0 = blockIdx.x * 32;
    int t = threadIdx.x;            // 128
    int tx = t & 15, ty = t >> 4;   // ty 0..7 (q groups of 4), tx 0..15 (k/d groups of 4)
    long long base = ((long long)(b*S_))*D_ + (long long)h*DH_;

    for (int i = t; i < 32*16; i += 128) {
        int qi = i >> 4, d4 = (i & 15) << 2;
        float4 v = *(const float4*)(Q + base + (long long)(q0+qi)*D_ + d4);
        Qs[d4+0][qi]=v.x; Qs[d4+1][qi]=v.y; Qs[d4+2][qi]=v.z; Qs[d4+3][qi]=v.w;
    }
    float m[4], l[4], o[4][4];
    #pragma unroll
    for (int i = 0; i < 4; ++i) {
        m[i] = -1e30f; l[i] = 0.f;
        #pragma unroll
        for (int j = 0; j < 4; ++j) o[i][j] = 0.f;
    }
    int lastKT = (q0 + 31) >> 6;
    for (int kt = 0; kt <= lastKT; ++kt) {
        int k0 = kt << 6;
        __syncthreads();
        for (int i = t; i < 64*16; i += 128) {
            int kk = i >> 4, d4 = (i & 15) << 2;
            float4 kv = *(const float4*)(Kg + base + (long long)(k0+kk)*D_ + d4);
            Ks[d4+0][kk]=kv.x; Ks[d4+1][kk]=kv.y; Ks[d4+2][kk]=kv.z; Ks[d4+3][kk]=kv.w;
            float4 vv = *(const float4*)(Vg + base + (long long)(k0+kk)*D_ + d4);
            *(float4*)&Vs[kk][d4] = vv;
        }
        __syncthreads();
        float s[4][4] = {};
        #pragma unroll 8
        for (int d = 0; d < 64; ++d) {
            float4 a = *(const float4*)&Qs[d][ty*4];
            float4 kb = *(const float4*)&Ks[d][tx*4];
            s[0][0]+=a.x*kb.x; s[0][1]+=a.x*kb.y; s[0][2]+=a.x*kb.z; s[0][3]+=a.x*kb.w;
            s[1][0]+=a.y*kb.x; s[1][1]+=a.y*kb.y; s[1][2]+=a.y*kb.z; s[1][3]+=a.y*kb.w;
            s[2][0]+=a.z*kb.x; s[2][1]+=a.z*kb.y; s[2][2]+=a.z*kb.z; s[2][3]+=a.z*kb.w;
            s[3][0]+=a.w*kb.x; s[3][1]+=a.w*kb.y; s[3][2]+=a.w*kb.z; s[3][3]+=a.w*kb.w;
        }
        #pragma unroll
        for (int i = 0; i < 4; ++i) {
            int qg = q0 + ty*4 + i;
            #pragma unroll
            for (int j = 0; j < 4; ++j) {
                int kg = k0 + tx*4 + j;
                float v = s[i][j] * 0.125f;
                s[i][j] = (kg > qg) ? -1e30f : v;
            }
        }
        float c[4];
        #pragma unroll
        for (int i = 0; i < 4; ++i) {
            float rm = fmaxf(fmaxf(s[i][0], s[i][1]), fmaxf(s[i][2], s[i][3]));
            #pragma unroll
            for (int off = 8; off > 0; off >>= 1)
                rm = fmaxf(rm, __shfl_xor_sync(0xffffffffu, rm, off));
            float mn = fmaxf(m[i], rm);
            c[i] = __expf(m[i] - mn);
            float rs = 0.f;
            #pragma unroll
            for (int j = 0; j < 4; ++j) { s[i][j] = __expf(s[i][j] - mn); rs += s[i][j]; }
            #pragma unroll
            for (int off = 8; off > 0; off >>= 1)
                rs += __shfl_xor_sync(0xffffffffu, rs, off);
            l[i] = l[i]*c[i] + rs;
            m[i] = mn;
            #pragma unroll
            for (int j = 0; j < 4; ++j) o[i][j] *= c[i];
        }
        __syncthreads();
        #pragma unroll
        for (int i = 0; i < 4; ++i)
            #pragma unroll
            for (int j = 0; j < 4; ++j)
                Ps[(tx*4+j)*36 + ty*4+i] = s[i][j];
        __syncthreads();
        #pragma unroll 8
        for (int kk = 0; kk < 64; ++kk) {
            float4 p = *(const float4*)&Ps[kk*36 + ty*4];
            float4 v = *(const float4*)&Vs[kk][tx*4];
            o[0][0]+=p.x*v.x; o[0][1]+=p.x*v.y; o[0][2]+=p.x*v.z; o[0][3]+=p.x*v.w;
            o[1][0]+=p.y*v.x; o[1][1]+=p.y*v.y; o[1][2]+=p.y*v.z; o[1][3]+=p.y*v.w;
            o[2][0]+=p.z*v.x; o[2][1]+=p.z*v.y; o[2][2]+=p.z*v.z; o[2][3]+=p.z*v.w;
            o[3][0]+=p.w*v.x; o[3][1]+=p.w*v.y; o[3][2]+=p.w*v.z; o[3][3]+=p.w*v.w;
        }
    }
    #pragma unroll
    for (int i = 0; i < 4; ++i) {
        float inv = 1.f / l[i];
        long long q = q0 + ty*4 + i;
        float4 r = make_float4(o[i][0]*inv, o[i][1]*inv, o[i][2]*inv, o[i][3]*inv);
        *(float4*)(O + base + q*D_ + (tx<<2)) = r;
    }
}

// ---------------- fused knowledge memory: scores + top-8 + softmax + gather ----------------
__global__ void knowledge_kernel(const float* __restrict__ Qm,
                                 const float* __restrict__ kK,
                                 const float* __restrict__ kV,
                                 float* __restrict__ out)
{
    __shared__ float kKs[KR_ * 32];      // d-major: kKs[d*32 + key]
    __shared__ float qs[16 * KR_];       // qs[r*256 + d]
    int t = threadIdx.x, w = t >> 5, lane = t & 31;
    int rowBase = blockIdx.x * 16;
    int r0 = w * 2, r1 = w * 2 + 1;

    for (int i = t; i < 16 * KR_ / 4; i += 256)
        ((float4*)qs)[i] = ((const float4*)(Qm + (size_t)rowBase * KR_))[i];

    float v0[TOPK_], v1[TOPK_]; int i0[TOPK_], i1[TOPK_];
    #pragma unroll
    for (int j = 0; j < TOPK_; ++j) {
        v0[j] = -3.0e38f; v1[j] = -3.0e38f; i0[j] = 0x7fffffff; i1[j] = 0x7fffffff;
    }

    for (int t0 = 0; t0 < NK_; t0 += 32) {
        __syncthreads();
        {
            int kk = t >> 3;
            int d0 = (t & 7) * 32;
            const float* src = kK + (size_t)(t0 + kk) * KR_ + d0;
            #pragma unroll
            for (int j = 0; j < 32; j += 4) {
                float4 vv = *(const float4*)(src + j);
                kKs[(d0 + j + 0) * 32 + kk] = vv.x;
                kKs[(d0 + j + 1) * 32 + kk] = vv.y;
                kKs[(d0 + j + 2) * 32 + kk] = vv.z;
                kKs[(d0 + j + 3) * 32 + kk] = vv.w;
            }
        }
        __syncthreads();
        float a0 = 0.f, a1 = 0.f;
        #pragma unroll 8
        for (int d = 0; d < KR_; d += 4) {
            float4 qa = *(const float4*)(qs + r0 * KR_ + d);
            float4 qb = *(const float4*)(qs + r1 * KR_ + d);
            float k0v = kKs[(d + 0) * 32 + lane];
            float k1v = kKs[(d + 1) * 32 + lane];
            float k2v = kKs[(d + 2) * 32 + lane];
            float k3v = kKs[(d + 3) * 32 + lane];
            a0 += qa.x * k0v; a0 += qa.y * k1v; a0 += qa.z * k2v; a0 += qa.w * k3v;
            a1 += qb.x * k0v; a1 += qb.y * k1v; a1 += qb.z * k2v; a1 += qb.w * k3v;
        }
        int keyIdx = t0 + lane;
        if (a0 > v0[TOPK_-1]) {
            v0[TOPK_-1] = a0; i0[TOPK_-1] = keyIdx;
            #pragma unroll
            for (int j = TOPK_-1; j > 0; --j)
                if (v0[j] > v0[j-1]) {
                    float tv = v0[j]; v0[j] = v0[j-1]; v0[j-1] = tv;
                    int ti = i0[j]; i0[j] = i0[j-1]; i0[j-1] = ti;
                }
        }
        if (a1 > v1[TOPK_-1]) {
            v1[TOPK_-1] = a1; i1[TOPK_-1] = keyIdx;
            #pragma unroll
            for (int j = TOPK_-1; j > 0; --j)
                if (v1[j] > v1[j-1]) {
                    float tv = v1[j]; v1[j] = v1[j-1]; v1[j-1] = tv;
                    int ti = i1[j]; i1[j] = i1[j-1]; i1[j-1] = ti;
                }
        }
    }

    #pragma unroll
    for (int rr = 0; rr < 2; ++rr) {
        float* lv = rr ? v1 : v0;
        int*   li = rr ? i1 : i0;
        int gr = rowBase + (rr ? r1 : r0);
        float tv[TOPK_]; int ti[TOPK_];
        int p = 0;
        #pragma unroll
        for (int it = 0; it < TOPK_; ++it) {
            float bv = lv[p];
            int   bi = li[p];
            float mv = bv; int mi = bi;
            #pragma unroll
            for (int off = 16; off > 0; off >>= 1) {
                float ov = __shfl_xor_sync(0xffffffffu, mv, off);
                int   oi = __shfl_xor_sync(0xffffffffu, mi, off);
                if (ov > mv || (ov == mv && oi < mi)) { mv = ov; mi = oi; }
            }
            tv[it] = mv; ti[it] = mi;
            if (bi == mi) ++p;
        }
        float mx = tv[0] * 0.0625f;
        float w8[TOPK_]; float ssum = 0.f;
        #pragma unroll
        for (int k2 = 0; k2 < TOPK_; ++k2) { w8[k2] = __expf(tv[k2] * 0.0625f - mx); ssum += w8[k2]; }
        float inv = 1.f / ssum;
        for (int j = 0; j < D_ / 32; ++j) {
            int d = j * 32 + lane;
            float acc = 0.f;
            #pragma unroll
            for (int k2 = 0; k2 < TOPK_; ++k2)
                acc += w8[k2] * kV[(size_t)ti[k2] * D_ + d];
            out[(size_t)gr * D_ + d] += acc * inv;
        }
    }
}

// ---------------- host orchestration ----------------
extern "C" void kernel_launch(void* const* d_in, const int* in_sizes, int n_in,
                              void* d_out, int out_size)
{
    (void)in_sizes; (void)n_in; (void)out_size;
    const float* x   = (const float*)d_in[0];
    const float* imp = (const float*)d_in[1];
    const float* Wc  = (const float*)d_in[2];
    const float* WQ  = (const float*)d_in[3];
    const float* WK  = (const float*)d_in[4];
    const float* WV  = (const float*)d_in[5];
    const float* Wm  = (const float*)d_in[6];
    const float* cn  = (const float*)d_in[7];
    const float* pool= (const float*)d_in[8];
    const float* kK  = (const float*)d_in[9];
    const float* kV  = (const float*)d_in[10];
    const float* WO  = (const float*)d_in[11];
    const float* g1  = (const float*)d_in[12];
    const float* b1  = (const float*)d_in[13];
    const float* g2  = (const float*)d_in[14];
    const float* b2  = (const float*)d_in[15];
    float* out = (float*)d_out;

    float *nx, *sc, *h, *e, *q, *k, *v, *ao;
    cudaGetSymbolAddress((void**)&nx, g_nx);
    cudaGetSymbolAddress((void**)&sc, g_sc);
    cudaGetSymbolAddress((void**)&h,  g_h);
    cudaGetSymbolAddress((void**)&e,  g_e);
    cudaGetSymbolAddress((void**)&q,  g_q);
    cudaGetSymbolAddress((void**)&k,  g_k);
    cudaGetSymbolAddress((void**)&v,  g_v);
    cudaGetSymbolAddress((void**)&ao, g_ao);

    cudaFuncSetAttribute(sgemm_kernel<false>,
        cudaFuncAttributeMaxDynamicSharedMemorySize, SMEM_GEMM_BYTES);
    cudaFuncSetAttribute(sgemm_kernel<true>,
        cudaFuncAttributeMaxDynamicSharedMemorySize, SMEM_GEMM_BYTES);

    const long long BRD = (long long)B_*R_*D_;

    // ---- attention sub-block ----
    ln_kernel<<<B_*S_, 256>>>(x, g1, b1, nx);
    route_kernel<<<dim3(NBLK_, B_), 256>>>(nx, imp, Wc, WQ, WK, WV, 64);
    reduce_norm_kernel<<<4, 32>>>(0);
    mix_sc_kernel<<<(B_*D_*R_ + 255)/256, 256>>>(cn, 0, sc);
    // h[b] = nx[b] @ sc[b]   (S x D) @ (D x R)
    sgemm_kernel<false><<<dim3(R_/64, S_/128, B_), 256, SMEM_GEMM_BYTES>>>(
        nx, sc, h, S_, R_, D_, (long long)S_*D_, (long long)D_*R_, (long long)S_*R_, nullptr);
    mix_e_kernel<<<dim3((B_*R_*D_ + 255)/256, 3), 256>>>(pool);
    // Q/K/V[b] = h[b] @ e_x[b]   (S x R) @ (R x D)
    sgemm_kernel<false><<<dim3(D_/64, S_/128, B_), 256, SMEM_GEMM_BYTES>>>(
        h, e + 0*BRD, q, S_, D_, R_, (long long)S_*R_, (long long)R_*D_, (long long)S_*D_, nullptr);
    sgemm_kernel<false><<<dim3(D_/64, S_/128, B_), 256, SMEM_GEMM_BYTES>>>(
        h, e + 1*BRD, k, S_, D_, R_, (long long)S_*R_, (long long)R_*D_, (long long)S_*D_, nullptr);
    sgemm_kernel<false><<<dim3(D_/64, S_/128, B_), 256, SMEM_GEMM_BYTES>>>(
        h, e + 2*BRD, v, S_, D_, R_, (long long)S_*R_, (long long)R_*D_, (long long)S_*D_, nullptr);
    attn_kernel<<<dim3(S_/32, H_, B_), 128>>>(q, k, v, ao);
    // out = x + ao @ WO^T    ([B*S, D] @ [D, D]^T), NT
    sgemm_kernel<true><<<dim3(D_/64, (B_*S_)/128, 1), 256, SMEM_GEMM_BYTES>>>(
        ao, WO, out, B_*S_, D_, D_, 0, 0, 0, x);

    // ---- memory sub-block ----
    ln_kernel<<<B_*S_, 256>>>(out, g2, b2, nx);
    route_kernel<<<dim3(NBLK_, B_), 256>>>(nx, imp, Wm, Wm, Wm, Wm, 16);
    reduce_norm_kernel<<<1, 32>>>(4);
    mix_sc_kernel<<<(B_*D_*R_ + 255)/256, 256>>>(cn, 4, sc);
    // Qm[b] = nx2[b] @ mc[b]
    sgemm_kernel<false><<<dim3(R_/64, S_/128, B_), 256, SMEM_GEMM_BYTES>>>(
        nx, sc, h, S_, R_, D_, (long long)S_*D_, (long long)D_*R_, (long long)S_*R_, nullptr);
    // fused: ms = Qm @ kK^T -> top-8 -> softmax -> gather(kV) -> out +=
    knowledge_kernel<<<(B_*S_)/16, 256>>>(h, kK, kV, out);
}

// round 8
// speedup vs baseline: 2.6687x; 1.2343x over previous
#include <cuda_runtime.h>
#include <math.h>
#include <stdint.h>

// ---------------- problem constants ----------------
#define B_    2
#define S_    2048
#define D_    1024
#define H_    16
#define DH_   64
#define R_    256
#define NK_   4096
#define KR_   256
#define TOPK_ 8
#define NBLK_ (S_/8)   // route blocks per batch (8 rows per block)

// ---------------- device scratch (allocation-free) ----------------
__device__ float g_nx [B_*S_*D_];        // LN output (reused for LN2)
__device__ float g_part[B_*NBLK_*64];    // routing partial sums
__device__ float g_rw [5*B_*16];         // normalized router weights: slots c,q,k,v,m
__device__ float g_sc [B_*D_*R_];        // compress matrix (reused for mc)
__device__ float g_h  [B_*S_*R_];        // h (reused for Qm)
__device__ float g_e  [3*(B_*R_*D_)];    // expand matrices q,k,v
__device__ float g_q  [B_*S_*D_];
__device__ float g_k  [B_*S_*D_];
__device__ float g_v  [B_*S_*D_];
__device__ float g_ao [B_*S_*D_];

// ---------------- mma / cp.async helpers ----------------
__device__ __forceinline__ void mma_tf32(float* d, const uint32_t* a, const uint32_t* b) {
    asm volatile(
        "mma.sync.aligned.m16n8k8.row.col.f32.tf32.tf32.f32 "
        "{%0,%1,%2,%3},{%4,%5,%6,%7},{%8,%9},{%0,%1,%2,%3};"
        : "+f"(d[0]), "+f"(d[1]), "+f"(d[2]), "+f"(d[3])
        : "r"(a[0]), "r"(a[1]), "r"(a[2]), "r"(a[3]), "r"(b[0]), "r"(b[1]));
}

__device__ __forceinline__ void cpa16(float* smem, const float* g) {
    uint32_t s = (uint32_t)__cvta_generic_to_shared(smem);
    asm volatile("cp.async.cg.shared.global [%0], [%1], 16;\n" :: "r"(s), "l"(g));
}
#define CPA_COMMIT() asm volatile("cp.async.commit_group;\n" ::: "memory")
#define CPA_WAIT2()  asm volatile("cp.async.wait_group 2;\n" ::: "memory")

// ---------------- LayerNorm: one block per row ----------------
__global__ void ln_kernel(const float* __restrict__ x,
                          const float* __restrict__ g,
                          const float* __restrict__ b,
                          float* __restrict__ out)
{
    int row = blockIdx.x;                 // 0 .. B*S-1
    int t = threadIdx.x;                  // 256
    const float4* xr = (const float4*)(x + (size_t)row * D_);
    float4 v = xr[t];
    float s1 = v.x + v.y + v.z + v.w;
    float s2 = v.x*v.x + v.y*v.y + v.z*v.z + v.w*v.w;
    #pragma unroll
    for (int off = 16; off > 0; off >>= 1) {
        s1 += __shfl_xor_sync(0xffffffffu, s1, off);
        s2 += __shfl_xor_sync(0xffffffffu, s2, off);
    }
    __shared__ float sa[8], sb[8];
    __shared__ float s_mu, s_rs;
    int warp = t >> 5, lane = t & 31;
    if (lane == 0) { sa[warp] = s1; sb[warp] = s2; }
    __syncthreads();
    if (t == 0) {
        float ta = 0.f, tb = 0.f;
        #pragma unroll
        for (int w = 0; w < 8; ++w) { ta += sa[w]; tb += sb[w]; }
        float mu = ta * (1.0f / D_);
        float var = tb * (1.0f / D_) - mu * mu;
        s_mu = mu;
        s_rs = rsqrtf(var + 1e-5f);
    }
    __syncthreads();
    float mu = s_mu, rs = s_rs;
    float4 gg = ((const float4*)g)[t];
    float4 bb = ((const float4*)b)[t];
    float4 o;
    o.x = (v.x - mu) * rs * gg.x + bb.x;
    o.y = (v.y - mu) * rs * gg.y + bb.y;
    o.z = (v.z - mu) * rs * gg.z + bb.z;
    o.w = (v.w - mu) * rs * gg.w + bb.w;
    ((float4*)(out + (size_t)row * D_))[t] = o;
}

// ---------------- routing: logits + softmax + importance pool (deterministic) ----------------
__global__ void route_kernel(const float* __restrict__ nx, const float* __restrict__ imp,
                             const float* __restrict__ W0, const float* __restrict__ W1,
                             const float* __restrict__ W2, const float* __restrict__ W3,
                             int nPairs)
{
    __shared__ float xs[8][128];
    __shared__ float ws[64][129];
    __shared__ float lg[8][64];
    int t = threadIdx.x;
    int b = blockIdx.y;
    int r0 = blockIdx.x * 8;
    float acc[8] = {0.f,0.f,0.f,0.f,0.f,0.f,0.f,0.f};
    for (int c = 0; c < 8; ++c) {
        int d0 = c * 128;
        for (int idx = t; idx < 8*128; idx += 256) {
            int r = idx >> 7, dd = idx & 127;
            xs[r][dd] = nx[((size_t)(b*S_ + r0 + r))*D_ + d0 + dd];
        }
        for (int idx = t; idx < nPairs*128; idx += 256) {
            int p = idx >> 7, dd = idx & 127;
            const float* Wp = (p < 16) ? W0 : (p < 32) ? W1 : (p < 48) ? W2 : W3;
            ws[p][dd] = Wp[(size_t)(p & 15)*D_ + d0 + dd];
        }
        __syncthreads();
        if (t < nPairs) {
            for (int dd = 0; dd < 128; ++dd) {
                float wv = ws[t][dd];
                #pragma unroll
                for (int r = 0; r < 8; ++r) acc[r] += wv * xs[r][dd];
            }
        }
        __syncthreads();
    }
    if (t < nPairs) {
        #pragma unroll
        for (int r = 0; r < 8; ++r) lg[r][t] = acc[r];
    }
    __syncthreads();
    if (t < nPairs) {
        int router = t >> 4;
        float contrib = 0.f;
        for (int r = 0; r < 8; ++r) {
            float mx = -1e30f;
            for (int e = 0; e < 16; ++e) mx = fmaxf(mx, lg[r][(router<<4) + e]);
            float ssum = 0.f;
            for (int e = 0; e < 16; ++e) ssum += __expf(lg[r][(router<<4) + e] - mx);
            float p = __expf(lg[r][t] - mx) / ssum;
            contrib += imp[b*S_ + r0 + r] * p;
        }
        g_part[((size_t)(b*NBLK_) + blockIdx.x)*64 + t] = contrib;
    }
}

// grid nRouters, block 32. Deterministic reduction of partials + normalization.
__global__ void reduce_norm_kernel(int slotBase)
{
    int r = blockIdx.x;
    int lane = threadIdx.x;
    int b = lane >> 4, e = lane & 15;
    float acc = 0.f;
    for (int blk = 0; blk < NBLK_; ++blk)
        acc += g_part[((size_t)(b*NBLK_) + blk)*64 + (r<<4) + e];
    float gs = acc;
    gs += __shfl_xor_sync(0xffffffffu, gs, 1);
    gs += __shfl_xor_sync(0xffffffffu, gs, 2);
    gs += __shfl_xor_sync(0xffffffffu, gs, 4);
    gs += __shfl_xor_sync(0xffffffffu, gs, 8);
    g_rw[(slotBase + r)*B_*16 + b*16 + e] = acc / (gs + 1e-8f);
}

// ---------------- weighted pool mixes ----------------
__global__ void mix_sc_kernel(const float* __restrict__ cn, int slot, float* __restrict__ out)
{
    int idx = blockIdx.x*256 + threadIdx.x;
    if (idx >= B_*D_*R_) return;
    int b = idx / (D_*R_);
    int dr = idx - b*(D_*R_);
    float acc = 0.f;
    #pragma unroll
    for (int n = 0; n < 16; ++n)
        acc += g_rw[slot*B_*16 + b*16 + n] * cn[(size_t)n*(D_*R_) + dr];
    out[idx] = acc;
}

__global__ void mix_e_kernel(const float* __restrict__ pool)
{
    int idx = blockIdx.x*256 + threadIdx.x;
    if (idx >= B_*R_*D_) return;
    int which = blockIdx.y;               // 0=q 1=k 2=v -> rw slots 1..3
    int b = idx / (R_*D_);
    int rd = idx - b*(R_*D_);
    float acc = 0.f;
    #pragma unroll
    for (int n = 0; n < 16; ++n)
        acc += g_rw[(which+1)*B_*16 + b*16 + n] * pool[(size_t)n*(R_*D_) + rd];
    g_e[(size_t)which*(B_*R_*D_) + idx] = acc;
}

// ---------------- 128x64 3-stage cp.async TF32 tensor-core SGEMM ----------------
#define AS_STRIDE (128*36)
#define BS_STRIDE 2304
#define SMEM_GEMM_BYTES ((3*AS_STRIDE + 3*BS_STRIDE)*4)

template<bool TB>
__global__ void sgemm_kernel(const float* __restrict__ A, const float* __restrict__ Bm,
                             float* __restrict__ C, int M, int N, int K,
                             long long sA, long long sB, long long sC,
                             const float* __restrict__ addsrc)
{
    extern __shared__ float smem[];
    float* asBase = smem;
    float* bsBase = smem + 3*AS_STRIDE;
    A  += (long long)blockIdx.z * sA;
    Bm += (long long)blockIdx.z * sB;
    C  += (long long)blockIdx.z * sC;
    int m0 = blockIdx.y * 128, n0 = blockIdx.x * 64;
    int t = threadIdx.x;
    int warp = t >> 5, lane = t & 31;
    int wm = warp >> 1, wn = warp & 1;   // 4 x 2 warp grid
    int qr = lane >> 2, qc = lane & 3;   // mma fragment coords

    float acc[2][4][4];
    #pragma unroll
    for (int i = 0; i < 2; ++i)
        #pragma unroll
        for (int j = 0; j < 4; ++j)
            #pragma unroll
            for (int c = 0; c < 4; ++c) acc[i][j][c] = 0.f;

    auto stage_load = [&](int stage, int kt) {
        float* asS = asBase + stage * AS_STRIDE;
        float* bsS = bsBase + stage * BS_STRIDE;
        int k0 = kt * 32;
        #pragma unroll
        for (int i = 0; i < 4; ++i) {
            int c = t + i*256;
            int m = c >> 3, k4 = (c & 7) << 2;
            cpa16(asS + m*36 + k4, A + (long long)(m0 + m)*K + k0 + k4);
        }
        #pragma unroll
        for (int i = 0; i < 2; ++i) {
            int c = t + i*256;
            if (TB) {
                int n = c >> 3, k4 = (c & 7) << 2;
                cpa16(bsS + n*36 + k4, Bm + (long long)(n0 + n)*K + k0 + k4);
            } else {
                int kr = c >> 4, n4 = (c & 15) << 2;
                cpa16(bsS + kr*72 + n4, Bm + (long long)(k0 + kr)*N + n0 + n4);
            }
        }
    };

    int nk = K >> 5;
    stage_load(0, 0); CPA_COMMIT();
    stage_load(1, 1); CPA_COMMIT();

    for (int kt = 0; kt < nk; ++kt) {
        if (kt + 2 < nk) stage_load((kt + 2) % 3, kt + 2);
        CPA_COMMIT();
        CPA_WAIT2();
        __syncthreads();
        float* asS = asBase + (kt % 3) * AS_STRIDE;
        float* bsS = bsBase + (kt % 3) * BS_STRIDE;
        #pragma unroll
        for (int ks = 0; ks < 32; ks += 8) {
            uint32_t af[2][4], bf[4][2];
            #pragma unroll
            for (int mt = 0; mt < 2; ++mt) {
                int mb = wm*32 + mt*16;
                const float* ap = asS + (mb + qr)*36 + ks + qc;
                af[mt][0] = __float_as_uint(ap[0]);
                af[mt][1] = __float_as_uint(ap[8*36]);
                af[mt][2] = __float_as_uint(ap[4]);
                af[mt][3] = __float_as_uint(ap[8*36 + 4]);
            }
            #pragma unroll
            for (int nt = 0; nt < 4; ++nt) {
                int nb = wn*32 + nt*8;
                if (TB) {
                    const float* bp = bsS + (nb + qr)*36 + ks + qc;
                    bf[nt][0] = __float_as_uint(bp[0]);
                    bf[nt][1] = __float_as_uint(bp[4]);
                } else {
                    const float* bp = bsS + (ks + qc)*72 + nb + qr;
                    bf[nt][0] = __float_as_uint(bp[0]);
                    bf[nt][1] = __float_as_uint(bp[4*72]);
                }
            }
            #pragma unroll
            for (int mt = 0; mt < 2; ++mt)
                #pragma unroll
                for (int nt = 0; nt < 4; ++nt)
                    mma_tf32(acc[mt][nt], af[mt], bf[nt]);
        }
        __syncthreads();
    }

    #pragma unroll
    for (int mt = 0; mt < 2; ++mt) {
        long long row = m0 + wm*32 + mt*16 + qr;
        #pragma unroll
        for (int nt = 0; nt < 4; ++nt) {
            long long col = n0 + wn*32 + nt*8 + qc*2;
            long long off0 = row * N + col;
            long long off1 = (row + 8) * N + col;
            float2 r0 = make_float2(acc[mt][nt][0], acc[mt][nt][1]);
            float2 r1 = make_float2(acc[mt][nt][2], acc[mt][nt][3]);
            if (addsrc) {
                float2 a0 = *(const float2*)(addsrc + off0);
                float2 a1 = *(const float2*)(addsrc + off1);
                r0.x += a0.x; r0.y += a0.y; r1.x += a1.x; r1.y += a1.y;
            }
            *(float2*)(C + off0) = r0;
            *(float2*)(C + off1) = r1;
        }
    }
}

// ---------------- tf32-MMA flash attention (dynamic smem) ----------------
// grid (S/64, H, B), block 128 (4 warps, each owns 16 q-rows). Tile: 64 q x 64 k, dh=64.
// Q-frags register-resident; K staged transposed [d][key]; probs via per-warp-private Ps rows.
// dyn smem: Ks[64][72] | Vs[64][72] | Ps[64][72]  = 55296 B
#define ATT_TILE (64*72)
#define SMEM_ATT_BYTES (3*ATT_TILE*4)

__global__ __launch_bounds__(128) void attn_kernel(
    const float* __restrict__ Q, const float* __restrict__ Kg,
    const float* __restrict__ Vg, float* __restrict__ O)
{
    extern __shared__ float asmem[];
    float* Ks = asmem;                 // [d][key] stride 72
    float* Vs = asmem + ATT_TILE;      // [key][d] stride 72
    float* Ps = asmem + 2*ATT_TILE;    // Q staging then [q][key] probs, stride 72
    int b = blockIdx.z, h = blockIdx.y;
    int qb = gridDim.x - 1 - blockIdx.x;         // long blocks launch first
    int q0 = qb * 64;
    int t = threadIdx.x, w = t >> 5, lane = t & 31;
    int qr = lane >> 2, qc = lane & 3;
    long long base = ((long long)(b*S_))*D_ + (long long)h*DH_;

    // stage Q [q][d] into Ps (one-time)
    for (int i = t; i < 64*16; i += 128) {
        int qi = i >> 4, d4 = (i & 15) << 2;
        float4 v = *(const float4*)(Q + base + (long long)(q0+qi)*D_ + d4);
        *(float4*)&Ps[qi*72 + d4] = v;
    }
    __syncthreads();
    // register-resident Q fragments (8 k-steps x 4 regs)
    uint32_t qf[8][4];
    #pragma unroll
    for (int ks = 0; ks < 8; ++ks) {
        qf[ks][0] = __float_as_uint(Ps[(w*16 + qr    )*72 + ks*8 + qc    ]);
        qf[ks][1] = __float_as_uint(Ps[(w*16 + qr + 8)*72 + ks*8 + qc    ]);
        qf[ks][2] = __float_as_uint(Ps[(w*16 + qr    )*72 + ks*8 + qc + 4]);
        qf[ks][3] = __float_as_uint(Ps[(w*16 + qr + 8)*72 + ks*8 + qc + 4]);
    }
    __syncthreads();

    float m[2] = {-1e30f, -1e30f}, l[2] = {0.f, 0.f};
    float o[8][4];
    #pragma unroll
    for (int nt = 0; nt < 8; ++nt)
        #pragma unroll
        for (int j = 0; j < 4; ++j) o[nt][j] = 0.f;

    for (int kt = 0; kt <= qb; ++kt) {
        int k0 = kt * 64;
        __syncthreads();   // prior tile's reads of Ks/Vs complete
        // stage K transposed (key-contiguous stores: conflict-free)
        for (int i = t; i < 1024; i += 128) {
            int kk = i & 63, d4 = (i >> 6) << 2;
            float4 kv = *(const float4*)(Kg + base + (long long)(k0+kk)*D_ + d4);
            Ks[(d4+0)*72 + kk] = kv.x; Ks[(d4+1)*72 + kk] = kv.y;
            Ks[(d4+2)*72 + kk] = kv.z; Ks[(d4+3)*72 + kk] = kv.w;
        }
        // stage V row-major
        for (int i = t; i < 1024; i += 128) {
            int kk = i >> 4, d4 = (i & 15) << 2;
            *(float4*)&Vs[kk*72 + d4] =
                *(const float4*)(Vg + base + (long long)(k0+kk)*D_ + d4);
        }
        __syncthreads();

        // score: s[nt] = Q(16 rows) x K^T(8 keys per nt)
        float s[8][4];
        #pragma unroll
        for (int nt = 0; nt < 8; ++nt)
            #pragma unroll
            for (int j = 0; j < 4; ++j) s[nt][j] = 0.f;
        #pragma unroll
        for (int ks = 0; ks < 8; ++ks) {
            #pragma unroll
            for (int nt = 0; nt < 8; ++nt) {
                uint32_t bf[2];
                bf[0] = __float_as_uint(Ks[(ks*8 + qc    )*72 + nt*8 + qr]);
                bf[1] = __float_as_uint(Ks[(ks*8 + qc + 4)*72 + nt*8 + qr]);
                mma_tf32(s[nt], qf[ks], bf);
            }
        }
        // scale + causal mask (diag tile only needs the compare)
        if (kt == qb) {
            #pragma unroll
            for (int nt = 0; nt < 8; ++nt)
                #pragma unroll
                for (int j = 0; j < 4; ++j) {
                    int key = k0 + nt*8 + qc*2 + (j & 1);
                    int qg  = q0 + w*16 + qr + (j >> 1)*8;
                    float v = s[nt][j] * 0.125f;
                    s[nt][j] = (key > qg) ? -1e30f : v;
                }
        } else {
            #pragma unroll
            for (int nt = 0; nt < 8; ++nt)
                #pragma unroll
                for (int j = 0; j < 4; ++j) s[nt][j] *= 0.125f;
        }
        // online softmax per row (r=0: row qr; r=1: row qr+8); lanes share row across qc (xor 1,2)
        #pragma unroll
        for (int r = 0; r < 2; ++r) {
            float rm = -1e30f;
            #pragma unroll
            for (int nt = 0; nt < 8; ++nt)
                rm = fmaxf(rm, fmaxf(s[nt][r*2], s[nt][r*2+1]));
            rm = fmaxf(rm, __shfl_xor_sync(0xffffffffu, rm, 1));
            rm = fmaxf(rm, __shfl_xor_sync(0xffffffffu, rm, 2));
            float mn = fmaxf(m[r], rm);
            float c = __expf(m[r] - mn);
            float rs = 0.f;
            #pragma unroll
            for (int nt = 0; nt < 8; ++nt) {
                float p0 = __expf(s[nt][r*2]   - mn);
                float p1 = __expf(s[nt][r*2+1] - mn);
                s[nt][r*2] = p0; s[nt][r*2+1] = p1;
                rs += p0 + p1;
            }
            rs += __shfl_xor_sync(0xffffffffu, rs, 1);
            rs += __shfl_xor_sync(0xffffffffu, rs, 2);
            l[r] = l[r]*c + rs;
            m[r] = mn;
            #pragma unroll
            for (int nt = 0; nt < 8; ++nt) { o[nt][r*2] *= c; o[nt][r*2+1] *= c; }
        }
        // probs -> Ps (warp-private rows, no sync needed)
        #pragma unroll
        for (int nt = 0; nt < 8; ++nt) {
            *(float2*)&Ps[(w*16 + qr    )*72 + nt*8 + qc*2] = make_float2(s[nt][0], s[nt][1]);
            *(float2*)&Ps[(w*16 + qr + 8)*72 + nt*8 + qc*2] = make_float2(s[nt][2], s[nt][3]);
        }
        // PV: o[nt(d)] += P(16 q x 64 key) x V(key x 8 d per nt)
        #pragma unroll
        for (int ks = 0; ks < 8; ++ks) {
            uint32_t pf[4];
            pf[0] = __float_as_uint(Ps[(w*16 + qr    )*72 + ks*8 + qc    ]);
            pf[1] = __float_as_uint(Ps[(w*16 + qr + 8)*72 + ks*8 + qc    ]);
            pf[2] = __float_as_uint(Ps[(w*16 + qr    )*72 + ks*8 + qc + 4]);
            pf[3] = __float_as_uint(Ps[(w*16 + qr + 8)*72 + ks*8 + qc + 4]);
            #pragma unroll
            for (int nt = 0; nt < 8; ++nt) {
                uint32_t vf[2];
                vf[0] = __float_as_uint(Vs[(ks*8 + qc    )*72 + nt*8 + qr]);
                vf[1] = __float_as_uint(Vs[(ks*8 + qc + 4)*72 + nt*8 + qr]);
                mma_tf32(o[nt], pf, vf);
            }
        }
    }
    // epilogue
    float inv0 = 1.f / l[0], inv1 = 1.f / l[1];
    long long row0 = q0 + w*16 + qr;
    #pragma unroll
    for (int nt = 0; nt < 8; ++nt) {
        long long col = nt*8 + qc*2;
        *(float2*)(O + base + row0*D_ + col) =
            make_float2(o[nt][0]*inv0, o[nt][1]*inv0);
        *(float2*)(O + base + (row0+8)*D_ + col) =
            make_float2(o[nt][2]*inv1, o[nt][3]*inv1);
    }
}

// ---------------- fused knowledge memory: scores + top-8 + softmax + gather ----------------
__global__ void knowledge_kernel(const float* __restrict__ Qm,
                                 const float* __restrict__ kK,
                                 const float* __restrict__ kV,
                                 float* __restrict__ out)
{
    __shared__ float kKs[KR_ * 32];      // d-major: kKs[d*32 + key]
    __shared__ float qs[16 * KR_];       // qs[r*256 + d]
    int t = threadIdx.x, w = t >> 5, lane = t & 31;
    int rowBase = blockIdx.x * 16;
    int r0 = w * 2, r1 = w * 2 + 1;

    for (int i = t; i < 16 * KR_ / 4; i += 256)
        ((float4*)qs)[i] = ((const float4*)(Qm + (size_t)rowBase * KR_))[i];

    float v0[TOPK_], v1[TOPK_]; int i0[TOPK_], i1[TOPK_];
    #pragma unroll
    for (int j = 0; j < TOPK_; ++j) {
        v0[j] = -3.0e38f; v1[j] = -3.0e38f; i0[j] = 0x7fffffff; i1[j] = 0x7fffffff;
    }

    for (int t0 = 0; t0 < NK_; t0 += 32) {
        __syncthreads();
        {
            int kk = t >> 3;
            int d0 = (t & 7) * 32;
            const float* src = kK + (size_t)(t0 + kk) * KR_ + d0;
            #pragma unroll
            for (int j = 0; j < 32; j += 4) {
                float4 vv = *(const float4*)(src + j);
                kKs[(d0 + j + 0) * 32 + kk] = vv.x;
                kKs[(d0 + j + 1) * 32 + kk] = vv.y;
                kKs[(d0 + j + 2) * 32 + kk] = vv.z;
                kKs[(d0 + j + 3) * 32 + kk] = vv.w;
            }
        }
        __syncthreads();
        float a0 = 0.f, a1 = 0.f;
        #pragma unroll 8
        for (int d = 0; d < KR_; d += 4) {
            float4 qa = *(const float4*)(qs + r0 * KR_ + d);
            float4 qb = *(const float4*)(qs + r1 * KR_ + d);
            float k0v = kKs[(d + 0) * 32 + lane];
            float k1v = kKs[(d + 1) * 32 + lane];
            float k2v = kKs[(d + 2) * 32 + lane];
            float k3v = kKs[(d + 3) * 32 + lane];
            a0 += qa.x * k0v; a0 += qa.y * k1v; a0 += qa.z * k2v; a0 += qa.w * k3v;
            a1 += qb.x * k0v; a1 += qb.y * k1v; a1 += qb.z * k2v; a1 += qb.w * k3v;
        }
        int keyIdx = t0 + lane;
        if (a0 > v0[TOPK_-1]) {
            v0[TOPK_-1] = a0; i0[TOPK_-1] = keyIdx;
            #pragma unroll
            for (int j = TOPK_-1; j > 0; --j)
                if (v0[j] > v0[j-1]) {
                    float tv = v0[j]; v0[j] = v0[j-1]; v0[j-1] = tv;
                    int ti = i0[j]; i0[j] = i0[j-1]; i0[j-1] = ti;
                }
        }
        if (a1 > v1[TOPK_-1]) {
            v1[TOPK_-1] = a1; i1[TOPK_-1] = keyIdx;
            #pragma unroll
            for (int j = TOPK_-1; j > 0; --j)
                if (v1[j] > v1[j-1]) {
                    float tv = v1[j]; v1[j] = v1[j-1]; v1[j-1] = tv;
                    int ti = i1[j]; i1[j] = i1[j-1]; i1[j-1] = ti;
                }
        }
    }

    #pragma unroll
    for (int rr = 0; rr < 2; ++rr) {
        float* lv = rr ? v1 : v0;
        int*   li = rr ? i1 : i0;
        int gr = rowBase + (rr ? r1 : r0);
        float tv[TOPK_]; int ti[TOPK_];
        int p = 0;
        #pragma unroll
        for (int it = 0; it < TOPK_; ++it) {
            float bv = lv[p];
            int   bi = li[p];
            float mv = bv; int mi = bi;
            #pragma unroll
            for (int off = 16; off > 0; off >>= 1) {
                float ov = __shfl_xor_sync(0xffffffffu, mv, off);
                int   oi = __shfl_xor_sync(0xffffffffu, mi, off);
                if (ov > mv || (ov == mv && oi < mi)) { mv = ov; mi = oi; }
            }
            tv[it] = mv; ti[it] = mi;
            if (bi == mi) ++p;
        }
        float mx = tv[0] * 0.0625f;
        float w8[TOPK_]; float ssum = 0.f;
        #pragma unroll
        for (int k2 = 0; k2 < TOPK_; ++k2) { w8[k2] = __expf(tv[k2] * 0.0625f - mx); ssum += w8[k2]; }
        float inv = 1.f / ssum;
        for (int j = 0; j < D_ / 32; ++j) {
            int d = j * 32 + lane;
            float acc = 0.f;
            #pragma unroll
            for (int k2 = 0; k2 < TOPK_; ++k2)
                acc += w8[k2] * kV[(size_t)ti[k2] * D_ + d];
            out[(size_t)gr * D_ + d] += acc * inv;
        }
    }
}

// ---------------- host orchestration ----------------
extern "C" void kernel_launch(void* const* d_in, const int* in_sizes, int n_in,
                              void* d_out, int out_size)
{
    (void)in_sizes; (void)n_in; (void)out_size;
    const float* x   = (const float*)d_in[0];
    const float* imp = (const float*)d_in[1];
    const float* Wc  = (const float*)d_in[2];
    const float* WQ  = (const float*)d_in[3];
    const float* WK  = (const float*)d_in[4];
    const float* WV  = (const float*)d_in[5];
    const float* Wm  = (const float*)d_in[6];
    const float* cn  = (const float*)d_in[7];
    const float* pool= (const float*)d_in[8];
    const float* kK  = (const float*)d_in[9];
    const float* kV  = (const float*)d_in[10];
    const float* WO  = (const float*)d_in[11];
    const float* g1  = (const float*)d_in[12];
    const float* b1  = (const float*)d_in[13];
    const float* g2  = (const float*)d_in[14];
    const float* b2  = (const float*)d_in[15];
    float* out = (float*)d_out;

    float *nx, *sc, *h, *e, *q, *k, *v, *ao;
    cudaGetSymbolAddress((void**)&nx, g_nx);
    cudaGetSymbolAddress((void**)&sc, g_sc);
    cudaGetSymbolAddress((void**)&h,  g_h);
    cudaGetSymbolAddress((void**)&e,  g_e);
    cudaGetSymbolAddress((void**)&q,  g_q);
    cudaGetSymbolAddress((void**)&k,  g_k);
    cudaGetSymbolAddress((void**)&v,  g_v);
    cudaGetSymbolAddress((void**)&ao, g_ao);

    cudaFuncSetAttribute(sgemm_kernel<false>,
        cudaFuncAttributeMaxDynamicSharedMemorySize, SMEM_GEMM_BYTES);
    cudaFuncSetAttribute(sgemm_kernel<true>,
        cudaFuncAttributeMaxDynamicSharedMemorySize, SMEM_GEMM_BYTES);
    cudaFuncSetAttribute(attn_kernel,
        cudaFuncAttributeMaxDynamicSharedMemorySize, SMEM_ATT_BYTES);

    const long long BRD = (long long)B_*R_*D_;

    // ---- attention sub-block ----
    ln_kernel<<<B_*S_, 256>>>(x, g1, b1, nx);
    route_kernel<<<dim3(NBLK_, B_), 256>>>(nx, imp, Wc, WQ, WK, WV, 64);
    reduce_norm_kernel<<<4, 32>>>(0);
    mix_sc_kernel<<<(B_*D_*R_ + 255)/256, 256>>>(cn, 0, sc);
    // h[b] = nx[b] @ sc[b]   (S x D) @ (D x R)
    sgemm_kernel<false><<<dim3(R_/64, S_/128, B_), 256, SMEM_GEMM_BYTES>>>(
        nx, sc, h, S_, R_, D_, (long long)S_*D_, (long long)D_*R_, (long long)S_*R_, nullptr);
    mix_e_kernel<<<dim3((B_*R_*D_ + 255)/256, 3), 256>>>(pool);
    // Q/K/V[b] = h[b] @ e_x[b]   (S x R) @ (R x D)
    sgemm_kernel<false><<<dim3(D_/64, S_/128, B_), 256, SMEM_GEMM_BYTES>>>(
        h, e + 0*BRD, q, S_, D_, R_, (long long)S_*R_, (long long)R_*D_, (long long)S_*D_, nullptr);
    sgemm_kernel<false><<<dim3(D_/64, S_/128, B_), 256, SMEM_GEMM_BYTES>>>(
        h, e + 1*BRD, k, S_, D_, R_, (long long)S_*R_, (long long)R_*D_, (long long)S_*D_, nullptr);
    sgemm_kernel<false><<<dim3(D_/64, S_/128, B_), 256, SMEM_GEMM_BYTES>>>(
        h, e + 2*BRD, v, S_, D_, R_, (long long)S_*R_, (long long)R_*D_, (long long)S_*D_, nullptr);
    attn_kernel<<<dim3(S_/64, H_, B_), 128, SMEM_ATT_BYTES>>>(q, k, v, ao);
    // out = x + ao @ WO^T    ([B*S, D] @ [D, D]^T), NT
    sgemm_kernel<true><<<dim3(D_/64, (B_*S_)/128, 1), 256, SMEM_GEMM_BYTES>>>(
        ao, WO, out, B_*S_, D_, D_, 0, 0, 0, x);

    // ---- memory sub-block ----
    ln_kernel<<<B_*S_, 256>>>(out, g2, b2, nx);
    route_kernel<<<dim3(NBLK_, B_), 256>>>(nx, imp, Wm, Wm, Wm, Wm, 16);
    reduce_norm_kernel<<<1, 32>>>(4);
    mix_sc_kernel<<<(B_*D_*R_ + 255)/256, 256>>>(cn, 4, sc);
    // Qm[b] = nx2[b] @ mc[b]
    sgemm_kernel<false><<<dim3(R_/64, S_/128, B_), 256, SMEM_GEMM_BYTES>>>(
        nx, sc, h, S_, R_, D_, (long long)S_*D_, (long long)D_*R_, (long long)S_*R_, nullptr);
    // fused: ms = Qm @ kK^T -> top-8 -> softmax -> gather(kV) -> out +=
    knowledge_kernel<<<(B_*S_)/16, 256>>>(h, kK, kV, out);
}

// round 9
// speedup vs baseline: 4.0601x; 1.5214x over previous
#include <cuda_runtime.h>
#include <math.h>
#include <stdint.h>

// ---------------- problem constants ----------------
#define B_    2
#define S_    2048
#define D_    1024
#define H_    16
#define DH_   64
#define R_    256
#define NK_   4096
#define KR_   256
#define TOPK_ 8
#define NBLK_ (S_/8)   // route blocks per batch (8 rows per block)

// ---------------- device scratch (allocation-free) ----------------
__device__ float g_nx [B_*S_*D_];        // LN output (reused for LN2)
__device__ float g_part[B_*NBLK_*64];    // routing partial sums
__device__ float g_rw [5*B_*16];         // normalized router weights: slots c,q,k,v,m
__device__ float g_sc [B_*D_*R_];        // compress matrix (reused for mc)
__device__ float g_h  [B_*S_*R_];        // h (reused for Qm)
__device__ float g_e  [3*(B_*R_*D_)];    // expand matrices q,k,v
__device__ float g_qkv[3*(B_*S_*D_)];    // q | k | v
__device__ float g_ao [B_*S_*D_];

// ---------------- mma / cp.async helpers ----------------
__device__ __forceinline__ void mma_tf32(float* d, const uint32_t* a, const uint32_t* b) {
    asm volatile(
        "mma.sync.aligned.m16n8k8.row.col.f32.tf32.tf32.f32 "
        "{%0,%1,%2,%3},{%4,%5,%6,%7},{%8,%9},{%0,%1,%2,%3};"
        : "+f"(d[0]), "+f"(d[1]), "+f"(d[2]), "+f"(d[3])
        : "r"(a[0]), "r"(a[1]), "r"(a[2]), "r"(a[3]), "r"(b[0]), "r"(b[1]));
}

__device__ __forceinline__ void cpa16(float* smem, const float* g) {
    uint32_t s = (uint32_t)__cvta_generic_to_shared(smem);
    asm volatile("cp.async.cg.shared.global [%0], [%1], 16;\n" :: "r"(s), "l"(g));
}
#define CPA_COMMIT() asm volatile("cp.async.commit_group;\n" ::: "memory")
#define CPA_WAIT2()  asm volatile("cp.async.wait_group 2;\n" ::: "memory")

// ---------------- LayerNorm: one block per row ----------------
__global__ void ln_kernel(const float* __restrict__ x,
                          const float* __restrict__ g,
                          const float* __restrict__ b,
                          float* __restrict__ out)
{
    int row = blockIdx.x;
    int t = threadIdx.x;                  // 256
    const float4* xr = (const float4*)(x + (size_t)row * D_);
    float4 v = xr[t];
    float s1 = v.x + v.y + v.z + v.w;
    float s2 = v.x*v.x + v.y*v.y + v.z*v.z + v.w*v.w;
    #pragma unroll
    for (int off = 16; off > 0; off >>= 1) {
        s1 += __shfl_xor_sync(0xffffffffu, s1, off);
        s2 += __shfl_xor_sync(0xffffffffu, s2, off);
    }
    __shared__ float sa[8], sb[8];
    __shared__ float s_mu, s_rs;
    int warp = t >> 5, lane = t & 31;
    if (lane == 0) { sa[warp] = s1; sb[warp] = s2; }
    __syncthreads();
    if (t == 0) {
        float ta = 0.f, tb = 0.f;
        #pragma unroll
        for (int w = 0; w < 8; ++w) { ta += sa[w]; tb += sb[w]; }
        float mu = ta * (1.0f / D_);
        float var = tb * (1.0f / D_) - mu * mu;
        s_mu = mu;
        s_rs = rsqrtf(var + 1e-5f);
    }
    __syncthreads();
    float mu = s_mu, rs = s_rs;
    float4 gg = ((const float4*)g)[t];
    float4 bb = ((const float4*)b)[t];
    float4 o;
    o.x = (v.x - mu) * rs * gg.x + bb.x;
    o.y = (v.y - mu) * rs * gg.y + bb.y;
    o.z = (v.z - mu) * rs * gg.z + bb.z;
    o.w = (v.w - mu) * rs * gg.w + bb.w;
    ((float4*)(out + (size_t)row * D_))[t] = o;
}

// ---------------- routing: logits + softmax + importance pool (deterministic) ----------------
__global__ void route_kernel(const float* __restrict__ nx, const float* __restrict__ imp,
                             const float* __restrict__ W0, const float* __restrict__ W1,
                             const float* __restrict__ W2, const float* __restrict__ W3,
                             int nPairs)
{
    __shared__ float xs[8][128];
    __shared__ float ws[64][129];
    __shared__ float lg[8][64];
    int t = threadIdx.x;
    int b = blockIdx.y;
    int r0 = blockIdx.x * 8;
    float acc[8] = {0.f,0.f,0.f,0.f,0.f,0.f,0.f,0.f};
    for (int c = 0; c < 8; ++c) {
        int d0 = c * 128;
        for (int idx = t; idx < 8*128; idx += 256) {
            int r = idx >> 7, dd = idx & 127;
            xs[r][dd] = nx[((size_t)(b*S_ + r0 + r))*D_ + d0 + dd];
        }
        for (int idx = t; idx < nPairs*128; idx += 256) {
            int p = idx >> 7, dd = idx & 127;
            const float* Wp = (p < 16) ? W0 : (p < 32) ? W1 : (p < 48) ? W2 : W3;
            ws[p][dd] = Wp[(size_t)(p & 15)*D_ + d0 + dd];
        }
        __syncthreads();
        if (t < nPairs) {
            for (int dd = 0; dd < 128; ++dd) {
                float wv = ws[t][dd];
                #pragma unroll
                for (int r = 0; r < 8; ++r) acc[r] += wv * xs[r][dd];
            }
        }
        __syncthreads();
    }
    if (t < nPairs) {
        #pragma unroll
        for (int r = 0; r < 8; ++r) lg[r][t] = acc[r];
    }
    __syncthreads();
    if (t < nPairs) {
        int router = t >> 4;
        float contrib = 0.f;
        for (int r = 0; r < 8; ++r) {
            float mx = -1e30f;
            for (int e = 0; e < 16; ++e) mx = fmaxf(mx, lg[r][(router<<4) + e]);
            float ssum = 0.f;
            for (int e = 0; e < 16; ++e) ssum += __expf(lg[r][(router<<4) + e] - mx);
            float p = __expf(lg[r][t] - mx) / ssum;
            contrib += imp[b*S_ + r0 + r] * p;
        }
        g_part[((size_t)(b*NBLK_) + blockIdx.x)*64 + t] = contrib;
    }
}

// grid nRouters, block 32. Deterministic reduction of partials + normalization.
__global__ void reduce_norm_kernel(int slotBase)
{
    int r = blockIdx.x;
    int lane = threadIdx.x;
    int b = lane >> 4, e = lane & 15;
    float acc = 0.f;
    for (int blk = 0; blk < NBLK_; ++blk)
        acc += g_part[((size_t)(b*NBLK_) + blk)*64 + (r<<4) + e];
    float gs = acc;
    gs += __shfl_xor_sync(0xffffffffu, gs, 1);
    gs += __shfl_xor_sync(0xffffffffu, gs, 2);
    gs += __shfl_xor_sync(0xffffffffu, gs, 4);
    gs += __shfl_xor_sync(0xffffffffu, gs, 8);
    g_rw[(slotBase + r)*B_*16 + b*16 + e] = acc / (gs + 1e-8f);
}

// ---------------- weighted pool mixes (merged sc + e) ----------------
// grid (4096, 4): y==0 -> sc (slot given), y in 1..3 -> e[y-1] (slots slotE+y-1)
__global__ void mix_all_kernel(const float* __restrict__ cn, const float* __restrict__ pool,
                               int slotSc, float* __restrict__ sc, int doE)
{
    int idx = blockIdx.x*256 + threadIdx.x;
    if (idx >= B_*D_*R_) return;
    int y = blockIdx.y;
    if (y == 0) {
        int b = idx / (D_*R_);
        int dr = idx - b*(D_*R_);
        float acc = 0.f;
        #pragma unroll
        for (int n = 0; n < 16; ++n)
            acc += g_rw[slotSc*B_*16 + b*16 + n] * cn[(size_t)n*(D_*R_) + dr];
        sc[idx] = acc;
    } else if (doE) {
        int which = y - 1;
        int b = idx / (R_*D_);
        int rd = idx - b*(R_*D_);
        float acc = 0.f;
        #pragma unroll
        for (int n = 0; n < 16; ++n)
            acc += g_rw[(which+1)*B_*16 + b*16 + n] * pool[(size_t)n*(R_*D_) + rd];
        g_e[(size_t)which*(B_*R_*D_) + idx] = acc;
    }
}

// ---------------- 128x64 3-stage cp.async TF32 tensor-core SGEMM ----------------
// zmode 0: batch strides sA/sB/sC.  zmode 1: QKV mode — z = which*2 + b over (h, e, qkv).
#define AS_STRIDE (128*36)
#define BS_STRIDE 2304
#define SMEM_GEMM_BYTES ((3*AS_STRIDE + 3*BS_STRIDE)*4)

template<bool TB>
__global__ void sgemm_kernel(const float* __restrict__ A, const float* __restrict__ Bm,
                             float* __restrict__ C, int M, int N, int K,
                             long long sA, long long sB, long long sC,
                             const float* __restrict__ addsrc, int zmode)
{
    extern __shared__ float smem[];
    float* asBase = smem;
    float* bsBase = smem + 3*AS_STRIDE;
    if (zmode == 1) {
        int which = blockIdx.z >> 1, b = blockIdx.z & 1;
        A  += (long long)b * S_ * R_;
        Bm += (long long)which * (B_*R_*D_) + (long long)b * R_ * D_;
        C  += (long long)which * (B_*S_*D_) + (long long)b * S_ * D_;
    } else {
        A  += (long long)blockIdx.z * sA;
        Bm += (long long)blockIdx.z * sB;
        C  += (long long)blockIdx.z * sC;
    }
    int m0 = blockIdx.y * 128, n0 = blockIdx.x * 64;
    int t = threadIdx.x;
    int warp = t >> 5, lane = t & 31;
    int wm = warp >> 1, wn = warp & 1;
    int qr = lane >> 2, qc = lane & 3;

    float acc[2][4][4];
    #pragma unroll
    for (int i = 0; i < 2; ++i)
        #pragma unroll
        for (int j = 0; j < 4; ++j)
            #pragma unroll
            for (int c = 0; c < 4; ++c) acc[i][j][c] = 0.f;

    auto stage_load = [&](int stage, int kt) {
        float* asS = asBase + stage * AS_STRIDE;
        float* bsS = bsBase + stage * BS_STRIDE;
        int k0 = kt * 32;
        #pragma unroll
        for (int i = 0; i < 4; ++i) {
            int c = t + i*256;
            int m = c >> 3, k4 = (c & 7) << 2;
            cpa16(asS + m*36 + k4, A + (long long)(m0 + m)*K + k0 + k4);
        }
        #pragma unroll
        for (int i = 0; i < 2; ++i) {
            int c = t + i*256;
            if (TB) {
                int n = c >> 3, k4 = (c & 7) << 2;
                cpa16(bsS + n*36 + k4, Bm + (long long)(n0 + n)*K + k0 + k4);
            } else {
                int kr = c >> 4, n4 = (c & 15) << 2;
                cpa16(bsS + kr*72 + n4, Bm + (long long)(k0 + kr)*N + n0 + n4);
            }
        }
    };

    int nk = K >> 5;
    stage_load(0, 0); CPA_COMMIT();
    stage_load(1, 1); CPA_COMMIT();

    for (int kt = 0; kt < nk; ++kt) {
        if (kt + 2 < nk) stage_load((kt + 2) % 3, kt + 2);
        CPA_COMMIT();
        CPA_WAIT2();
        __syncthreads();
        float* asS = asBase + (kt % 3) * AS_STRIDE;
        float* bsS = bsBase + (kt % 3) * BS_STRIDE;
        #pragma unroll
        for (int ks = 0; ks < 32; ks += 8) {
            uint32_t af[2][4], bf[4][2];
            #pragma unroll
            for (int mt = 0; mt < 2; ++mt) {
                int mb = wm*32 + mt*16;
                const float* ap = asS + (mb + qr)*36 + ks + qc;
                af[mt][0] = __float_as_uint(ap[0]);
                af[mt][1] = __float_as_uint(ap[8*36]);
                af[mt][2] = __float_as_uint(ap[4]);
                af[mt][3] = __float_as_uint(ap[8*36 + 4]);
            }
            #pragma unroll
            for (int nt = 0; nt < 4; ++nt) {
                int nb = wn*32 + nt*8;
                if (TB) {
                    const float* bp = bsS + (nb + qr)*36 + ks + qc;
                    bf[nt][0] = __float_as_uint(bp[0]);
                    bf[nt][1] = __float_as_uint(bp[4]);
                } else {
                    const float* bp = bsS + (ks + qc)*72 + nb + qr;
                    bf[nt][0] = __float_as_uint(bp[0]);
                    bf[nt][1] = __float_as_uint(bp[4*72]);
                }
            }
            #pragma unroll
            for (int mt = 0; mt < 2; ++mt)
                #pragma unroll
                for (int nt = 0; nt < 4; ++nt)
                    mma_tf32(acc[mt][nt], af[mt], bf[nt]);
        }
        __syncthreads();
    }

    #pragma unroll
    for (int mt = 0; mt < 2; ++mt) {
        long long row = m0 + wm*32 + mt*16 + qr;
        #pragma unroll
        for (int nt = 0; nt < 4; ++nt) {
            long long col = n0 + wn*32 + nt*8 + qc*2;
            long long off0 = row * N + col;
            long long off1 = (row + 8) * N + col;
            float2 r0 = make_float2(acc[mt][nt][0], acc[mt][nt][1]);
            float2 r1 = make_float2(acc[mt][nt][2], acc[mt][nt][3]);
            if (addsrc) {
                float2 a0 = *(const float2*)(addsrc + off0);
                float2 a1 = *(const float2*)(addsrc + off1);
                r0.x += a0.x; r0.y += a0.y; r1.x += a1.x; r1.y += a1.y;
            }
            *(float2*)(C + off0) = r0;
            *(float2*)(C + off1) = r1;
        }
    }
}

// ---------------- tf32-MMA flash attention (dynamic smem) ----------------
#define ATT_TILE (64*72)
#define SMEM_ATT_BYTES (3*ATT_TILE*4)

__global__ __launch_bounds__(128) void attn_kernel(
    const float* __restrict__ Q, const float* __restrict__ Kg,
    const float* __restrict__ Vg, float* __restrict__ O)
{
    extern __shared__ float asmem[];
    float* Ks = asmem;
    float* Vs = asmem + ATT_TILE;
    float* Ps = asmem + 2*ATT_TILE;
    int b = blockIdx.z, h = blockIdx.y;
    int qb = gridDim.x - 1 - blockIdx.x;
    int q0 = qb * 64;
    int t = threadIdx.x, w = t >> 5, lane = t & 31;
    int qr = lane >> 2, qc = lane & 3;
    long long base = ((long long)(b*S_))*D_ + (long long)h*DH_;

    for (int i = t; i < 64*16; i += 128) {
        int qi = i >> 4, d4 = (i & 15) << 2;
        float4 v = *(const float4*)(Q + base + (long long)(q0+qi)*D_ + d4);
        *(float4*)&Ps[qi*72 + d4] = v;
    }
    __syncthreads();
    uint32_t qf[8][4];
    #pragma unroll
    for (int ks = 0; ks < 8; ++ks) {
        qf[ks][0] = __float_as_uint(Ps[(w*16 + qr    )*72 + ks*8 + qc    ]);
        qf[ks][1] = __float_as_uint(Ps[(w*16 + qr + 8)*72 + ks*8 + qc    ]);
        qf[ks][2] = __float_as_uint(Ps[(w*16 + qr    )*72 + ks*8 + qc + 4]);
        qf[ks][3] = __float_as_uint(Ps[(w*16 + qr + 8)*72 + ks*8 + qc + 4]);
    }
    __syncthreads();

    float m[2] = {-1e30f, -1e30f}, l[2] = {0.f, 0.f};
    float o[8][4];
    #pragma unroll
    for (int nt = 0; nt < 8; ++nt)
        #pragma unroll
        for (int j = 0; j < 4; ++j) o[nt][j] = 0.f;

    for (int kt = 0; kt <= qb; ++kt) {
        int k0 = kt * 64;
        __syncthreads();
        for (int i = t; i < 1024; i += 128) {
            int kk = i & 63, d4 = (i >> 6) << 2;
            float4 kv = *(const float4*)(Kg + base + (long long)(k0+kk)*D_ + d4);
            Ks[(d4+0)*72 + kk] = kv.x; Ks[(d4+1)*72 + kk] = kv.y;
            Ks[(d4+2)*72 + kk] = kv.z; Ks[(d4+3)*72 + kk] = kv.w;
        }
        for (int i = t; i < 1024; i += 128) {
            int kk = i >> 4, d4 = (i & 15) << 2;
            *(float4*)&Vs[kk*72 + d4] =
                *(const float4*)(Vg + base + (long long)(k0+kk)*D_ + d4);
        }
        __syncthreads();

        float s[8][4];
        #pragma unroll
        for (int nt = 0; nt < 8; ++nt)
            #pragma unroll
            for (int j = 0; j < 4; ++j) s[nt][j] = 0.f;
        #pragma unroll
        for (int ks = 0; ks < 8; ++ks) {
            #pragma unroll
            for (int nt = 0; nt < 8; ++nt) {
                uint32_t bf[2];
                bf[0] = __float_as_uint(Ks[(ks*8 + qc    )*72 + nt*8 + qr]);
                bf[1] = __float_as_uint(Ks[(ks*8 + qc + 4)*72 + nt*8 + qr]);
                mma_tf32(s[nt], qf[ks], bf);
            }
        }
        if (kt == qb) {
            #pragma unroll
            for (int nt = 0; nt < 8; ++nt)
                #pragma unroll
                for (int j = 0; j < 4; ++j) {
                    int key = k0 + nt*8 + qc*2 + (j & 1);
                    int qg  = q0 + w*16 + qr + (j >> 1)*8;
                    float v = s[nt][j] * 0.125f;
                    s[nt][j] = (key > qg) ? -1e30f : v;
                }
        } else {
            #pragma unroll
            for (int nt = 0; nt < 8; ++nt)
                #pragma unroll
                for (int j = 0; j < 4; ++j) s[nt][j] *= 0.125f;
        }
        #pragma unroll
        for (int r = 0; r < 2; ++r) {
            float rm = -1e30f;
            #pragma unroll
            for (int nt = 0; nt < 8; ++nt)
                rm = fmaxf(rm, fmaxf(s[nt][r*2], s[nt][r*2+1]));
            rm = fmaxf(rm, __shfl_xor_sync(0xffffffffu, rm, 1));
            rm = fmaxf(rm, __shfl_xor_sync(0xffffffffu, rm, 2));
            float mn = fmaxf(m[r], rm);
            float c = __expf(m[r] - mn);
            float rs = 0.f;
            #pragma unroll
            for (int nt = 0; nt < 8; ++nt) {
                float p0 = __expf(s[nt][r*2]   - mn);
                float p1 = __expf(s[nt][r*2+1] - mn);
                s[nt][r*2] = p0; s[nt][r*2+1] = p1;
                rs += p0 + p1;
            }
            rs += __shfl_xor_sync(0xffffffffu, rs, 1);
            rs += __shfl_xor_sync(0xffffffffu, rs, 2);
            l[r] = l[r]*c + rs;
            m[r] = mn;
            #pragma unroll
            for (int nt = 0; nt < 8; ++nt) { o[nt][r*2] *= c; o[nt][r*2+1] *= c; }
        }
        #pragma unroll
        for (int nt = 0; nt < 8; ++nt) {
            *(float2*)&Ps[(w*16 + qr    )*72 + nt*8 + qc*2] = make_float2(s[nt][0], s[nt][1]);
            *(float2*)&Ps[(w*16 + qr + 8)*72 + nt*8 + qc*2] = make_float2(s[nt][2], s[nt][3]);
        }
        #pragma unroll
        for (int ks = 0; ks < 8; ++ks) {
            uint32_t pf[4];
            pf[0] = __float_as_uint(Ps[(w*16 + qr    )*72 + ks*8 + qc    ]);
            pf[1] = __float_as_uint(Ps[(w*16 + qr + 8)*72 + ks*8 + qc    ]);
            pf[2] = __float_as_uint(Ps[(w*16 + qr    )*72 + ks*8 + qc + 4]);
            pf[3] = __float_as_uint(Ps[(w*16 + qr + 8)*72 + ks*8 + qc + 4]);
            #pragma unroll
            for (int nt = 0; nt < 8; ++nt) {
                uint32_t vf[2];
                vf[0] = __float_as_uint(Vs[(ks*8 + qc    )*72 + nt*8 + qr]);
                vf[1] = __float_as_uint(Vs[(ks*8 + qc + 4)*72 + nt*8 + qr]);
                mma_tf32(o[nt], pf, vf);
            }
        }
    }
    float inv0 = 1.f / l[0], inv1 = 1.f / l[1];
    long long row0 = q0 + w*16 + qr;
    #pragma unroll
    for (int nt = 0; nt < 8; ++nt) {
        long long col = nt*8 + qc*2;
        *(float2*)(O + base + row0*D_ + col) =
            make_float2(o[nt][0]*inv0, o[nt][1]*inv0);
        *(float2*)(O + base + (row0+8)*D_ + col) =
            make_float2(o[nt][2]*inv1, o[nt][3]*inv1);
    }
}

// ---------------- tf32-MMA fused knowledge memory ----------------
// grid B*S/16, block 256 (8 warps). Block = 16 Qm rows; warp owns 8 keys per 64-key tile.
// Qs stride 260 (frag banks all-distinct); kKs [d][key] stride 73.
// smem overlay: scoring = Qs(16x260) + kKs(64x73); merge = mv(16x256) + mi(16x256).
#define QS_STRIDE 260
#define KKS_STRIDE 73
#define KN_SCORE_BYTES ((16*QS_STRIDE + 64*KKS_STRIDE)*4)   // 35296
#define KN_MERGE_BYTES (16*256*8)                           // 32768
__global__ __launch_bounds__(256) void knowledge_kernel(
    const float* __restrict__ Qm, const float* __restrict__ kK,
    const float* __restrict__ kV, float* __restrict__ out)
{
    __shared__ __align__(16) char sbuf[KN_SCORE_BYTES > KN_MERGE_BYTES ? KN_SCORE_BYTES : KN_MERGE_BYTES];
    float* Qs  = (float*)sbuf;                         // [16][260]
    float* kKs = (float*)(sbuf + 16*QS_STRIDE*4);      // [64][73]
    float* mv_s = (float*)sbuf;                        // merge: [16][256] values
    int*   mi_s = (int*)(sbuf + 16*256*4);             // merge: [16][256] indices
    int t = threadIdx.x, w = t >> 5, lane = t & 31;
    int qr = lane >> 2, qc = lane & 3;
    int rowBase = blockIdx.x * 16;

    // stage 16 Qm rows into Qs (stride 260, float4-aligned: 260%4==0)
    for (int i = t; i < 16*64; i += 256) {
        int row = i >> 6, d4 = (i & 63) << 2;
        float4 v = *(const float4*)(Qm + (size_t)(rowBase + row)*KR_ + d4);
        *(float4*)&Qs[row*QS_STRIDE + d4] = v;
    }
    __syncthreads();

    float v0[TOPK_], v1[TOPK_]; int i0[TOPK_], i1[TOPK_];
    #pragma unroll
    for (int j = 0; j < TOPK_; ++j) {
        v0[j] = -3.0e38f; v1[j] = -3.0e38f; i0[j] = 0x7fffffff; i1[j] = 0x7fffffff;
    }

    for (int kt = 0; kt < NK_/64; ++kt) {
        int key0 = kt * 64;
        float s[4] = {0.f, 0.f, 0.f, 0.f};
        for (int c = 0; c < 4; ++c) {               // 64-d chunks
            __syncthreads();
            {   // stage kK[key0+key][c*64 .. +64) transposed -> kKs[d_local][key]
                int key = t >> 2;                   // 0..63
                int d16 = (t & 3) * 16;
                const float* src = kK + (size_t)(key0 + key)*KR_ + c*64 + d16;
                #pragma unroll
                for (int j = 0; j < 16; j += 4) {
                    float4 vv = *(const float4*)(src + j);
                    kKs[(d16+j+0)*KKS_STRIDE + key] = vv.x;
                    kKs[(d16+j+1)*KKS_STRIDE + key] = vv.y;
                    kKs[(d16+j+2)*KKS_STRIDE + key] = vv.z;
                    kKs[(d16+j+3)*KKS_STRIDE + key] = vv.w;
                }
            }
            __syncthreads();
            #pragma unroll
            for (int j = 0; j < 8; ++j) {           // k-steps within chunk
                int kk = c*64 + j*8;
                uint32_t af[4], bf[2];
                af[0] = __float_as_uint(Qs[ qr   *QS_STRIDE + kk + qc    ]);
                af[1] = __float_as_uint(Qs[(qr+8)*QS_STRIDE + kk + qc    ]);
                af[2] = __float_as_uint(Qs[ qr   *QS_STRIDE + kk + qc + 4]);
                af[3] = __float_as_uint(Qs[(qr+8)*QS_STRIDE + kk + qc + 4]);
                bf[0] = __float_as_uint(kKs[(j*8 + qc    )*KKS_STRIDE + w*8 + qr]);
                bf[1] = __float_as_uint(kKs[(j*8 + qc + 4)*KKS_STRIDE + w*8 + qr]);
                mma_tf32(s, af, bf);
            }
        }
        // insert: lane holds (row qr: s0,s1) (row qr+8: s2,s3), keys kA, kA+1
        int kA = key0 + w*8 + qc*2;
        #pragma unroll
        for (int e2 = 0; e2 < 2; ++e2) {
            float sv = e2 ? s[1] : s[0];
            int   ki = kA + e2;
            if (sv > v0[TOPK_-1]) {
                v0[TOPK_-1] = sv; i0[TOPK_-1] = ki;
                #pragma unroll
                for (int j = TOPK_-1; j > 0; --j)
                    if (v0[j] > v0[j-1]) {
                        float tv = v0[j]; v0[j] = v0[j-1]; v0[j-1] = tv;
                        int ti = i0[j]; i0[j] = i0[j-1]; i0[j-1] = ti;
                    }
            }
        }
        #pragma unroll
        for (int e2 = 0; e2 < 2; ++e2) {
            float sv = e2 ? s[3] : s[2];
            int   ki = kA + e2;
            if (sv > v1[TOPK_-1]) {
                v1[TOPK_-1] = sv; i1[TOPK_-1] = ki;
                #pragma unroll
                for (int j = TOPK_-1; j > 0; --j)
                    if (v1[j] > v1[j-1]) {
                        float tv = v1[j]; v1[j] = v1[j-1]; v1[j-1] = tv;
                        int ti = i1[j]; i1[j] = i1[j-1]; i1[j-1] = ti;
                    }
            }
        }
    }

    // ---- merge phase: overlay smem ----
    __syncthreads();
    int lbase = (w*4 + qc)*8;                       // 32 candidate lists per row
    #pragma unroll
    for (int j = 0; j < TOPK_; ++j) {
        mv_s[ qr   *256 + lbase + j] = v0[j];  mi_s[ qr   *256 + lbase + j] = i0[j];
        mv_s[(qr+8)*256 + lbase + j] = v1[j];  mi_s[(qr+8)*256 + lbase + j] = i1[j];
    }
    __syncthreads();

    // warp w handles rows 2w, 2w+1: 256 candidates each, lane holds 8
    #pragma unroll
    for (int rr = 0; rr < 2; ++rr) {
        int row = w*2 + rr;
        float cv[8]; int ci[8];
        #pragma unroll
        for (int j = 0; j < 8; ++j) {
            cv[j] = mv_s[row*256 + lane*8 + j];
            ci[j] = mi_s[row*256 + lane*8 + j];
        }
        float tv[TOPK_]; int ti[TOPK_];
        #pragma unroll
        for (int it = 0; it < TOPK_; ++it) {
            float bm = -3.0e38f; int bi = 0x7fffffff; int bj = 0;
            #pragma unroll
            for (int j = 0; j < 8; ++j)
                if (cv[j] > bm || (cv[j] == bm && ci[j] < bi)) { bm = cv[j]; bi = ci[j]; bj = j; }
            float mv = bm; int mi = bi;
            #pragma unroll
            for (int off = 16; off > 0; off >>= 1) {
                float ov = __shfl_xor_sync(0xffffffffu, mv, off);
                int   oi = __shfl_xor_sync(0xffffffffu, mi, off);
                if (ov > mv || (ov == mv && oi < mi)) { mv = ov; mi = oi; }
            }
            tv[it] = mv; ti[it] = mi;
            if (bi == mi) cv[bj] = -3.0e38f;       // unique indices -> exactly one lane pops
        }
        // softmax (tv[0] is max) + gather
        float mx = tv[0] * 0.0625f;
        float w8[TOPK_]; float ssum = 0.f;
        #pragma unroll
        for (int k2 = 0; k2 < TOPK_; ++k2) { w8[k2] = __expf(tv[k2]*0.0625f - mx); ssum += w8[k2]; }
        float inv = 1.f / ssum;
        int gr = rowBase + row;
        for (int j = 0; j < D_/32; ++j) {
            int d = j*32 + lane;
            float acc = 0.f;
            #pragma unroll
            for (int k2 = 0; k2 < TOPK_; ++k2)
                acc += w8[k2] * kV[(size_t)ti[k2]*D_ + d];
            out[(size_t)gr*D_ + d] += acc * inv;
        }
    }
}

// ---------------- host orchestration ----------------
extern "C" void kernel_launch(void* const* d_in, const int* in_sizes, int n_in,
                              void* d_out, int out_size)
{
    (void)in_sizes; (void)n_in; (void)out_size;
    const float* x   = (const float*)d_in[0];
    const float* imp = (const float*)d_in[1];
    const float* Wc  = (const float*)d_in[2];
    const float* WQ  = (const float*)d_in[3];
    const float* WK  = (const float*)d_in[4];
    const float* WV  = (const float*)d_in[5];
    const float* Wm  = (const float*)d_in[6];
    const float* cn  = (const float*)d_in[7];
    const float* pool= (const float*)d_in[8];
    const float* kK  = (const float*)d_in[9];
    const float* kV  = (const float*)d_in[10];
    const float* WO  = (const float*)d_in[11];
    const float* g1  = (const float*)d_in[12];
    const float* b1  = (const float*)d_in[13];
    const float* g2  = (const float*)d_in[14];
    const float* b2  = (const float*)d_in[15];
    float* out = (float*)d_out;

    float *nx, *sc, *h, *e, *qkv, *ao;
    cudaGetSymbolAddress((void**)&nx,  g_nx);
    cudaGetSymbolAddress((void**)&sc,  g_sc);
    cudaGetSymbolAddress((void**)&h,   g_h);
    cudaGetSymbolAddress((void**)&e,   g_e);
    cudaGetSymbolAddress((void**)&qkv, g_qkv);
    cudaGetSymbolAddress((void**)&ao,  g_ao);

    cudaFuncSetAttribute(sgemm_kernel<false>,
        cudaFuncAttributeMaxDynamicSharedMemorySize, SMEM_GEMM_BYTES);
    cudaFuncSetAttribute(sgemm_kernel<true>,
        cudaFuncAttributeMaxDynamicSharedMemorySize, SMEM_GEMM_BYTES);
    cudaFuncSetAttribute(attn_kernel,
        cudaFuncAttributeMaxDynamicSharedMemorySize, SMEM_ATT_BYTES);

    const long long BSD = (long long)B_*S_*D_;

    // ---- attention sub-block ----
    ln_kernel<<<B_*S_, 256>>>(x, g1, b1, nx);
    route_kernel<<<dim3(NBLK_, B_), 256>>>(nx, imp, Wc, WQ, WK, WV, 64);
    reduce_norm_kernel<<<4, 32>>>(0);
    mix_all_kernel<<<dim3((B_*D_*R_ + 255)/256, 4), 256>>>(cn, pool, 0, sc, 1);
    // h[b] = nx[b] @ sc[b]
    sgemm_kernel<false><<<dim3(R_/64, S_/128, B_), 256, SMEM_GEMM_BYTES>>>(
        nx, sc, h, S_, R_, D_, (long long)S_*D_, (long long)D_*R_, (long long)S_*R_, nullptr, 0);
    // Q|K|V = h @ e_{q,k,v}   one launch, grid.z = 6
    sgemm_kernel<false><<<dim3(D_/64, S_/128, 3*B_), 256, SMEM_GEMM_BYTES>>>(
        h, e, qkv, S_, D_, R_, 0, 0, 0, nullptr, 1);
    attn_kernel<<<dim3(S_/64, H_, B_), 128, SMEM_ATT_BYTES>>>(
        qkv, qkv + BSD, qkv + 2*BSD, ao);
    // out = x + ao @ WO^T
    sgemm_kernel<true><<<dim3(D_/64, (B_*S_)/128, 1), 256, SMEM_GEMM_BYTES>>>(
        ao, WO, out, B_*S_, D_, D_, 0, 0, 0, x, 0);

    // ---- memory sub-block ----
    ln_kernel<<<B_*S_, 256>>>(out, g2, b2, nx);
    route_kernel<<<dim3(NBLK_, B_), 256>>>(nx, imp, Wm, Wm, Wm, Wm, 16);
    reduce_norm_kernel<<<1, 32>>>(4);
    mix_all_kernel<<<dim3((B_*D_*R_ + 255)/256, 1), 256>>>(cn, pool, 4, sc, 0);
    // Qm[b] = nx2[b] @ mc[b]
    sgemm_kernel<false><<<dim3(R_/64, S_/128, B_), 256, SMEM_GEMM_BYTES>>>(
        nx, sc, h, S_, R_, D_, (long long)S_*D_, (long long)D_*R_, (long long)S_*R_, nullptr, 0);
    // fused: scores (tf32 MMA) -> top-8 -> softmax -> gather(kV) -> out +=
    knowledge_kernel<<<(B_*S_)/16, 256>>>(h, kK, kV, out);
}

// round 11
// speedup vs baseline: 4.3372x; 1.0683x over previous
#include <cuda_runtime.h>
#include <cuda_fp16.h>
#include <math.h>
#include <stdint.h>

// ---------------- problem constants ----------------
#define B_    2
#define S_    2048
#define D_    1024
#define H_    16
#define DH_   64
#define R_    256
#define NK_   4096
#define KR_   256
#define TOPK_ 8
#define NBLK_ (S_/8)

// ---------------- device scratch (allocation-free) ----------------
__device__ float  g_nx  [B_*S_*D_];       // LN output fp32 (route, knowledge src)
__device__ __half g_nxh [B_*S_*D_];       // LN output fp16 (GEMM A)
__device__ float  g_part[B_*NBLK_*64];
__device__ float  g_rw  [5*B_*16];
__device__ __half g_sch [B_*D_*R_];       // compress matrix fp16 (GEMM B)
__device__ float  g_h   [B_*S_*R_];       // Qm fp32 (knowledge)
__device__ __half g_hh  [B_*S_*R_];       // h fp16 (QKV GEMM A)
__device__ __half g_eh  [3*(B_*R_*D_)];   // expand matrices fp16
__device__ float  g_qkv [3*(B_*S_*D_)];   // q | k | v fp32 (attention)
__device__ __half g_aoh [B_*S_*D_];       // attention out fp16 (WO GEMM A)
__device__ __half g_woh [D_*D_];          // W_O fp16

// ---------------- mma / ldmatrix / cp.async helpers ----------------
__device__ __forceinline__ void mma_tf32(float* d, const uint32_t* a, const uint32_t* b) {
    asm volatile(
        "mma.sync.aligned.m16n8k8.row.col.f32.tf32.tf32.f32 "
        "{%0,%1,%2,%3},{%4,%5,%6,%7},{%8,%9},{%0,%1,%2,%3};"
        : "+f"(d[0]), "+f"(d[1]), "+f"(d[2]), "+f"(d[3])
        : "r"(a[0]), "r"(a[1]), "r"(a[2]), "r"(a[3]), "r"(b[0]), "r"(b[1]));
}
__device__ __forceinline__ void mma_f16(float* d, const uint32_t* a, const uint32_t* b) {
    asm volatile(
        "mma.sync.aligned.m16n8k16.row.col.f32.f16.f16.f32 "
        "{%0,%1,%2,%3},{%4,%5,%6,%7},{%8,%9},{%0,%1,%2,%3};"
        : "+f"(d[0]), "+f"(d[1]), "+f"(d[2]), "+f"(d[3])
        : "r"(a[0]), "r"(a[1]), "r"(a[2]), "r"(a[3]), "r"(b[0]), "r"(b[1]));
}
__device__ __forceinline__ uint32_t smaddr(const void* p) {
    return (uint32_t)__cvta_generic_to_shared(p);
}
__device__ __forceinline__ void ldsm_x4(uint32_t* r, uint32_t a) {
    asm volatile("ldmatrix.sync.aligned.m8n8.x4.shared.b16 {%0,%1,%2,%3},[%4];"
        : "=r"(r[0]), "=r"(r[1]), "=r"(r[2]), "=r"(r[3]) : "r"(a));
}
__device__ __forceinline__ void ldsm_x2(uint32_t* r, uint32_t a) {
    asm volatile("ldmatrix.sync.aligned.m8n8.x2.shared.b16 {%0,%1},[%2];"
        : "=r"(r[0]), "=r"(r[1]) : "r"(a));
}
__device__ __forceinline__ void ldsm_x2t(uint32_t* r, uint32_t a) {
    asm volatile("ldmatrix.sync.aligned.m8n8.x2.trans.shared.b16 {%0,%1},[%2];"
        : "=r"(r[0]), "=r"(r[1]) : "r"(a));
}
__device__ __forceinline__ void cpa16h(__half* smem, const __half* g) {
    asm volatile("cp.async.cg.shared.global [%0], [%1], 16;\n" :: "r"(smaddr(smem)), "l"(g));
}
#define CPA_COMMIT() asm volatile("cp.async.commit_group;\n" ::: "memory")
#define CPA_WAIT2()  asm volatile("cp.async.wait_group 2;\n" ::: "memory")

// ---------------- fp32 -> fp16 convert ----------------
__global__ void f2h_kernel(const float* __restrict__ src, __half* __restrict__ dst, int n)
{
    int i = blockIdx.x*256 + threadIdx.x;
    if (i < n) dst[i] = __float2half(src[i]);
}

// ---------------- LayerNorm: fp32 + fp16 outputs ----------------
__global__ void ln_kernel(const float* __restrict__ x,
                          const float* __restrict__ g,
                          const float* __restrict__ b,
                          float* __restrict__ out, __half* __restrict__ outh)
{
    int row = blockIdx.x;
    int t = threadIdx.x;                  // 256
    const float4* xr = (const float4*)(x + (size_t)row * D_);
    float4 v = xr[t];
    float s1 = v.x + v.y + v.z + v.w;
    float s2 = v.x*v.x + v.y*v.y + v.z*v.z + v.w*v.w;
    #pragma unroll
    for (int off = 16; off > 0; off >>= 1) {
        s1 += __shfl_xor_sync(0xffffffffu, s1, off);
        s2 += __shfl_xor_sync(0xffffffffu, s2, off);
    }
    __shared__ float sa[8], sb[8];
    __shared__ float s_mu, s_rs;
    int warp = t >> 5, lane = t & 31;
    if (lane == 0) { sa[warp] = s1; sb[warp] = s2; }
    __syncthreads();
    if (t == 0) {
        float ta = 0.f, tb = 0.f;
        #pragma unroll
        for (int w = 0; w < 8; ++w) { ta += sa[w]; tb += sb[w]; }
        float mu = ta * (1.0f / D_);
        float var = tb * (1.0f / D_) - mu * mu;
        s_mu = mu;
        s_rs = rsqrtf(var + 1e-5f);
    }
    __syncthreads();
    float mu = s_mu, rs = s_rs;
    float4 gg = ((const float4*)g)[t];
    float4 bb = ((const float4*)b)[t];
    float4 o;
    o.x = (v.x - mu) * rs * gg.x + bb.x;
    o.y = (v.y - mu) * rs * gg.y + bb.y;
    o.z = (v.z - mu) * rs * gg.z + bb.z;
    o.w = (v.w - mu) * rs * gg.w + bb.w;
    ((float4*)(out + (size_t)row * D_))[t] = o;
    ((__half2*)(outh + (size_t)row * D_))[t*2]   = __floats2half2_rn(o.x, o.y);
    ((__half2*)(outh + (size_t)row * D_))[t*2+1] = __floats2half2_rn(o.z, o.w);
}

// ---------------- routing (unchanged) ----------------
__global__ void route_kernel(const float* __restrict__ nx, const float* __restrict__ imp,
                             const float* __restrict__ W0, const float* __restrict__ W1,
                             const float* __restrict__ W2, const float* __restrict__ W3,
                             int nPairs)
{
    __shared__ float xs[8][128];
    __shared__ float ws[64][129];
    __shared__ float lg[8][64];
    int t = threadIdx.x;
    int b = blockIdx.y;
    int r0 = blockIdx.x * 8;
    float acc[8] = {0.f,0.f,0.f,0.f,0.f,0.f,0.f,0.f};
    for (int c = 0; c < 8; ++c) {
        int d0 = c * 128;
        for (int idx = t; idx < 8*128; idx += 256) {
            int r = idx >> 7, dd = idx & 127;
            xs[r][dd] = nx[((size_t)(b*S_ + r0 + r))*D_ + d0 + dd];
        }
        for (int idx = t; idx < nPairs*128; idx += 256) {
            int p = idx >> 7, dd = idx & 127;
            const float* Wp = (p < 16) ? W0 : (p < 32) ? W1 : (p < 48) ? W2 : W3;
            ws[p][dd] = Wp[(size_t)(p & 15)*D_ + d0 + dd];
        }
        __syncthreads();
        if (t < nPairs) {
            for (int dd = 0; dd < 128; ++dd) {
                float wv = ws[t][dd];
                #pragma unroll
                for (int r = 0; r < 8; ++r) acc[r] += wv * xs[r][dd];
            }
        }
        __syncthreads();
    }
    if (t < nPairs) {
        #pragma unroll
        for (int r = 0; r < 8; ++r) lg[r][t] = acc[r];
    }
    __syncthreads();
    if (t < nPairs) {
        int router = t >> 4;
        float contrib = 0.f;
        for (int r = 0; r < 8; ++r) {
            float mx = -1e30f;
            for (int e = 0; e < 16; ++e) mx = fmaxf(mx, lg[r][(router<<4) + e]);
            float ssum = 0.f;
            for (int e = 0; e < 16; ++e) ssum += __expf(lg[r][(router<<4) + e] - mx);
            float p = __expf(lg[r][t] - mx) / ssum;
            contrib += imp[b*S_ + r0 + r] * p;
        }
        g_part[((size_t)(b*NBLK_) + blockIdx.x)*64 + t] = contrib;
    }
}

__global__ void reduce_norm_kernel(int slotBase)
{
    int r = blockIdx.x;
    int lane = threadIdx.x;
    int b = lane >> 4, e = lane & 15;
    float acc = 0.f;
    for (int blk = 0; blk < NBLK_; ++blk)
        acc += g_part[((size_t)(b*NBLK_) + blk)*64 + (r<<4) + e];
    float gs = acc;
    gs += __shfl_xor_sync(0xffffffffu, gs, 1);
    gs += __shfl_xor_sync(0xffffffffu, gs, 2);
    gs += __shfl_xor_sync(0xffffffffu, gs, 4);
    gs += __shfl_xor_sync(0xffffffffu, gs, 8);
    g_rw[(slotBase + r)*B_*16 + b*16 + e] = acc / (gs + 1e-8f);
}

// ---------------- weighted pool mixes -> fp16 outputs ----------------
__global__ void mix_all_kernel(const float* __restrict__ cn, const float* __restrict__ pool,
                               int slotSc, int doE)
{
    int idx = blockIdx.x*256 + threadIdx.x;
    if (idx >= B_*D_*R_) return;
    int y = blockIdx.y;
    if (y == 0) {
        int b = idx / (D_*R_);
        int dr = idx - b*(D_*R_);
        float acc = 0.f;
        #pragma unroll
        for (int n = 0; n < 16; ++n)
            acc += g_rw[slotSc*B_*16 + b*16 + n] * cn[(size_t)n*(D_*R_) + dr];
        g_sch[idx] = __float2half(acc);
    } else if (doE) {
        int which = y - 1;
        int b = idx / (R_*D_);
        int rd = idx - b*(R_*D_);
        float acc = 0.f;
        #pragma unroll
        for (int n = 0; n < 16; ++n)
            acc += g_rw[(which+1)*B_*16 + b*16 + n] * pool[(size_t)n*(R_*D_) + rd];
        g_eh[(size_t)which*(B_*R_*D_) + idx] = __float2half(acc);
    }
}

// ---------------- 128x64 3-stage cp.async FP16 tensor-core GEMM ----------------
// C[M,N] = A[M,K] @ B (NN: B[K,N]; NT: B[N,K]); A,B fp16; C fp32 and/or Ch fp16.
// A smem [m][40h]; B NN [k][72h] (.trans frag); B NT [n][40h] (non-trans frag).
#define ASH 40
#define ASH_STAGE (128*ASH)          // 5120 halves
#define BSH_STAGE 2560               // max(32*72=2304, 64*40=2560)
#define SMEM_GEMM_BYTES ((3*(ASH_STAGE + BSH_STAGE))*2)   // 46080

template<bool TB>
__global__ __launch_bounds__(256)
void hgemm_kernel(const __half* __restrict__ A, const __half* __restrict__ Bm,
                  float* __restrict__ C, __half* __restrict__ Ch,
                  int M, int N, int K,
                  long long sA, long long sB, long long sC,
                  const float* __restrict__ addsrc, int zmode)
{
    extern __shared__ __half hsm[];
    __half* asBase = hsm;
    __half* bsBase = hsm + 3*ASH_STAGE;
    if (zmode == 1) {
        int which = blockIdx.z >> 1, b = blockIdx.z & 1;
        A  += (long long)b * S_ * R_;
        Bm += (long long)which * (B_*R_*D_) + (long long)b * R_ * D_;
        if (C)  C  += (long long)which * (B_*S_*D_) + (long long)b * S_ * D_;
        if (Ch) Ch += (long long)which * (B_*S_*D_) + (long long)b * S_ * D_;
    } else {
        A  += (long long)blockIdx.z * sA;
        Bm += (long long)blockIdx.z * sB;
        if (C)  C  += (long long)blockIdx.z * sC;
        if (Ch) Ch += (long long)blockIdx.z * sC;
    }
    int m0 = blockIdx.y * 128, n0 = blockIdx.x * 64;
    int t = threadIdx.x;
    int warp = t >> 5, lane = t & 31;
    int wm = warp >> 1, wn = warp & 1;
    int qr = lane >> 2, qc = lane & 3;
    int l15 = lane & 15;

    float acc[2][4][4];
    #pragma unroll
    for (int i = 0; i < 2; ++i)
        #pragma unroll
        for (int j = 0; j < 4; ++j)
            #pragma unroll
            for (int c = 0; c < 4; ++c) acc[i][j][c] = 0.f;

    auto stage_load = [&](int stage, int kt) {
        __half* asS = asBase + stage * ASH_STAGE;
        __half* bsS = bsBase + stage * BSH_STAGE;
        int k0 = kt * 32;
        #pragma unroll
        for (int i = 0; i < 2; ++i) {
            int c = t + i*256;               // 512 chunks: m = c/4, k8 = (c&3)*8
            int m = c >> 2, k8 = (c & 3) << 3;
            cpa16h(asS + m*ASH + k8, A + (long long)(m0 + m)*K + k0 + k8);
        }
        {
            int c = t;                       // 256 chunks
            if (TB) {
                int n = c >> 2, k8 = (c & 3) << 3;
                cpa16h(bsS + n*ASH + k8, Bm + (long long)(n0 + n)*K + k0 + k8);
            } else {
                int kr = c >> 3, n8 = (c & 7) << 3;
                cpa16h(bsS + kr*72 + n8, Bm + (long long)(k0 + kr)*N + n0 + n8);
            }
        }
    };

    int nk = K >> 5;
    stage_load(0, 0); CPA_COMMIT();
    stage_load(1, 1); CPA_COMMIT();

    for (int kt = 0; kt < nk; ++kt) {
        if (kt + 2 < nk) stage_load((kt + 2) % 3, kt + 2);
        CPA_COMMIT();
        CPA_WAIT2();
        __syncthreads();
        __half* asS = asBase + (kt % 3) * ASH_STAGE;
        __half* bsS = bsBase + (kt % 3) * BSH_STAGE;
        #pragma unroll
        for (int ks = 0; ks < 32; ks += 16) {
            uint32_t af[2][4], bf[4][2];
            #pragma unroll
            for (int mt = 0; mt < 2; ++mt) {
                int row = wm*32 + mt*16 + l15;
                int koff = ks + ((lane >> 4) << 3);
                ldsm_x4(af[mt], smaddr(asS + row*ASH + koff));
            }
            #pragma unroll
            for (int nt = 0; nt < 4; ++nt) {
                int nb = wn*32 + nt*8;
                if (TB) {
                    int n = nb + (l15 & 7);
                    int koff = ks + ((l15 >> 3) << 3);
                    ldsm_x2(bf[nt], smaddr(bsS + n*ASH + koff));
                } else {
                    int kidx = ks + l15;
                    ldsm_x2t(bf[nt], smaddr(bsS + kidx*72 + nb));
                }
            }
            #pragma unroll
            for (int mt = 0; mt < 2; ++mt)
                #pragma unroll
                for (int nt = 0; nt < 4; ++nt)
                    mma_f16(acc[mt][nt], af[mt], bf[nt]);
        }
        __syncthreads();
    }

    #pragma unroll
    for (int mt = 0; mt < 2; ++mt) {
        long long row = m0 + wm*32 + mt*16 + qr;
        #pragma unroll
        for (int nt = 0; nt < 4; ++nt) {
            long long col = n0 + wn*32 + nt*8 + qc*2;
            long long off0 = row * N + col;
            long long off1 = (row + 8) * N + col;
            float2 r0 = make_float2(acc[mt][nt][0], acc[mt][nt][1]);
            float2 r1 = make_float2(acc[mt][nt][2], acc[mt][nt][3]);
            if (addsrc) {
                float2 a0 = *(const float2*)(addsrc + off0);
                float2 a1 = *(const float2*)(addsrc + off1);
                r0.x += a0.x; r0.y += a0.y; r1.x += a1.x; r1.y += a1.y;
            }
            if (C) {
                *(float2*)(C + off0) = r0;
                *(float2*)(C + off1) = r1;
            }
            if (Ch) {
                *(__half2*)(Ch + off0) = __floats2half2_rn(r0.x, r0.y);
                *(__half2*)(Ch + off1) = __floats2half2_rn(r1.x, r1.y);
            }
        }
    }
}

// ---------------- tf32-MMA flash attention (fp16 output) ----------------
#define ATT_TILE (64*72)
#define SMEM_ATT_BYTES (3*ATT_TILE*4)

__global__ __launch_bounds__(128) void attn_kernel(
    const float* __restrict__ Q, const float* __restrict__ Kg,
    const float* __restrict__ Vg, __half* __restrict__ Oh)
{
    extern __shared__ float asmem[];
    float* Ks = asmem;
    float* Vs = asmem + ATT_TILE;
    float* Ps = asmem + 2*ATT_TILE;
    int b = blockIdx.z, h = blockIdx.y;
    int qb = gridDim.x - 1 - blockIdx.x;
    int q0 = qb * 64;
    int t = threadIdx.x, w = t >> 5, lane = t & 31;
    int qr = lane >> 2, qc = lane & 3;
    long long base = ((long long)(b*S_))*D_ + (long long)h*DH_;

    for (int i = t; i < 64*16; i += 128) {
        int qi = i >> 4, d4 = (i & 15) << 2;
        float4 v = *(const float4*)(Q + base + (long long)(q0+qi)*D_ + d4);
        *(float4*)&Ps[qi*72 + d4] = v;
    }
    __syncthreads();
    uint32_t qf[8][4];
    #pragma unroll
    for (int ks = 0; ks < 8; ++ks) {
        qf[ks][0] = __float_as_uint(Ps[(w*16 + qr    )*72 + ks*8 + qc    ]);
        qf[ks][1] = __float_as_uint(Ps[(w*16 + qr + 8)*72 + ks*8 + qc    ]);
        qf[ks][2] = __float_as_uint(Ps[(w*16 + qr    )*72 + ks*8 + qc + 4]);
        qf[ks][3] = __float_as_uint(Ps[(w*16 + qr + 8)*72 + ks*8 + qc + 4]);
    }
    __syncthreads();

    float m[2] = {-1e30f, -1e30f}, l[2] = {0.f, 0.f};
    float o[8][4];
    #pragma unroll
    for (int nt = 0; nt < 8; ++nt)
        #pragma unroll
        for (int j = 0; j < 4; ++j) o[nt][j] = 0.f;

    for (int kt = 0; kt <= qb; ++kt) {
        int k0 = kt * 64;
        __syncthreads();
        for (int i = t; i < 1024; i += 128) {
            int kk = i & 63, d4 = (i >> 6) << 2;
            float4 kv = *(const float4*)(Kg + base + (long long)(k0+kk)*D_ + d4);
            Ks[(d4+0)*72 + kk] = kv.x; Ks[(d4+1)*72 + kk] = kv.y;
            Ks[(d4+2)*72 + kk] = kv.z; Ks[(d4+3)*72 + kk] = kv.w;
        }
        for (int i = t; i < 1024; i += 128) {
            int kk = i >> 4, d4 = (i & 15) << 2;
            *(float4*)&Vs[kk*72 + d4] =
                *(const float4*)(Vg + base + (long long)(k0+kk)*D_ + d4);
        }
        __syncthreads();

        float s[8][4];
        #pragma unroll
        for (int nt = 0; nt < 8; ++nt)
            #pragma unroll
            for (int j = 0; j < 4; ++j) s[nt][j] = 0.f;
        #pragma unroll
        for (int ks = 0; ks < 8; ++ks) {
            #pragma unroll
            for (int nt = 0; nt < 8; ++nt) {
                uint32_t bf[2];
                bf[0] = __float_as_uint(Ks[(ks*8 + qc    )*72 + nt*8 + qr]);
                bf[1] = __float_as_uint(Ks[(ks*8 + qc + 4)*72 + nt*8 + qr]);
                mma_tf32(s[nt], qf[ks], bf);
            }
        }
        if (kt == qb) {
            #pragma unroll
            for (int nt = 0; nt < 8; ++nt)
                #pragma unroll
                for (int j = 0; j < 4; ++j) {
                    int key = k0 + nt*8 + qc*2 + (j & 1);
                    int qg  = q0 + w*16 + qr + (j >> 1)*8;
                    float v = s[nt][j] * 0.125f;
                    s[nt][j] = (key > qg) ? -1e30f : v;
                }
        } else {
            #pragma unroll
            for (int nt = 0; nt < 8; ++nt)
                #pragma unroll
                for (int j = 0; j < 4; ++j) s[nt][j] *= 0.125f;
        }
        #pragma unroll
        for (int r = 0; r < 2; ++r) {
            float rm = -1e30f;
            #pragma unroll
            for (int nt = 0; nt < 8; ++nt)
                rm = fmaxf(rm, fmaxf(s[nt][r*2], s[nt][r*2+1]));
            rm = fmaxf(rm, __shfl_xor_sync(0xffffffffu, rm, 1));
            rm = fmaxf(rm, __shfl_xor_sync(0xffffffffu, rm, 2));
            float mn = fmaxf(m[r], rm);
            float c = __expf(m[r] - mn);
            float rs = 0.f;
            #pragma unroll
            for (int nt = 0; nt < 8; ++nt) {
                float p0 = __expf(s[nt][r*2]   - mn);
                float p1 = __expf(s[nt][r*2+1] - mn);
                s[nt][r*2] = p0; s[nt][r*2+1] = p1;
                rs += p0 + p1;
            }
            rs += __shfl_xor_sync(0xffffffffu, rs, 1);
            rs += __shfl_xor_sync(0xffffffffu, rs, 2);
            l[r] = l[r]*c + rs;
            m[r] = mn;
            #pragma unroll
            for (int nt = 0; nt < 8; ++nt) { o[nt][r*2] *= c; o[nt][r*2+1] *= c; }
        }
        #pragma unroll
        for (int nt = 0; nt < 8; ++nt) {
            *(float2*)&Ps[(w*16 + qr    )*72 + nt*8 + qc*2] = make_float2(s[nt][0], s[nt][1]);
            *(float2*)&Ps[(w*16 + qr + 8)*72 + nt*8 + qc*2] = make_float2(s[nt][2], s[nt][3]);
        }
        #pragma unroll
        for (int ks = 0; ks < 8; ++ks) {
            uint32_t pf[4];
            pf[0] = __float_as_uint(Ps[(w*16 + qr    )*72 + ks*8 + qc    ]);
            pf[1] = __float_as_uint(Ps[(w*16 + qr + 8)*72 + ks*8 + qc    ]);
            pf[2] = __float_as_uint(Ps[(w*16 + qr    )*72 + ks*8 + qc + 4]);
            pf[3] = __float_as_uint(Ps[(w*16 + qr + 8)*72 + ks*8 + qc + 4]);
            #pragma unroll
            for (int nt = 0; nt < 8; ++nt) {
                uint32_t vf[2];
                vf[0] = __float_as_uint(Vs[(ks*8 + qc    )*72 + nt*8 + qr]);
                vf[1] = __float_as_uint(Vs[(ks*8 + qc + 4)*72 + nt*8 + qr]);
                mma_tf32(o[nt], pf, vf);
            }
        }
    }
    float inv0 = 1.f / l[0], inv1 = 1.f / l[1];
    long long row0 = q0 + w*16 + qr;
    #pragma unroll
    for (int nt = 0; nt < 8; ++nt) {
        long long col = nt*8 + qc*2;
        *(__half2*)(Oh + base + row0*D_ + col) =
            __floats2half2_rn(o[nt][0]*inv0, o[nt][1]*inv0);
        *(__half2*)(Oh + base + (row0+8)*D_ + col) =
            __floats2half2_rn(o[nt][2]*inv1, o[nt][3]*inv1);
    }
}

// ---------------- tf32-MMA fused knowledge memory (unchanged) ----------------
#define QS_STRIDE 260
#define KKS_STRIDE 73
#define KN_SCORE_BYTES ((16*QS_STRIDE + 64*KKS_STRIDE)*4)
#define KN_MERGE_BYTES (16*256*8)
__global__ __launch_bounds__(256) void knowledge_kernel(
    const float* __restrict__ Qm, const float* __restrict__ kK,
    const float* __restrict__ kV, float* __restrict__ out)
{
    __shared__ __align__(16) char sbuf[KN_SCORE_BYTES > KN_MERGE_BYTES ? KN_SCORE_BYTES : KN_MERGE_BYTES];
    float* Qs  = (float*)sbuf;
    float* kKs = (float*)(sbuf + 16*QS_STRIDE*4);
    float* mv_s = (float*)sbuf;
    int*   mi_s = (int*)(sbuf + 16*256*4);
    int t = threadIdx.x, w = t >> 5, lane = t & 31;
    int qr = lane >> 2, qc = lane & 3;
    int rowBase = blockIdx.x * 16;

    for (int i = t; i < 16*64; i += 256) {
        int row = i >> 6, d4 = (i & 63) << 2;
        float4 v = *(const float4*)(Qm + (size_t)(rowBase + row)*KR_ + d4);
        *(float4*)&Qs[row*QS_STRIDE + d4] = v;
    }
    __syncthreads();

    float v0[TOPK_], v1[TOPK_]; int i0[TOPK_], i1[TOPK_];
    #pragma unroll
    for (int j = 0; j < TOPK_; ++j) {
        v0[j] = -3.0e38f; v1[j] = -3.0e38f; i0[j] = 0x7fffffff; i1[j] = 0x7fffffff;
    }

    for (int kt = 0; kt < NK_/64; ++kt) {
        int key0 = kt * 64;
        float s[4] = {0.f, 0.f, 0.f, 0.f};
        for (int c = 0; c < 4; ++c) {
            __syncthreads();
            {
                int key = t >> 2;
                int d16 = (t & 3) * 16;
                const float* src = kK + (size_t)(key0 + key)*KR_ + c*64 + d16;
                #pragma unroll
                for (int j = 0; j < 16; j += 4) {
                    float4 vv = *(const float4*)(src + j);
                    kKs[(d16+j+0)*KKS_STRIDE + key] = vv.x;
                    kKs[(d16+j+1)*KKS_STRIDE + key] = vv.y;
                    kKs[(d16+j+2)*KKS_STRIDE + key] = vv.z;
                    kKs[(d16+j+3)*KKS_STRIDE + key] = vv.w;
                }
            }
            __syncthreads();
            #pragma unroll
            for (int j = 0; j < 8; ++j) {
                int kk = c*64 + j*8;
                uint32_t af[4], bf[2];
                af[0] = __float_as_uint(Qs[ qr   *QS_STRIDE + kk + qc    ]);
                af[1] = __float_as_uint(Qs[(qr+8)*QS_STRIDE + kk + qc    ]);
                af[2] = __float_as_uint(Qs[ qr   *QS_STRIDE + kk + qc + 4]);
                af[3] = __float_as_uint(Qs[(qr+8)*QS_STRIDE + kk + qc + 4]);
                bf[0] = __float_as_uint(kKs[(j*8 + qc    )*KKS_STRIDE + w*8 + qr]);
                bf[1] = __float_as_uint(kKs[(j*8 + qc + 4)*KKS_STRIDE + w*8 + qr]);
                mma_tf32(s, af, bf);
            }
        }
        int kA = key0 + w*8 + qc*2;
        #pragma unroll
        for (int e2 = 0; e2 < 2; ++e2) {
            float sv = e2 ? s[1] : s[0];
            int   ki = kA + e2;
            if (sv > v0[TOPK_-1]) {
                v0[TOPK_-1] = sv; i0[TOPK_-1] = ki;
                #pragma unroll
                for (int j = TOPK_-1; j > 0; --j)
                    if (v0[j] > v0[j-1]) {
                        float tv = v0[j]; v0[j] = v0[j-1]; v0[j-1] = tv;
                        int ti = i0[j]; i0[j] = i0[j-1]; i0[j-1] = ti;
                    }
            }
        }
        #pragma unroll
        for (int e2 = 0; e2 < 2; ++e2) {
            float sv = e2 ? s[3] : s[2];
            int   ki = kA + e2;
            if (sv > v1[TOPK_-1]) {
                v1[TOPK_-1] = sv; i1[TOPK_-1] = ki;
                #pragma unroll
                for (int j = TOPK_-1; j > 0; --j)
                    if (v1[j] > v1[j-1]) {
                        float tv = v1[j]; v1[j] = v1[j-1]; v1[j-1] = tv;
                        int ti = i1[j]; i1[j] = i1[j-1]; i1[j-1] = ti;
                    }
            }
        }
    }

    __syncthreads();
    int lbase = (w*4 + qc)*8;
    #pragma unroll
    for (int j = 0; j < TOPK_; ++j) {
        mv_s[ qr   *256 + lbase + j] = v0[j];  mi_s[ qr   *256 + lbase + j] = i0[j];
        mv_s[(qr+8)*256 + lbase + j] = v1[j];  mi_s[(qr+8)*256 + lbase + j] = i1[j];
    }
    __syncthreads();

    #pragma unroll
    for (int rr = 0; rr < 2; ++rr) {
        int row = w*2 + rr;
        float cv[8]; int ci[8];
        #pragma unroll
        for (int j = 0; j < 8; ++j) {
            cv[j] = mv_s[row*256 + lane*8 + j];
            ci[j] = mi_s[row*256 + lane*8 + j];
        }
        float tv[TOPK_]; int ti[TOPK_];
        #pragma unroll
        for (int it = 0; it < TOPK_; ++it) {
            float bm = -3.0e38f; int bi = 0x7fffffff; int bj = 0;
            #pragma unroll
            for (int j = 0; j < 8; ++j)
                if (cv[j] > bm || (cv[j] == bm && ci[j] < bi)) { bm = cv[j]; bi = ci[j]; bj = j; }
            float mv = bm; int mi = bi;
            #pragma unroll
            for (int off = 16; off > 0; off >>= 1) {
                float ov = __shfl_xor_sync(0xffffffffu, mv, off);
                int   oi = __shfl_xor_sync(0xffffffffu, mi, off);
                if (ov > mv || (ov == mv && oi < mi)) { mv = ov; mi = oi; }
            }
            tv[it] = mv; ti[it] = mi;
            if (bi == mi) cv[bj] = -3.0e38f;
        }
        float mx = tv[0] * 0.0625f;
        float w8[TOPK_]; float ssum = 0.f;
        #pragma unroll
        for (int k2 = 0; k2 < TOPK_; ++k2) { w8[k2] = __expf(tv[k2]*0.0625f - mx); ssum += w8[k2]; }
        float inv = 1.f / ssum;
        int gr = rowBase + row;
        for (int j = 0; j < D_/32; ++j) {
            int d = j*32 + lane;
            float acc = 0.f;
            #pragma unroll
            for (int k2 = 0; k2 < TOPK_; ++k2)
                acc += w8[k2] * kV[(size_t)ti[k2]*D_ + d];
            out[(size_t)gr*D_ + d] += acc * inv;
        }
    }
}

// ---------------- host orchestration ----------------
extern "C" void kernel_launch(void* const* d_in, const int* in_sizes, int n_in,
                              void* d_out, int out_size)
{
    (void)in_sizes; (void)n_in; (void)out_size;
    const float* x   = (const float*)d_in[0];
    const float* imp = (const float*)d_in[1];
    const float* Wc  = (const float*)d_in[2];
    const float* WQ  = (const float*)d_in[3];
    const float* WK  = (const float*)d_in[4];
    const float* WV  = (const float*)d_in[5];
    const float* Wm  = (const float*)d_in[6];
    const float* cn  = (const float*)d_in[7];
    const float* pool= (const float*)d_in[8];
    const float* kK  = (const float*)d_in[9];
    const float* kV  = (const float*)d_in[10];
    const float* WO  = (const float*)d_in[11];
    const float* g1  = (const float*)d_in[12];
    const float* b1  = (const float*)d_in[13];
    const float* g2  = (const float*)d_in[14];
    const float* b2  = (const float*)d_in[15];
    float* out = (float*)d_out;

    float *nx, *h, *qkv;
    __half *nxh, *sch, *hh, *eh, *aoh, *woh;
    cudaGetSymbolAddress((void**)&nx,  g_nx);
    cudaGetSymbolAddress((void**)&nxh, g_nxh);
    cudaGetSymbolAddress((void**)&sch, g_sch);
    cudaGetSymbolAddress((void**)&h,   g_h);
    cudaGetSymbolAddress((void**)&hh,  g_hh);
    cudaGetSymbolAddress((void**)&eh,  g_eh);
    cudaGetSymbolAddress((void**)&qkv, g_qkv);
    cudaGetSymbolAddress((void**)&aoh, g_aoh);
    cudaGetSymbolAddress((void**)&woh, g_woh);

    cudaFuncSetAttribute(hgemm_kernel<false>,
        cudaFuncAttributeMaxDynamicSharedMemorySize, SMEM_GEMM_BYTES);
    cudaFuncSetAttribute(hgemm_kernel<true>,
        cudaFuncAttributeMaxDynamicSharedMemorySize, SMEM_GEMM_BYTES);
    cudaFuncSetAttribute(attn_kernel,
        cudaFuncAttributeMaxDynamicSharedMemorySize, SMEM_ATT_BYTES);

    const long long BSD = (long long)B_*S_*D_;

    // ---- attention sub-block ----
    f2h_kernel<<<(D_*D_)/256, 256>>>(WO, woh, D_*D_);
    ln_kernel<<<B_*S_, 256>>>(x, g1, b1, nx, nxh);
    route_kernel<<<dim3(NBLK_, B_), 256>>>(nx, imp, Wc, WQ, WK, WV, 64);
    reduce_norm_kernel<<<4, 32>>>(0);
    mix_all_kernel<<<dim3((B_*D_*R_ + 255)/256, 4), 256>>>(cn, pool, 0, 1);
    // h[b] = nx[b] @ sc[b]  -> hh (fp16 only)
    hgemm_kernel<false><<<dim3(R_/64, S_/128, B_), 256, SMEM_GEMM_BYTES>>>(
        nxh, sch, nullptr, hh, S_, R_, D_,
        (long long)S_*D_, (long long)D_*R_, (long long)S_*R_, nullptr, 0);
    // Q|K|V = hh @ eh  (fp32 out for attention), one launch grid.z = 6
    hgemm_kernel<false><<<dim3(D_/64, S_/128, 3*B_), 256, SMEM_GEMM_BYTES>>>(
        hh, eh, qkv, nullptr, S_, D_, R_, 0, 0, 0, nullptr, 1);
    attn_kernel<<<dim3(S_/64, H_, B_), 128, SMEM_ATT_BYTES>>>(
        qkv, qkv + BSD, qkv + 2*BSD, aoh);
    // out = x + aoh @ woh^T
    hgemm_kernel<true><<<dim3(D_/64, (B_*S_)/128, 1), 256, SMEM_GEMM_BYTES>>>(
        aoh, woh, out, nullptr, B_*S_, D_, D_, 0, 0, 0, x, 0);

    // ---- memory sub-block ----
    ln_kernel<<<B_*S_, 256>>>(out, g2, b2, nx, nxh);
    route_kernel<<<dim3(NBLK_, B_), 256>>>(nx, imp, Wm, Wm, Wm, Wm, 16);
    reduce_norm_kernel<<<1, 32>>>(4);
    mix_all_kernel<<<dim3((B_*D_*R_ + 255)/256, 1), 256>>>(cn, pool, 4, 0);
    // Qm[b] = nx2[b] @ mc[b]  (fp32 out for knowledge)
    hgemm_kernel<false><<<dim3(R_/64, S_/128, B_), 256, SMEM_GEMM_BYTES>>>(
        nxh, sch, h, nullptr, S_, R_, D_,
        (long long)S_*D_, (long long)D_*R_, (long long)S_*R_, nullptr, 0);
    // fused: scores (tf32 MMA) -> top-8 -> softmax -> gather(kV) -> out +=
    knowledge_kernel<<<(B_*S_)/16, 256>>>(h, kK, kV, out);
}